// round 4
// baseline (speedup 1.0000x reference)
#include <cuda_runtime.h>
#include <cuda_bf16.h>
#include <math.h>
#include <stdint.h>

#define D 128
#define DD 16384
#define BATCH 16
#define NSEQ 1024
#define M_ROWS 16384
#define NE 32768
#define NS 6
#define NL 4

typedef unsigned long long u64;
typedef unsigned int u32;
typedef long long i64;
typedef __nv_bfloat16 bf16;

// ---------------- scratch (fp32) ---------------------------------------------
__device__ __align__(256) float g_v [M_ROWS * D];
__device__ __align__(256) float g_sc[(size_t)BATCH * NSEQ * NSEQ];
__device__ __align__(256) float g_T [M_ROWS * D];
__device__ __align__(256) float g_Z [M_ROWS * D];
__device__ __align__(256) int   g_iota[M_ROWS];

// ---------------- scratch (bf16 hi/lo splits) ---------------------------------
__device__ __align__(256) bf16 s_ctrs_h[M_ROWS*D],  s_ctrs_l[M_ROWS*D];
__device__ __align__(256) bf16 s_feat_h[M_ROWS*D],  s_feat_l[M_ROWS*D];
__device__ __align__(256) bf16 s_q_h[M_ROWS*D],     s_q_l[M_ROWS*D];
__device__ __align__(256) bf16 s_k_h[M_ROWS*D],     s_k_l[M_ROWS*D];
__device__ __align__(256) bf16 s_vt_h[M_ROWS*D],    s_vt_l[M_ROWS*D];
__device__ __align__(256) bf16 s_x_h[M_ROWS*D],     s_x_l[M_ROWS*D];
__device__ __align__(256) bf16 s_y_h[M_ROWS*D],     s_y_l[M_ROWS*D];
__device__ __align__(256) bf16 s_sc_h[(size_t)BATCH*NSEQ*NSEQ], s_sc_l[(size_t)BATCH*NSEQ*NSEQ];
__device__ __align__(256) bf16 s_wq_h[DD], s_wq_l[DD], s_wk_h[DD], s_wk_l[DD], s_wv_h[DD], s_wv_l[DD];
__device__ __align__(256) bf16 s_wc_h[NL*DD],  s_wc_l[NL*DD];
__device__ __align__(256) bf16 s_wp_h[NL*NS*DD], s_wp_l[NL*NS*DD];
__device__ __align__(256) bf16 s_ws_h[NL*NS*DD], s_ws_l[NL*NS*DD];
__device__ __align__(256) bf16 s_wl_h[NL*DD],  s_wl_l[NL*DD];
__device__ __align__(256) bf16 s_wr_h[NL*DD],  s_wr_l[NL*DD];
__device__ __align__(256) bf16 s_w2_h[NL*DD],  s_w2_l[NL*DD];

// ---------------- PTX helpers ------------------------------------------------
__device__ __forceinline__ u32 smem_u32(const void* p) {
    u32 a;
    asm("{ .reg .u64 t; cvta.to.shared.u64 t, %1; cvt.u32.u64 %0, t; }" : "=r"(a) : "l"(p));
    return a;
}
__device__ __forceinline__ void ldsm4(u32* r, u32 addr) {
    asm volatile("ldmatrix.sync.aligned.m8n8.x4.shared.b16 {%0,%1,%2,%3}, [%4];"
                 : "=r"(r[0]), "=r"(r[1]), "=r"(r[2]), "=r"(r[3]) : "r"(addr));
}
__device__ __forceinline__ void mma_bf16(float* d, const u32* a, u32 b0, u32 b1) {
    asm volatile("mma.sync.aligned.m16n8k16.row.col.f32.bf16.bf16.f32 "
                 "{%0,%1,%2,%3}, {%4,%5,%6,%7}, {%8,%9}, {%0,%1,%2,%3};"
                 : "+f"(d[0]), "+f"(d[1]), "+f"(d[2]), "+f"(d[3])
                 : "r"(a[0]), "r"(a[1]), "r"(a[2]), "r"(a[3]), "r"(b0), "r"(b1));
}
__device__ __forceinline__ void red4(float* p, float a, float b, float c, float d) {
    asm volatile("red.global.add.v4.f32 [%0], {%1,%2,%3,%4};"
                 :: "l"(p), "f"(a), "f"(b), "f"(c), "f"(d) : "memory");
}
__device__ __forceinline__ void cp16_cg(u32 dst, const void* src) {
    asm volatile("cp.async.cg.shared.global [%0], [%1], 16;" :: "r"(dst), "l"(src));
}
__device__ __forceinline__ void cp16_ca(u32 dst, const void* src) {
    asm volatile("cp.async.ca.shared.global [%0], [%1], 16;" :: "r"(dst), "l"(src));
}
__device__ __forceinline__ void cp_commit() { asm volatile("cp.async.commit_group;" ::: "memory"); }
template<int N> __device__ __forceinline__ void cp_wait() {
    asm volatile("cp.async.wait_group %0;" :: "n"(N) : "memory");
}

// split fp32 float4 -> packed hi bf16x2 pair + lo bf16x2 pair
__device__ __forceinline__ void split4(float4 v, uint2& hv, uint2& lv) {
    __nv_bfloat162 h0 = __floats2bfloat162_rn(v.x, v.y);
    __nv_bfloat162 h1 = __floats2bfloat162_rn(v.z, v.w);
    float2 f0 = __bfloat1622float2(h0);
    float2 f1 = __bfloat1622float2(h1);
    __nv_bfloat162 l0 = __floats2bfloat162_rn(v.x - f0.x, v.y - f0.y);
    __nv_bfloat162 l1 = __floats2bfloat162_rn(v.z - f1.x, v.w - f1.y);
    hv = make_uint2(*(u32*)&h0, *(u32*)&h1);
    lv = make_uint2(*(u32*)&l0, *(u32*)&l1);
}

// ---------------- GEMM core ----------------------------------------------------
// C[m,n] (+)= scale * sum_k A[m,k]*B[n,k]; A,B pre-split bf16 hi/lo; K = KT*128.
// Double-buffered 64-wide K-halves via cp.async. SMEM: 2 stages x 4 x 16KB = 128KB.
// GS: gather rows via gi (pre-offset), scatter-add via si (red.v4).
template<bool GS, bool RES, bool OF32, bool OSPLIT>
__device__ __forceinline__ void gemm_core(
    const bf16* __restrict__ Ah, const bf16* __restrict__ Al, int lda,
    const bf16* __restrict__ Bh, const bf16* __restrict__ Bl, int ldb,
    float* __restrict__ C, int ldc,
    bf16* __restrict__ Ch, bf16* __restrict__ Cl,
    const float* __restrict__ Fres,
    const int* __restrict__ gi, const int* __restrict__ si,
    int row0, int col0, float scale, int KT)
{
    extern __shared__ char sm[];
    const u32 sb = smem_u32(sm);
    const int tid = threadIdx.x;
    const int wid = tid >> 5, lane = tid & 31;
    const int m0w = (wid >> 1) * 32, n0w = (wid & 1) * 64;

    float acc[2][8][4];
    #pragma unroll
    for (int mi = 0; mi < 2; mi++)
        #pragma unroll
        for (int nj = 0; nj < 8; nj++)
            #pragma unroll
            for (int e = 0; e < 4; e++) acc[mi][nj][e] = 0.f;

    // per-lane ldmatrix components (pitch 128B, xor-by-(row&7) swizzle)
    const u32 a_rb = (u32)(m0w + (lane & 15)) * 128;
    const u32 b_rb = (u32)(n0w + ((lane >> 4) << 3) + (lane & 7)) * 128;
    const int a_hi = lane >> 4;
    const int b_hi = (lane >> 3) & 1;
    const int xr = lane & 7;

    // loader for half h into stage s
    const int r_ld = tid >> 1;                    // row handled by this thread
    const int c0_ld = (tid & 1) * 4;              // first of 4 16B chunks
    i64 arow_ld = GS ? (i64)__ldg(gi + r_ld) : (i64)(row0 + r_ld);
    const int H = 2 * KT;

    auto load_half = [&](int h, int s) {
        const int kofs = h * 64;
        const u32 base = sb + (u32)s * 65536u;
        const bf16* ap  = Ah + arow_ld * (i64)lda + kofs;
        const bf16* alp = Al + arow_ld * (i64)lda + kofs;
        const bf16* bp  = Bh + (i64)(col0 + r_ld) * ldb + kofs;
        const bf16* blp = Bl + (i64)(col0 + r_ld) * ldb + kofs;
        #pragma unroll
        for (int j = 0; j < 4; j++) {
            int c = c0_ld + j;
            u32 so = (u32)r_ld * 128 + (u32)((c ^ (r_ld & 7)) << 4);
            cp16_cg(base + so,          ap  + c * 8);
            cp16_cg(base + 16384 + so,  alp + c * 8);
            cp16_ca(base + 32768 + so,  bp  + c * 8);
            cp16_ca(base + 49152 + so,  blp + c * 8);
        }
        cp_commit();
    };

    load_half(0, 0);
    for (int h = 0; h < H; h++) {
        const int s = h & 1;
        const bool more = (h + 1 < H);
        if (more) { load_half(h + 1, 1 - s); cp_wait<1>(); }
        else      { cp_wait<0>(); }
        __syncthreads();
        const u32 base = sb + (u32)s * 65536u;
        #pragma unroll 1
        for (int pass = 0; pass < 3; pass++) {
            const u32 abase = base + ((pass == 2) ? 16384u : 0u) + a_rb;
            const u32 bbase = base + 32768u + ((pass == 1) ? 16384u : 0u) + b_rb;
            #pragma unroll
            for (int ks = 0; ks < 4; ks++) {
                const u32 aoff = (u32)(((ks * 2 + a_hi) ^ xr) << 4);
                const u32 boff = (u32)(((ks * 2 + b_hi) ^ xr) << 4);
                u32 a0[4], a1[4], b[4][4];
                ldsm4(a0, abase + aoff);
                ldsm4(a1, abase + aoff + 2048);
                #pragma unroll
                for (int p = 0; p < 4; p++)
                    ldsm4(b[p], bbase + boff + p * 2048);
                #pragma unroll
                for (int nj = 0; nj < 8; nj++) {
                    u32 bb0 = b[nj >> 1][(nj & 1) * 2], bb1 = b[nj >> 1][(nj & 1) * 2 + 1];
                    mma_bf16(acc[0][nj], a0, bb0, bb1);
                    mma_bf16(acc[1][nj], a1, bb0, bb1);
                }
            }
        }
        __syncthreads();
    }

    // ---- stage C to SMEM (pitch 132 floats), then output ----
    float* Cs = reinterpret_cast<float*>(sm);
    const int g = lane >> 2, q2 = (lane & 3) * 2;
    #pragma unroll
    for (int mi = 0; mi < 2; mi++)
        #pragma unroll
        for (int nj = 0; nj < 8; nj++) {
            int r = m0w + mi * 16 + g;
            int c = n0w + nj * 8 + q2;
            Cs[r * 132 + c]           = acc[mi][nj][0];
            Cs[r * 132 + c + 1]       = acc[mi][nj][1];
            Cs[(r + 8) * 132 + c]     = acc[mi][nj][2];
            Cs[(r + 8) * 132 + c + 1] = acc[mi][nj][3];
        }
    __syncthreads();

    const int rr = tid >> 1, hh = tid & 1;
    const float* srow = Cs + rr * 132 + hh * 64;
    if (GS) {
        i64 drow = (i64)__ldg(si + rr);
        float* p = C + drow * (i64)ldc + col0 + hh * 64;
        #pragma unroll
        for (int j = 0; j < 16; j++) {
            float4 vv = *reinterpret_cast<const float4*>(srow + j * 4);
            red4(p + j * 4, vv.x, vv.y, vv.z, vv.w);
        }
    } else {
        const i64 ro = (i64)(row0 + rr) * ldc + col0 + hh * 64;
        const float* fp = RES ? (Fres + ro) : (const float*)0;
        float* p = OF32 ? (C + ro) : (float*)0;
        #pragma unroll
        for (int j = 0; j < 16; j++) {
            float4 vv = *reinterpret_cast<const float4*>(srow + j * 4);
            vv.x *= scale; vv.y *= scale; vv.z *= scale; vv.w *= scale;
            if (RES) {
                float4 f = *reinterpret_cast<const float4*>(fp + j * 4);
                vv.x += f.x; vv.y += f.y; vv.z += f.z; vv.w += f.w;
            }
            if (OF32) *reinterpret_cast<float4*>(p + j * 4) = vv;
            if (OSPLIT) {
                uint2 hv, lv;
                split4(vv, hv, lv);
                *reinterpret_cast<uint2*>(Ch + ro + j * 4) = hv;
                *reinterpret_cast<uint2*>(Cl + ro + j * 4) = lv;
            }
        }
    }
}

// ---------------- GEMM wrapper kernels -----------------------------------------
template<bool GS, bool RES, bool OF32, bool OSPLIT>
__global__ __launch_bounds__(256, 1)
void gemm_k(const bf16* Ah, const bf16* Al, int lda, i64 aZ,
            const bf16* Bh, const bf16* Bl, int ldb, i64 bZ,
            float* C, int ldc, i64 cZ,
            bf16* Ch, bf16* Cl,
            const float* Fres, i64 fZ,
            const int* gidx, const int* sidx, i64 iZ,
            float scale, int KT)
{
    const int z = blockIdx.z;
    const int row0 = blockIdx.x * 128, col0 = blockIdx.y * 128;
    gemm_core<GS, RES, OF32, OSPLIT>(
        Ah + (i64)z * aZ, Al + (i64)z * aZ, lda,
        Bh + (i64)z * bZ, Bl + (i64)z * bZ, ldb,
        C + (i64)z * cZ, ldc,
        OSPLIT ? Ch + (i64)z * cZ : (bf16*)0, OSPLIT ? Cl + (i64)z * cZ : (bf16*)0,
        RES ? Fres + (i64)z * fZ : (const float*)0,
        GS ? gidx + (i64)z * iZ + row0 : (const int*)0,
        GS ? sidx + (i64)z * iZ + row0 : (const int*)0,
        row0, col0, scale, KT);
}

// ---------------- fused per-layer scatter launch (3712 CTAs) -------------------
__global__ __launch_bounds__(256, 1)
void layer_scatter(const bf16* Xh, const bf16* Xl,
                   const bf16* wch, const bf16* wcl,
                   const bf16* wph, const bf16* wpl,
                   const bf16* wsh, const bf16* wsl,
                   const bf16* wlh, const bf16* wll,
                   const bf16* wrh, const bf16* wrl,
                   float* T,
                   const int* iota,
                   const int* pre_u, const int* pre_v,
                   const int* suc_u, const int* suc_v,
                   const int* left_u, const int* left_v,
                   const int* right_u, const int* right_v)
{
    const int t = blockIdx.x;
    const int* gi; const int* si; const bf16* Bh; const bf16* Bl;
    if (t < 128) {
        gi = iota + t * 128; si = gi; Bh = wch; Bl = wcl;
    } else if (t < 1664) {
        int u = t - 128, z = u >> 8, e = (u & 255) * 128;
        gi = pre_v + z * NE + e; si = pre_u + z * NE + e;
        Bh = wph + (i64)z * DD; Bl = wpl + (i64)z * DD;
    } else if (t < 3200) {
        int u = t - 1664, z = u >> 8, e = (u & 255) * 128;
        gi = suc_v + z * NE + e; si = suc_u + z * NE + e;
        Bh = wsh + (i64)z * DD; Bl = wsl + (i64)z * DD;
    } else if (t < 3456) {
        int e = (t - 3200) * 128;
        gi = left_v + e; si = left_u + e; Bh = wlh; Bl = wll;
    } else {
        int e = (t - 3456) * 128;
        gi = right_v + e; si = right_u + e; Bh = wrh; Bl = wrl;
    }
    gemm_core<true, false, false, false>(
        Xh, Xl, D, Bh, Bl, D, T, D, 0, 0, 0, gi, si, 0, 0, 1.f, 1);
}

// ---------------- small kernels -------------------------------------------------
__global__ void split_f32(const float4* __restrict__ in, uint2* __restrict__ oh,
                          uint2* __restrict__ ol, int n4)
{
    int i = blockIdx.x * 256 + threadIdx.x;
    if (i < n4) {
        uint2 h, l;
        split4(in[i], h, l);
        oh[i] = h; ol[i] = l;
    }
}
__global__ void iota_k(int* p) {
    int i = blockIdx.x * 256 + threadIdx.x;
    if (i < M_ROWS) p[i] = i;
}
__global__ void zero_k(float4* p) {
    p[blockIdx.x * 256 + threadIdx.x] = make_float4(0.f, 0.f, 0.f, 0.f);
}

// V transpose: vt[b][d][j] = v[b][j][d], emit bf16 hi/lo
__global__ __launch_bounds__(256)
void transpose_vt(const float* __restrict__ v, bf16* __restrict__ vth, bf16* __restrict__ vtl)
{
    __shared__ float ts[32][33];
    const int b = blockIdx.z;
    const int j0 = blockIdx.x * 32, d0 = blockIdx.y * 32;
    const float* vb = v + (i64)b * NSEQ * D;
    const i64 ob = (i64)b * D * NSEQ;
    const int tx = threadIdx.x, ty = threadIdx.y;
    #pragma unroll
    for (int i = 0; i < 32; i += 8)
        ts[ty + i][tx] = vb[(i64)(j0 + ty + i) * D + d0 + tx];
    __syncthreads();
    #pragma unroll
    for (int i = 0; i < 32; i += 8) {
        float val = ts[tx][ty + i];
        bf16 h = __float2bfloat16(val);
        bf16 l = __float2bfloat16(val - __bfloat162float(h));
        i64 o = ob + (i64)(d0 + ty + i) * NSEQ + j0 + tx;
        vth[o] = h; vtl[o] = l;
    }
}

// row softmax over 1024, emit bf16 hi/lo splits
__global__ __launch_bounds__(256)
void softmax_k(const float* __restrict__ Sc, bf16* __restrict__ oh, bf16* __restrict__ ol)
{
    i64 row = blockIdx.x;
    const float4* p = reinterpret_cast<const float4*>(Sc + row * NSEQ);
    int t = threadIdx.x;
    float4 v = p[t];
    float mx = fmaxf(fmaxf(v.x, v.y), fmaxf(v.z, v.w));
    #pragma unroll
    for (int o = 16; o; o >>= 1) mx = fmaxf(mx, __shfl_xor_sync(0xffffffffu, mx, o));
    __shared__ float red8[8];
    int w = t >> 5;
    if ((t & 31) == 0) red8[w] = mx;
    __syncthreads();
    mx = red8[0];
    #pragma unroll
    for (int i = 1; i < 8; i++) mx = fmaxf(mx, red8[i]);
    v.x = expf(v.x - mx); v.y = expf(v.y - mx);
    v.z = expf(v.z - mx); v.w = expf(v.w - mx);
    float s = v.x + v.y + v.z + v.w;
    #pragma unroll
    for (int o = 16; o; o >>= 1) s += __shfl_xor_sync(0xffffffffu, s, o);
    __syncthreads();
    if ((t & 31) == 0) red8[w] = s;
    __syncthreads();
    s = red8[0] + red8[1] + red8[2] + red8[3] + red8[4] + red8[5] + red8[6] + red8[7];
    float inv = 1.0f / s;
    v.x *= inv; v.y *= inv; v.z *= inv; v.w *= inv;
    uint2 hv, lv;
    split4(v, hv, lv);
    *reinterpret_cast<uint2*>(oh + row * NSEQ + t * 4) = hv;
    *reinterpret_cast<uint2*>(ol + row * NSEQ + t * 4) = lv;
}

// group norm; OF32: write fp32 out; OSPLIT: write bf16 hi/lo; RES: add res + relu
template<bool RES, bool OF32, bool OSPLIT>
__global__ __launch_bounds__(128)
void gn_kernel(const float* __restrict__ in, float* __restrict__ out,
               bf16* __restrict__ outh, bf16* __restrict__ outl,
               const float* __restrict__ gw, const float* __restrict__ bw,
               const float* __restrict__ res)
{
    const i64 row = blockIdx.x;
    const int t = threadIdx.x;
    float v = in[row * D + t];
    float s1 = v, s2 = v * v;
    #pragma unroll
    for (int o = 16; o; o >>= 1) {
        s1 += __shfl_xor_sync(0xffffffffu, s1, o);
        s2 += __shfl_xor_sync(0xffffffffu, s2, o);
    }
    __shared__ float a1[4], a2[4];
    int w = t >> 5;
    if ((t & 31) == 0) { a1[w] = s1; a2[w] = s2; }
    __syncthreads();
    s1 = a1[0] + a1[1] + a1[2] + a1[3];
    s2 = a2[0] + a2[1] + a2[2] + a2[3];
    float mu = s1 * (1.0f / D);
    float var = s2 * (1.0f / D) - mu * mu;
    float y = (v - mu) * rsqrtf(var + 1e-5f) * gw[t] + bw[t];
    if (RES) y = fmaxf(y + res[row * D + t], 0.f);
    else     y = fmaxf(y, 0.f);
    if (OF32) out[row * D + t] = y;
    if (OSPLIT) {
        bf16 h = __float2bfloat16(y);
        bf16 l = __float2bfloat16(y - __bfloat162float(h));
        outh[row * D + t] = h;
        outl[row * D + t] = l;
    }
}

// ---------------- driver ---------------------------------------------------------
#define SMEM_SZ 131072

extern "C" void kernel_launch(void* const* d_in, const int* in_sizes, int n_in,
                              void* d_out, int out_size)
{
    (void)in_sizes; (void)n_in; (void)out_size;
    const float* ctrs   = (const float*)d_in[0];
    const float* feats  = (const float*)d_in[1];
    const float* Wq     = (const float*)d_in[2];
    const float* Wk     = (const float*)d_in[3];
    const float* Wv     = (const float*)d_in[4];
    const float* Wc     = (const float*)d_in[5];
    const float* Wp     = (const float*)d_in[6];
    const float* Ws     = (const float*)d_in[7];
    const float* Wl     = (const float*)d_in[8];
    const float* Wr     = (const float*)d_in[9];
    const float* Wc2    = (const float*)d_in[10];
    const float* g1     = (const float*)d_in[11];
    const float* b1     = (const float*)d_in[12];
    const float* g2     = (const float*)d_in[13];
    const float* b2     = (const float*)d_in[14];
    const int* pre_u    = (const int*)d_in[15];
    const int* pre_v    = (const int*)d_in[16];
    const int* suc_u    = (const int*)d_in[17];
    const int* suc_v    = (const int*)d_in[18];
    const int* left_u   = (const int*)d_in[19];
    const int* left_v   = (const int*)d_in[20];
    const int* right_u  = (const int*)d_in[21];
    const int* right_v  = (const int*)d_in[22];
    float* X = (float*)d_out;

    // resolve scratch symbols
    float *v, *sc, *T, *Z; int* iota;
    cudaGetSymbolAddress((void**)&v,  g_v);
    cudaGetSymbolAddress((void**)&sc, g_sc);
    cudaGetSymbolAddress((void**)&T,  g_T);
    cudaGetSymbolAddress((void**)&Z,  g_Z);
    cudaGetSymbolAddress((void**)&iota, g_iota);
    bf16 *ctrs_h, *ctrs_l, *feat_h, *feat_l, *q_h, *q_l, *k_h, *k_l, *vt_h, *vt_l;
    bf16 *x_h, *x_l, *y_h, *y_l, *sc_h, *sc_l;
    bf16 *wq_h, *wq_l, *wk_h, *wk_l, *wv_h, *wv_l;
    bf16 *wc_h, *wc_l, *wp_h, *wp_l, *ws_h, *ws_l, *wl_h, *wl_l, *wr_h, *wr_l, *w2_h, *w2_l;
    cudaGetSymbolAddress((void**)&ctrs_h, s_ctrs_h); cudaGetSymbolAddress((void**)&ctrs_l, s_ctrs_l);
    cudaGetSymbolAddress((void**)&feat_h, s_feat_h); cudaGetSymbolAddress((void**)&feat_l, s_feat_l);
    cudaGetSymbolAddress((void**)&q_h, s_q_h);       cudaGetSymbolAddress((void**)&q_l, s_q_l);
    cudaGetSymbolAddress((void**)&k_h, s_k_h);       cudaGetSymbolAddress((void**)&k_l, s_k_l);
    cudaGetSymbolAddress((void**)&vt_h, s_vt_h);     cudaGetSymbolAddress((void**)&vt_l, s_vt_l);
    cudaGetSymbolAddress((void**)&x_h, s_x_h);       cudaGetSymbolAddress((void**)&x_l, s_x_l);
    cudaGetSymbolAddress((void**)&y_h, s_y_h);       cudaGetSymbolAddress((void**)&y_l, s_y_l);
    cudaGetSymbolAddress((void**)&sc_h, s_sc_h);     cudaGetSymbolAddress((void**)&sc_l, s_sc_l);
    cudaGetSymbolAddress((void**)&wq_h, s_wq_h);     cudaGetSymbolAddress((void**)&wq_l, s_wq_l);
    cudaGetSymbolAddress((void**)&wk_h, s_wk_h);     cudaGetSymbolAddress((void**)&wk_l, s_wk_l);
    cudaGetSymbolAddress((void**)&wv_h, s_wv_h);     cudaGetSymbolAddress((void**)&wv_l, s_wv_l);
    cudaGetSymbolAddress((void**)&wc_h, s_wc_h);     cudaGetSymbolAddress((void**)&wc_l, s_wc_l);
    cudaGetSymbolAddress((void**)&wp_h, s_wp_h);     cudaGetSymbolAddress((void**)&wp_l, s_wp_l);
    cudaGetSymbolAddress((void**)&ws_h, s_ws_h);     cudaGetSymbolAddress((void**)&ws_l, s_ws_l);
    cudaGetSymbolAddress((void**)&wl_h, s_wl_h);     cudaGetSymbolAddress((void**)&wl_l, s_wl_l);
    cudaGetSymbolAddress((void**)&wr_h, s_wr_h);     cudaGetSymbolAddress((void**)&wr_l, s_wr_l);
    cudaGetSymbolAddress((void**)&w2_h, s_w2_h);     cudaGetSymbolAddress((void**)&w2_l, s_w2_l);

    cudaFuncSetAttribute((const void*)gemm_k<false,false,false,true >, cudaFuncAttributeMaxDynamicSharedMemorySize, SMEM_SZ);
    cudaFuncSetAttribute((const void*)gemm_k<false,false,true ,false>, cudaFuncAttributeMaxDynamicSharedMemorySize, SMEM_SZ);
    cudaFuncSetAttribute((const void*)gemm_k<false,true ,true ,true >, cudaFuncAttributeMaxDynamicSharedMemorySize, SMEM_SZ);
    cudaFuncSetAttribute((const void*)layer_scatter, cudaFuncAttributeMaxDynamicSharedMemorySize, SMEM_SZ);

    const float NF = 0.08838834764831845f;  // 1/sqrt(128)
    dim3 blk(256);

    // ---- one-shot conversions ----
    auto spl = [&](const float* src, bf16* dh, bf16* dl, int n) {
        int n4 = n / 4;
        split_f32<<<(n4 + 255) / 256, 256>>>((const float4*)src, (uint2*)dh, (uint2*)dl, n4);
    };
    spl(ctrs,  ctrs_h, ctrs_l, M_ROWS * D);
    spl(feats, feat_h, feat_l, M_ROWS * D);
    spl(Wq, wq_h, wq_l, DD);
    spl(Wk, wk_h, wk_l, DD);
    spl(Wv, wv_h, wv_l, DD);
    spl(Wc, wc_h, wc_l, NL * DD);
    spl(Wp, wp_h, wp_l, NL * NS * DD);
    spl(Ws, ws_h, ws_l, NL * NS * DD);
    spl(Wl, wl_h, wl_l, NL * DD);
    spl(Wr, wr_h, wr_l, NL * DD);
    spl(Wc2, w2_h, w2_l, NL * DD);
    iota_k<<<M_ROWS / 256, 256>>>(iota);

    // ---- attention ----
    gemm_k<false,false,false,true><<<dim3(128,1,1), blk, SMEM_SZ>>>(
        ctrs_h, ctrs_l, D, 0, wq_h, wq_l, D, 0, (float*)0, D, 0, q_h, q_l, 0, 0, 0, 0, 0, 1.f, 1);
    gemm_k<false,false,false,true><<<dim3(128,1,1), blk, SMEM_SZ>>>(
        feat_h, feat_l, D, 0, wk_h, wk_l, D, 0, (float*)0, D, 0, k_h, k_l, 0, 0, 0, 0, 0, 1.f, 1);
    gemm_k<false,false,true,false><<<dim3(128,1,1), blk, SMEM_SZ>>>(
        feat_h, feat_l, D, 0, wv_h, wv_l, D, 0, v, D, 0, 0, 0, 0, 0, 0, 0, 0, 1.f, 1);
    transpose_vt<<<dim3(NSEQ/32, D/32, BATCH), dim3(32,8)>>>(v, vt_h, vt_l);
    gemm_k<false,false,true,false><<<dim3(8,8,16), blk, SMEM_SZ>>>(
        q_h, q_l, D, (i64)NSEQ*D, k_h, k_l, D, (i64)NSEQ*D,
        sc, NSEQ, (i64)NSEQ*NSEQ, 0, 0, 0, 0, 0, 0, 0, NF, 1);
    softmax_k<<<M_ROWS, 256>>>(sc, sc_h, sc_l);
    gemm_k<false,true,true,true><<<dim3(8,1,16), blk, SMEM_SZ>>>(
        sc_h, sc_l, NSEQ, (i64)NSEQ*NSEQ, vt_h, vt_l, NSEQ, (i64)D*NSEQ,
        X, D, (i64)NSEQ*D, x_h, x_l, feats, (i64)NSEQ*D, 0, 0, 0, 1.f, 8);

    // ---- 4-layer fusion loop ----
    for (int i = 0; i < NL; i++) {
        zero_k<<<M_ROWS * D / 4 / 256, 256>>>((float4*)T);
        layer_scatter<<<3712, blk, SMEM_SZ>>>(
            x_h, x_l,
            wc_h + (i64)i*DD, wc_l + (i64)i*DD,
            wp_h + (i64)i*NS*DD, wp_l + (i64)i*NS*DD,
            ws_h + (i64)i*NS*DD, ws_l + (i64)i*NS*DD,
            wl_h + (i64)i*DD, wl_l + (i64)i*DD,
            wr_h + (i64)i*DD, wr_l + (i64)i*DD,
            T, iota, pre_u, pre_v, suc_u, suc_v, left_u, left_v, right_u, right_v);
        gn_kernel<false,false,true><<<M_ROWS, 128>>>(T, (float*)0, y_h, y_l,
                                                     g1 + i*D, b1 + i*D, (const float*)0);
        gemm_k<false,false,true,false><<<dim3(128,1,1), blk, SMEM_SZ>>>(
            y_h, y_l, D, 0, w2_h + (i64)i*DD, w2_l + (i64)i*DD, D, 0,
            Z, D, 0, 0, 0, 0, 0, 0, 0, 0, 1.f, 1);
        gn_kernel<true,true,true><<<M_ROWS, 128>>>(Z, X, x_h, x_l,
                                                   g2 + i*D, b2 + i*D, X);
    }
}

// round 5
// speedup vs baseline: 1.2163x; 1.2163x over previous
#include <cuda_runtime.h>
#include <cuda_fp16.h>
#include <math.h>
#include <stdint.h>

#define D 128
#define DD 16384
#define BATCH 16
#define NSEQ 1024
#define M_ROWS 16384
#define NE 32768
#define NS 6
#define NL 4

typedef unsigned long long u64;
typedef unsigned int u32;
typedef long long i64;
typedef __half f16;

// ---------------- scratch (fp32) ---------------------------------------------
__device__ __align__(256) float g_v [M_ROWS * D];
__device__ __align__(256) float g_sc[(size_t)BATCH * NSEQ * NSEQ];
__device__ __align__(256) float g_T [M_ROWS * D];
__device__ __align__(256) float g_Z [M_ROWS * D];
__device__ __align__(256) int   g_iota[M_ROWS];

// ---------------- scratch (fp16 hi/lo splits) ----------------------------------
__device__ __align__(256) f16 s_ctrs_h[M_ROWS*D],  s_ctrs_l[M_ROWS*D];
__device__ __align__(256) f16 s_feat_h[M_ROWS*D],  s_feat_l[M_ROWS*D];
__device__ __align__(256) f16 s_q_h[M_ROWS*D],     s_q_l[M_ROWS*D];
__device__ __align__(256) f16 s_k_h[M_ROWS*D],     s_k_l[M_ROWS*D];
__device__ __align__(256) f16 s_vt_h[M_ROWS*D],    s_vt_l[M_ROWS*D];
__device__ __align__(256) f16 s_x_h[M_ROWS*D],     s_x_l[M_ROWS*D];
__device__ __align__(256) f16 s_y_h[M_ROWS*D],     s_y_l[M_ROWS*D];
__device__ __align__(256) f16 s_sc_h[(size_t)BATCH*NSEQ*NSEQ], s_sc_l[(size_t)BATCH*NSEQ*NSEQ];
__device__ __align__(256) f16 s_wq_h[DD], s_wq_l[DD], s_wk_h[DD], s_wk_l[DD], s_wv_h[DD], s_wv_l[DD];
__device__ __align__(256) f16 s_wc_h[NL*DD],  s_wc_l[NL*DD];
__device__ __align__(256) f16 s_wp_h[NL*NS*DD], s_wp_l[NL*NS*DD];
__device__ __align__(256) f16 s_ws_h[NL*NS*DD], s_ws_l[NL*NS*DD];
__device__ __align__(256) f16 s_wl_h[NL*DD],  s_wl_l[NL*DD];
__device__ __align__(256) f16 s_wr_h[NL*DD],  s_wr_l[NL*DD];
__device__ __align__(256) f16 s_w2_h[NL*DD],  s_w2_l[NL*DD];

// ---------------- PTX helpers ------------------------------------------------
__device__ __forceinline__ u32 smem_u32(const void* p) {
    u32 a;
    asm("{ .reg .u64 t; cvta.to.shared.u64 t, %1; cvt.u32.u64 %0, t; }" : "=r"(a) : "l"(p));
    return a;
}
__device__ __forceinline__ void ldsm4(u32* r, u32 addr) {
    asm volatile("ldmatrix.sync.aligned.m8n8.x4.shared.b16 {%0,%1,%2,%3}, [%4];"
                 : "=r"(r[0]), "=r"(r[1]), "=r"(r[2]), "=r"(r[3]) : "r"(addr));
}
__device__ __forceinline__ void mma_f16(float* d, const u32* a, u32 b0, u32 b1) {
    asm volatile("mma.sync.aligned.m16n8k16.row.col.f32.f16.f16.f32 "
                 "{%0,%1,%2,%3}, {%4,%5,%6,%7}, {%8,%9}, {%0,%1,%2,%3};"
                 : "+f"(d[0]), "+f"(d[1]), "+f"(d[2]), "+f"(d[3])
                 : "r"(a[0]), "r"(a[1]), "r"(a[2]), "r"(a[3]), "r"(b0), "r"(b1));
}
__device__ __forceinline__ void red4(float* p, float a, float b, float c, float d) {
    asm volatile("red.global.add.v4.f32 [%0], {%1,%2,%3,%4};"
                 :: "l"(p), "f"(a), "f"(b), "f"(c), "f"(d) : "memory");
}
__device__ __forceinline__ void cp16_cg(u32 dst, const void* src) {
    asm volatile("cp.async.cg.shared.global [%0], [%1], 16;" :: "r"(dst), "l"(src));
}
__device__ __forceinline__ void cp16_ca(u32 dst, const void* src) {
    asm volatile("cp.async.ca.shared.global [%0], [%1], 16;" :: "r"(dst), "l"(src));
}
__device__ __forceinline__ void cp_commit() { asm volatile("cp.async.commit_group;" ::: "memory"); }
template<int N> __device__ __forceinline__ void cp_wait() {
    asm volatile("cp.async.wait_group %0;" :: "n"(N) : "memory");
}

// split fp32 float4 -> packed hi half2 pair + lo half2 pair
__device__ __forceinline__ void split4(float4 v, uint2& hv, uint2& lv) {
    __half2 h0 = __floats2half2_rn(v.x, v.y);
    __half2 h1 = __floats2half2_rn(v.z, v.w);
    float2 f0 = __half22float2(h0);
    float2 f1 = __half22float2(h1);
    __half2 l0 = __floats2half2_rn(v.x - f0.x, v.y - f0.y);
    __half2 l1 = __floats2half2_rn(v.z - f1.x, v.w - f1.y);
    hv = make_uint2(*(u32*)&h0, *(u32*)&h1);
    lv = make_uint2(*(u32*)&l0, *(u32*)&l1);
}

// ---------------- GEMM core ----------------------------------------------------
// C[m,n] (+)= scale * sum_k A[m,k]*B[n,k]; A split fp16 hi/lo (2 passes), B hi only.
// K = KT*128, double-buffered 64-wide K-halves via cp.async.
// SMEM: 2 stages x 3 x 16KB = 96KB; epilogue staging reuses it.
template<bool GS, bool RES, bool OF32, bool OSPLIT>
__device__ __forceinline__ void gemm_core(
    const f16* __restrict__ Ah, const f16* __restrict__ Al, int lda,
    const f16* __restrict__ Bh, int ldb,
    float* __restrict__ C, int ldc,
    f16* __restrict__ Ch, f16* __restrict__ Cl,
    const float* __restrict__ Fres,
    const int* __restrict__ gi, const int* __restrict__ si,
    int row0, int col0, float scale, int KT)
{
    extern __shared__ char sm[];
    const u32 sb = smem_u32(sm);
    const int tid = threadIdx.x;
    const int wid = tid >> 5, lane = tid & 31;
    const int m0w = (wid >> 1) * 32, n0w = (wid & 1) * 64;

    float acc[2][8][4];
    #pragma unroll
    for (int mi = 0; mi < 2; mi++)
        #pragma unroll
        for (int nj = 0; nj < 8; nj++)
            #pragma unroll
            for (int e = 0; e < 4; e++) acc[mi][nj][e] = 0.f;

    // per-lane ldmatrix components (pitch 128B, xor-by-(row&7) swizzle)
    const u32 a_rb = (u32)(m0w + (lane & 15)) * 128;
    const u32 b_rb = (u32)(n0w + ((lane >> 4) << 3) + (lane & 7)) * 128;
    const int a_hi = lane >> 4;
    const int b_hi = (lane >> 3) & 1;
    const int xr = lane & 7;

    // loader for half h into stage s (Ah, Al, Bh = 12 chunks per thread)
    const int r_ld = tid >> 1;
    const int c0_ld = (tid & 1) * 4;
    i64 arow_ld = GS ? (i64)__ldg(gi + r_ld) : (i64)(row0 + r_ld);
    const int H = 2 * KT;

    auto load_half = [&](int h, int s) {
        const int kofs = h * 64;
        const u32 base = sb + (u32)s * 49152u;
        const f16* ap  = Ah + arow_ld * (i64)lda + kofs;
        const f16* alp = Al + arow_ld * (i64)lda + kofs;
        const f16* bp  = Bh + (i64)(col0 + r_ld) * ldb + kofs;
        #pragma unroll
        for (int j = 0; j < 4; j++) {
            int c = c0_ld + j;
            u32 so = (u32)r_ld * 128 + (u32)((c ^ (r_ld & 7)) << 4);
            cp16_cg(base + so,          ap  + c * 8);
            cp16_cg(base + 16384 + so,  alp + c * 8);
            cp16_ca(base + 32768 + so,  bp  + c * 8);
        }
        cp_commit();
    };

    load_half(0, 0);
    for (int h = 0; h < H; h++) {
        const int s = h & 1;
        const bool more = (h + 1 < H);
        if (more) { load_half(h + 1, 1 - s); cp_wait<1>(); }
        else      { cp_wait<0>(); }
        __syncthreads();
        const u32 base = sb + (u32)s * 49152u;
        const u32 abase_h = base + a_rb;
        const u32 abase_l = base + 16384u + a_rb;
        const u32 bbase   = base + 32768u + b_rb;
        #pragma unroll
        for (int ks = 0; ks < 4; ks++) {
            const u32 aoff = (u32)(((ks * 2 + a_hi) ^ xr) << 4);
            const u32 boff = (u32)(((ks * 2 + b_hi) ^ xr) << 4);
            u32 b[4][4], ah0[4], ah1[4], al0[4], al1[4];
            #pragma unroll
            for (int p = 0; p < 4; p++)
                ldsm4(b[p], bbase + boff + p * 2048);
            ldsm4(ah0, abase_h + aoff);
            ldsm4(ah1, abase_h + aoff + 2048);
            ldsm4(al0, abase_l + aoff);
            ldsm4(al1, abase_l + aoff + 2048);
            #pragma unroll
            for (int nj = 0; nj < 8; nj++) {
                u32 bb0 = b[nj >> 1][(nj & 1) * 2], bb1 = b[nj >> 1][(nj & 1) * 2 + 1];
                mma_f16(acc[0][nj], ah0, bb0, bb1);
                mma_f16(acc[1][nj], ah1, bb0, bb1);
                mma_f16(acc[0][nj], al0, bb0, bb1);
                mma_f16(acc[1][nj], al1, bb0, bb1);
            }
        }
        __syncthreads();
    }

    // ---- stage C to SMEM (pitch 132 floats), then output ----
    float* Cs = reinterpret_cast<float*>(sm);
    const int g = lane >> 2, q2 = (lane & 3) * 2;
    #pragma unroll
    for (int mi = 0; mi < 2; mi++)
        #pragma unroll
        for (int nj = 0; nj < 8; nj++) {
            int r = m0w + mi * 16 + g;
            int c = n0w + nj * 8 + q2;
            Cs[r * 132 + c]           = acc[mi][nj][0];
            Cs[r * 132 + c + 1]       = acc[mi][nj][1];
            Cs[(r + 8) * 132 + c]     = acc[mi][nj][2];
            Cs[(r + 8) * 132 + c + 1] = acc[mi][nj][3];
        }
    __syncthreads();

    const int rr = tid >> 1, hh = tid & 1;
    const float* srow = Cs + rr * 132 + hh * 64;
    if (GS) {
        i64 drow = (i64)__ldg(si + rr);
        float* p = C + drow * (i64)ldc + col0 + hh * 64;
        #pragma unroll
        for (int j = 0; j < 16; j++) {
            float4 vv = *reinterpret_cast<const float4*>(srow + j * 4);
            red4(p + j * 4, vv.x, vv.y, vv.z, vv.w);
        }
    } else {
        const i64 ro = (i64)(row0 + rr) * ldc + col0 + hh * 64;
        const float* fp = RES ? (Fres + ro) : (const float*)0;
        float* p = OF32 ? (C + ro) : (float*)0;
        #pragma unroll
        for (int j = 0; j < 16; j++) {
            float4 vv = *reinterpret_cast<const float4*>(srow + j * 4);
            vv.x *= scale; vv.y *= scale; vv.z *= scale; vv.w *= scale;
            if (RES) {
                float4 f = *reinterpret_cast<const float4*>(fp + j * 4);
                vv.x += f.x; vv.y += f.y; vv.z += f.z; vv.w += f.w;
            }
            if (OF32) *reinterpret_cast<float4*>(p + j * 4) = vv;
            if (OSPLIT) {
                uint2 hv, lv;
                split4(vv, hv, lv);
                *reinterpret_cast<uint2*>(Ch + ro + j * 4) = hv;
                *reinterpret_cast<uint2*>(Cl + ro + j * 4) = lv;
            }
        }
    }
}

// ---------------- GEMM wrapper kernels -----------------------------------------
template<bool GS, bool RES, bool OF32, bool OSPLIT>
__global__ __launch_bounds__(256, 1)
void gemm_k(const f16* Ah, const f16* Al, int lda, i64 aZ,
            const f16* Bh, int ldb, i64 bZ,
            float* C, int ldc, i64 cZ,
            f16* Ch, f16* Cl,
            const float* Fres, i64 fZ,
            const int* gidx, const int* sidx, i64 iZ,
            float scale, int KT)
{
    const int z = blockIdx.z;
    const int row0 = blockIdx.x * 128, col0 = blockIdx.y * 128;
    gemm_core<GS, RES, OF32, OSPLIT>(
        Ah + (i64)z * aZ, Al + (i64)z * aZ, lda,
        Bh + (i64)z * bZ, ldb,
        C + (i64)z * cZ, ldc,
        OSPLIT ? Ch + (i64)z * cZ : (f16*)0, OSPLIT ? Cl + (i64)z * cZ : (f16*)0,
        RES ? Fres + (i64)z * fZ : (const float*)0,
        GS ? gidx + (i64)z * iZ + row0 : (const int*)0,
        GS ? sidx + (i64)z * iZ + row0 : (const int*)0,
        row0, col0, scale, KT);
}

// ---------------- fused per-layer scatter launch (3712 CTAs) -------------------
__global__ __launch_bounds__(256, 1)
void layer_scatter(const f16* Xh, const f16* Xl,
                   const f16* wch, const f16* wph, const f16* wsh,
                   const f16* wlh, const f16* wrh,
                   float* T,
                   const int* iota,
                   const int* pre_u, const int* pre_v,
                   const int* suc_u, const int* suc_v,
                   const int* left_u, const int* left_v,
                   const int* right_u, const int* right_v)
{
    const int t = blockIdx.x;
    const int* gi; const int* si; const f16* Bh;
    if (t < 128) {
        gi = iota + t * 128; si = gi; Bh = wch;
    } else if (t < 1664) {
        int u = t - 128, z = u >> 8, e = (u & 255) * 128;
        gi = pre_v + z * NE + e; si = pre_u + z * NE + e;
        Bh = wph + (i64)z * DD;
    } else if (t < 3200) {
        int u = t - 1664, z = u >> 8, e = (u & 255) * 128;
        gi = suc_v + z * NE + e; si = suc_u + z * NE + e;
        Bh = wsh + (i64)z * DD;
    } else if (t < 3456) {
        int e = (t - 3200) * 128;
        gi = left_v + e; si = left_u + e; Bh = wlh;
    } else {
        int e = (t - 3456) * 128;
        gi = right_v + e; si = right_u + e; Bh = wrh;
    }
    gemm_core<true, false, false, false>(
        Xh, Xl, D, Bh, D, T, D, 0, 0, 0, gi, si, 0, 0, 1.f, 1);
}

// ---------------- small kernels -------------------------------------------------
__global__ void split_f32(const float4* __restrict__ in, uint2* __restrict__ oh,
                          uint2* __restrict__ ol, int n4)
{
    int i = blockIdx.x * 256 + threadIdx.x;
    if (i < n4) {
        uint2 h, l;
        split4(in[i], h, l);
        oh[i] = h; ol[i] = l;
    }
}
__global__ void iota_k(int* p) {
    int i = blockIdx.x * 256 + threadIdx.x;
    if (i < M_ROWS) p[i] = i;
}
__global__ void zero_k(float4* p) {
    p[blockIdx.x * 256 + threadIdx.x] = make_float4(0.f, 0.f, 0.f, 0.f);
}

// V transpose: vt[b][d][j] = v[b][j][d], emit fp16 hi (B-side only needs hi)
__global__ __launch_bounds__(256)
void transpose_vt(const float* __restrict__ v, f16* __restrict__ vth)
{
    __shared__ float ts[32][33];
    const int b = blockIdx.z;
    const int j0 = blockIdx.x * 32, d0 = blockIdx.y * 32;
    const float* vb = v + (i64)b * NSEQ * D;
    const i64 ob = (i64)b * D * NSEQ;
    const int tx = threadIdx.x, ty = threadIdx.y;
    #pragma unroll
    for (int i = 0; i < 32; i += 8)
        ts[ty + i][tx] = vb[(i64)(j0 + ty + i) * D + d0 + tx];
    __syncthreads();
    #pragma unroll
    for (int i = 0; i < 32; i += 8) {
        i64 o = ob + (i64)(d0 + ty + i) * NSEQ + j0 + tx;
        vth[o] = __float2half(ts[tx][ty + i]);
    }
}

// row softmax over 1024, emit fp16 hi/lo splits (A-side of PV)
__global__ __launch_bounds__(256)
void softmax_k(const float* __restrict__ Sc, f16* __restrict__ oh, f16* __restrict__ ol)
{
    i64 row = blockIdx.x;
    const float4* p = reinterpret_cast<const float4*>(Sc + row * NSEQ);
    int t = threadIdx.x;
    float4 v = p[t];
    float mx = fmaxf(fmaxf(v.x, v.y), fmaxf(v.z, v.w));
    #pragma unroll
    for (int o = 16; o; o >>= 1) mx = fmaxf(mx, __shfl_xor_sync(0xffffffffu, mx, o));
    __shared__ float red8[8];
    int w = t >> 5;
    if ((t & 31) == 0) red8[w] = mx;
    __syncthreads();
    mx = red8[0];
    #pragma unroll
    for (int i = 1; i < 8; i++) mx = fmaxf(mx, red8[i]);
    v.x = expf(v.x - mx); v.y = expf(v.y - mx);
    v.z = expf(v.z - mx); v.w = expf(v.w - mx);
    float s = v.x + v.y + v.z + v.w;
    #pragma unroll
    for (int o = 16; o; o >>= 1) s += __shfl_xor_sync(0xffffffffu, s, o);
    __syncthreads();
    if ((t & 31) == 0) red8[w] = s;
    __syncthreads();
    s = red8[0] + red8[1] + red8[2] + red8[3] + red8[4] + red8[5] + red8[6] + red8[7];
    float inv = 1.0f / s;
    v.x *= inv; v.y *= inv; v.z *= inv; v.w *= inv;
    uint2 hv, lv;
    split4(v, hv, lv);
    *reinterpret_cast<uint2*>(oh + row * NSEQ + t * 4) = hv;
    *reinterpret_cast<uint2*>(ol + row * NSEQ + t * 4) = lv;
}

// group norm; OF32: write fp32 out; OSPLIT: write fp16 hi/lo; RES: add res + relu
template<bool RES, bool OF32, bool OSPLIT>
__global__ __launch_bounds__(128)
void gn_kernel(const float* __restrict__ in, float* __restrict__ out,
               f16* __restrict__ outh, f16* __restrict__ outl,
               const float* __restrict__ gw, const float* __restrict__ bw,
               const float* __restrict__ res)
{
    const i64 row = blockIdx.x;
    const int t = threadIdx.x;
    float v = in[row * D + t];
    float s1 = v, s2 = v * v;
    #pragma unroll
    for (int o = 16; o; o >>= 1) {
        s1 += __shfl_xor_sync(0xffffffffu, s1, o);
        s2 += __shfl_xor_sync(0xffffffffu, s2, o);
    }
    __shared__ float a1[4], a2[4];
    int w = t >> 5;
    if ((t & 31) == 0) { a1[w] = s1; a2[w] = s2; }
    __syncthreads();
    s1 = a1[0] + a1[1] + a1[2] + a1[3];
    s2 = a2[0] + a2[1] + a2[2] + a2[3];
    float mu = s1 * (1.0f / D);
    float var = s2 * (1.0f / D) - mu * mu;
    float y = (v - mu) * rsqrtf(var + 1e-5f) * gw[t] + bw[t];
    if (RES) y = fmaxf(y + res[row * D + t], 0.f);
    else     y = fmaxf(y, 0.f);
    if (OF32) out[row * D + t] = y;
    if (OSPLIT) {
        f16 h = __float2half(y);
        f16 l = __float2half(y - __half2float(h));
        outh[row * D + t] = h;
        outl[row * D + t] = l;
    }
}

// ---------------- driver ---------------------------------------------------------
#define SMEM_SZ 98304

extern "C" void kernel_launch(void* const* d_in, const int* in_sizes, int n_in,
                              void* d_out, int out_size)
{
    (void)in_sizes; (void)n_in; (void)out_size;
    const float* ctrs   = (const float*)d_in[0];
    const float* feats  = (const float*)d_in[1];
    const float* Wq     = (const float*)d_in[2];
    const float* Wk     = (const float*)d_in[3];
    const float* Wv     = (const float*)d_in[4];
    const float* Wc     = (const float*)d_in[5];
    const float* Wp     = (const float*)d_in[6];
    const float* Ws     = (const float*)d_in[7];
    const float* Wl     = (const float*)d_in[8];
    const float* Wr     = (const float*)d_in[9];
    const float* Wc2    = (const float*)d_in[10];
    const float* g1     = (const float*)d_in[11];
    const float* b1     = (const float*)d_in[12];
    const float* g2     = (const float*)d_in[13];
    const float* b2     = (const float*)d_in[14];
    const int* pre_u    = (const int*)d_in[15];
    const int* pre_v    = (const int*)d_in[16];
    const int* suc_u    = (const int*)d_in[17];
    const int* suc_v    = (const int*)d_in[18];
    const int* left_u   = (const int*)d_in[19];
    const int* left_v   = (const int*)d_in[20];
    const int* right_u  = (const int*)d_in[21];
    const int* right_v  = (const int*)d_in[22];
    float* X = (float*)d_out;

    float *v, *sc, *T, *Z; int* iota;
    cudaGetSymbolAddress((void**)&v,  g_v);
    cudaGetSymbolAddress((void**)&sc, g_sc);
    cudaGetSymbolAddress((void**)&T,  g_T);
    cudaGetSymbolAddress((void**)&Z,  g_Z);
    cudaGetSymbolAddress((void**)&iota, g_iota);
    f16 *ctrs_h, *ctrs_l, *feat_h, *feat_l, *q_h, *q_l, *k_h, *k_l, *vt_h, *vt_l;
    f16 *x_h, *x_l, *y_h, *y_l, *sc_h, *sc_l;
    f16 *wq_h, *wq_l, *wk_h, *wk_l, *wv_h, *wv_l;
    f16 *wc_h, *wc_l, *wp_h, *wp_l, *ws_h, *ws_l, *wl_h, *wl_l, *wr_h, *wr_l, *w2_h, *w2_l;
    cudaGetSymbolAddress((void**)&ctrs_h, s_ctrs_h); cudaGetSymbolAddress((void**)&ctrs_l, s_ctrs_l);
    cudaGetSymbolAddress((void**)&feat_h, s_feat_h); cudaGetSymbolAddress((void**)&feat_l, s_feat_l);
    cudaGetSymbolAddress((void**)&q_h, s_q_h);       cudaGetSymbolAddress((void**)&q_l, s_q_l);
    cudaGetSymbolAddress((void**)&k_h, s_k_h);       cudaGetSymbolAddress((void**)&k_l, s_k_l);
    cudaGetSymbolAddress((void**)&vt_h, s_vt_h);     cudaGetSymbolAddress((void**)&vt_l, s_vt_l);
    cudaGetSymbolAddress((void**)&x_h, s_x_h);       cudaGetSymbolAddress((void**)&x_l, s_x_l);
    cudaGetSymbolAddress((void**)&y_h, s_y_h);       cudaGetSymbolAddress((void**)&y_l, s_y_l);
    cudaGetSymbolAddress((void**)&sc_h, s_sc_h);     cudaGetSymbolAddress((void**)&sc_l, s_sc_l);
    cudaGetSymbolAddress((void**)&wq_h, s_wq_h);     cudaGetSymbolAddress((void**)&wq_l, s_wq_l);
    cudaGetSymbolAddress((void**)&wk_h, s_wk_h);     cudaGetSymbolAddress((void**)&wk_l, s_wk_l);
    cudaGetSymbolAddress((void**)&wv_h, s_wv_h);     cudaGetSymbolAddress((void**)&wv_l, s_wv_l);
    cudaGetSymbolAddress((void**)&wc_h, s_wc_h);     cudaGetSymbolAddress((void**)&wc_l, s_wc_l);
    cudaGetSymbolAddress((void**)&wp_h, s_wp_h);     cudaGetSymbolAddress((void**)&wp_l, s_wp_l);
    cudaGetSymbolAddress((void**)&ws_h, s_ws_h);     cudaGetSymbolAddress((void**)&ws_l, s_ws_l);
    cudaGetSymbolAddress((void**)&wl_h, s_wl_h);     cudaGetSymbolAddress((void**)&wl_l, s_wl_l);
    cudaGetSymbolAddress((void**)&wr_h, s_wr_h);     cudaGetSymbolAddress((void**)&wr_l, s_wr_l);
    cudaGetSymbolAddress((void**)&w2_h, s_w2_h);     cudaGetSymbolAddress((void**)&w2_l, s_w2_l);

    cudaFuncSetAttribute((const void*)gemm_k<false,false,false,true >, cudaFuncAttributeMaxDynamicSharedMemorySize, SMEM_SZ);
    cudaFuncSetAttribute((const void*)gemm_k<false,false,true ,false>, cudaFuncAttributeMaxDynamicSharedMemorySize, SMEM_SZ);
    cudaFuncSetAttribute((const void*)gemm_k<false,true ,true ,true >, cudaFuncAttributeMaxDynamicSharedMemorySize, SMEM_SZ);
    cudaFuncSetAttribute((const void*)layer_scatter, cudaFuncAttributeMaxDynamicSharedMemorySize, SMEM_SZ);

    const float NF = 0.08838834764831845f;  // 1/sqrt(128)
    dim3 blk(256);

    // ---- one-shot conversions ----
    auto spl = [&](const float* src, f16* dh, f16* dl, int n) {
        int n4 = n / 4;
        split_f32<<<(n4 + 255) / 256, 256>>>((const float4*)src, (uint2*)dh, (uint2*)dl, n4);
    };
    spl(ctrs,  ctrs_h, ctrs_l, M_ROWS * D);
    spl(feats, feat_h, feat_l, M_ROWS * D);
    spl(Wq, wq_h, wq_l, DD);
    spl(Wk, wk_h, wk_l, DD);
    spl(Wv, wv_h, wv_l, DD);
    spl(Wc, wc_h, wc_l, NL * DD);
    spl(Wp, wp_h, wp_l, NL * NS * DD);
    spl(Ws, ws_h, ws_l, NL * NS * DD);
    spl(Wl, wl_h, wl_l, NL * DD);
    spl(Wr, wr_h, wr_l, NL * DD);
    spl(Wc2, w2_h, w2_l, NL * DD);
    iota_k<<<M_ROWS / 256, 256>>>(iota);

    // ---- attention ----
    gemm_k<false,false,false,true><<<dim3(128,1,1), blk, SMEM_SZ>>>(
        ctrs_h, ctrs_l, D, 0, wq_h, D, 0, (float*)0, D, 0, q_h, q_l, 0, 0, 0, 0, 0, 1.f, 1);
    gemm_k<false,false,false,true><<<dim3(128,1,1), blk, SMEM_SZ>>>(
        feat_h, feat_l, D, 0, wk_h, D, 0, (float*)0, D, 0, k_h, k_l, 0, 0, 0, 0, 0, 1.f, 1);
    gemm_k<false,false,true,false><<<dim3(128,1,1), blk, SMEM_SZ>>>(
        feat_h, feat_l, D, 0, wv_h, D, 0, v, D, 0, 0, 0, 0, 0, 0, 0, 0, 1.f, 1);
    transpose_vt<<<dim3(NSEQ/32, D/32, BATCH), dim3(32,8)>>>(v, vt_h);
    gemm_k<false,false,true,false><<<dim3(8,8,16), blk, SMEM_SZ>>>(
        q_h, q_l, D, (i64)NSEQ*D, k_h, D, (i64)NSEQ*D,
        sc, NSEQ, (i64)NSEQ*NSEQ, 0, 0, 0, 0, 0, 0, 0, NF, 1);
    softmax_k<<<M_ROWS, 256>>>(sc, sc_h, sc_l);
    gemm_k<false,true,true,true><<<dim3(8,1,16), blk, SMEM_SZ>>>(
        sc_h, sc_l, NSEQ, (i64)NSEQ*NSEQ, vt_h, NSEQ, (i64)D*NSEQ,
        X, D, (i64)NSEQ*D, x_h, x_l, feats, (i64)NSEQ*D, 0, 0, 0, 1.f, 8);

    // ---- 4-layer fusion loop ----
    for (int i = 0; i < NL; i++) {
        zero_k<<<M_ROWS * D / 4 / 256, 256>>>((float4*)T);
        layer_scatter<<<3712, blk, SMEM_SZ>>>(
            x_h, x_l,
            wc_h + (i64)i*DD,
            wp_h + (i64)i*NS*DD,
            ws_h + (i64)i*NS*DD,
            wl_h + (i64)i*DD,
            wr_h + (i64)i*DD,
            T, iota, pre_u, pre_v, suc_u, suc_v, left_u, left_v, right_u, right_v);
        gn_kernel<false,false,true><<<M_ROWS, 128>>>(T, (float*)0, y_h, y_l,
                                                     g1 + i*D, b1 + i*D, (const float*)0);
        gemm_k<false,false,true,false><<<dim3(128,1,1), blk, SMEM_SZ>>>(
            y_h, y_l, D, 0, w2_h + (i64)i*DD, D, 0,
            Z, D, 0, 0, 0, 0, 0, 0, 0, 0, 1.f, 1);
        gn_kernel<true,true,true><<<M_ROWS, 128>>>(Z, X, x_h, x_l,
                                                   g2 + i*D, b2 + i*D, X);
    }
}

// round 6
// speedup vs baseline: 1.3962x; 1.1479x over previous
#include <cuda_runtime.h>
#include <cuda_fp16.h>
#include <math.h>
#include <stdint.h>

#define D 128
#define DD 16384
#define BATCH 16
#define NSEQ 1024
#define M_ROWS 16384
#define NE 32768
#define NS 6
#define NL 4

typedef unsigned long long u64;
typedef unsigned int u32;
typedef long long i64;
typedef __half f16;

// ---------------- scratch (fp32) ---------------------------------------------
__device__ __align__(256) float g_v [M_ROWS * D];
__device__ __align__(256) float g_sc[(size_t)BATCH * NSEQ * NSEQ];
__device__ __align__(256) float g_T [M_ROWS * D];
__device__ __align__(256) float g_Z [M_ROWS * D];
__device__ __align__(256) int   g_iota[M_ROWS];

// ---------------- scratch (fp16 hi/lo splits) ----------------------------------
__device__ __align__(256) f16 s_ctrs_h[M_ROWS*D],  s_ctrs_l[M_ROWS*D];
__device__ __align__(256) f16 s_feat_h[M_ROWS*D],  s_feat_l[M_ROWS*D];
__device__ __align__(256) f16 s_q_h[M_ROWS*D],     s_q_l[M_ROWS*D];
__device__ __align__(256) f16 s_k_h[M_ROWS*D],     s_k_l[M_ROWS*D];
__device__ __align__(256) f16 s_vt_h[M_ROWS*D];
__device__ __align__(256) f16 s_x_h[M_ROWS*D],     s_x_l[M_ROWS*D];
__device__ __align__(256) f16 s_y_h[M_ROWS*D],     s_y_l[M_ROWS*D];
__device__ __align__(256) f16 s_sc_h[(size_t)BATCH*NSEQ*NSEQ], s_sc_l[(size_t)BATCH*NSEQ*NSEQ];
__device__ __align__(256) f16 s_wq_h[DD], s_wk_h[DD], s_wv_h[DD];
__device__ __align__(256) f16 s_wc_h[NL*DD];
__device__ __align__(256) f16 s_wp_h[NL*NS*DD];
__device__ __align__(256) f16 s_ws_h[NL*NS*DD];
__device__ __align__(256) f16 s_wl_h[NL*DD];
__device__ __align__(256) f16 s_wr_h[NL*DD];
__device__ __align__(256) f16 s_w2_h[NL*DD];

// ---------------- PTX helpers ------------------------------------------------
__device__ __forceinline__ u32 smem_u32(const void* p) {
    u32 a;
    asm("{ .reg .u64 t; cvta.to.shared.u64 t, %1; cvt.u32.u64 %0, t; }" : "=r"(a) : "l"(p));
    return a;
}
__device__ __forceinline__ void ldsm4(u32* r, u32 addr) {
    asm volatile("ldmatrix.sync.aligned.m8n8.x4.shared.b16 {%0,%1,%2,%3}, [%4];"
                 : "=r"(r[0]), "=r"(r[1]), "=r"(r[2]), "=r"(r[3]) : "r"(addr));
}
__device__ __forceinline__ void mma_f16(float* d, const u32* a, u32 b0, u32 b1) {
    asm volatile("mma.sync.aligned.m16n8k16.row.col.f32.f16.f16.f32 "
                 "{%0,%1,%2,%3}, {%4,%5,%6,%7}, {%8,%9}, {%0,%1,%2,%3};"
                 : "+f"(d[0]), "+f"(d[1]), "+f"(d[2]), "+f"(d[3])
                 : "r"(a[0]), "r"(a[1]), "r"(a[2]), "r"(a[3]), "r"(b0), "r"(b1));
}
__device__ __forceinline__ void red4(float* p, float a, float b, float c, float d) {
    asm volatile("red.global.add.v4.f32 [%0], {%1,%2,%3,%4};"
                 :: "l"(p), "f"(a), "f"(b), "f"(c), "f"(d) : "memory");
}
__device__ __forceinline__ void cp16_cg(u32 dst, const void* src) {
    asm volatile("cp.async.cg.shared.global [%0], [%1], 16;" :: "r"(dst), "l"(src));
}
__device__ __forceinline__ void cp16_ca(u32 dst, const void* src) {
    asm volatile("cp.async.ca.shared.global [%0], [%1], 16;" :: "r"(dst), "l"(src));
}
__device__ __forceinline__ void cp_commit() { asm volatile("cp.async.commit_group;" ::: "memory"); }
template<int N> __device__ __forceinline__ void cp_wait() {
    asm volatile("cp.async.wait_group %0;" :: "n"(N) : "memory");
}

// split fp32 float4 -> packed hi half2 pair + lo half2 pair
__device__ __forceinline__ void split4(float4 v, uint2& hv, uint2& lv) {
    __half2 h0 = __floats2half2_rn(v.x, v.y);
    __half2 h1 = __floats2half2_rn(v.z, v.w);
    float2 f0 = __half22float2(h0);
    float2 f1 = __half22float2(h1);
    __half2 l0 = __floats2half2_rn(v.x - f0.x, v.y - f0.y);
    __half2 l1 = __floats2half2_rn(v.z - f1.x, v.w - f1.y);
    hv = make_uint2(*(u32*)&h0, *(u32*)&h1);
    lv = make_uint2(*(u32*)&l0, *(u32*)&l1);
}

// ---------------- GEMM core ----------------------------------------------------
// C[m,n] (+)= scale * sum_k A[m,k]*B[n,k]; A split fp16 hi/lo (2 passes), B hi only.
// K = KT*128, double-buffered 64-wide K-halves via cp.async.
// SMEM: 2 stages x 3 x 16KB = 96KB -> 2 CTAs/SM co-resident (192KB of 228KB).
template<bool GS, bool RES, bool OF32, bool OSPLIT>
__device__ __forceinline__ void gemm_core(
    const f16* __restrict__ Ah, const f16* __restrict__ Al, int lda,
    const f16* __restrict__ Bh, int ldb,
    float* __restrict__ C, int ldc,
    f16* __restrict__ Ch, f16* __restrict__ Cl,
    const float* __restrict__ Fres,
    const int* __restrict__ gi, const int* __restrict__ si,
    int row0, int col0, float scale, int KT)
{
    extern __shared__ char sm[];
    const u32 sb = smem_u32(sm);
    const int tid = threadIdx.x;
    const int wid = tid >> 5, lane = tid & 31;
    const int m0w = (wid >> 1) * 32, n0w = (wid & 1) * 64;

    float acc[2][8][4];
    #pragma unroll
    for (int mi = 0; mi < 2; mi++)
        #pragma unroll
        for (int nj = 0; nj < 8; nj++)
            #pragma unroll
            for (int e = 0; e < 4; e++) acc[mi][nj][e] = 0.f;

    // per-lane ldmatrix components (pitch 128B, xor-by-(row&7) swizzle)
    const u32 a_rb = (u32)(m0w + (lane & 15)) * 128;
    const u32 b_rb = (u32)(n0w + ((lane >> 4) << 3) + (lane & 7)) * 128;
    const int a_hi = lane >> 4;
    const int b_hi = (lane >> 3) & 1;
    const int xr = lane & 7;

    // loader for half h into stage s (Ah, Al, Bh = 12 chunks per thread)
    const int r_ld = tid >> 1;
    const int c0_ld = (tid & 1) * 4;
    i64 arow_ld = GS ? (i64)__ldg(gi + r_ld) : (i64)(row0 + r_ld);
    const int H = 2 * KT;

    auto load_half = [&](int h, int s) {
        const int kofs = h * 64;
        const u32 base = sb + (u32)s * 49152u;
        const f16* ap  = Ah + arow_ld * (i64)lda + kofs;
        const f16* alp = Al + arow_ld * (i64)lda + kofs;
        const f16* bp  = Bh + (i64)(col0 + r_ld) * ldb + kofs;
        #pragma unroll
        for (int j = 0; j < 4; j++) {
            int c = c0_ld + j;
            u32 so = (u32)r_ld * 128 + (u32)((c ^ (r_ld & 7)) << 4);
            cp16_cg(base + so,          ap  + c * 8);
            cp16_cg(base + 16384 + so,  alp + c * 8);
            cp16_ca(base + 32768 + so,  bp  + c * 8);
        }
        cp_commit();
    };

    load_half(0, 0);
    for (int h = 0; h < H; h++) {
        const int s = h & 1;
        const bool more = (h + 1 < H);
        if (more) { load_half(h + 1, 1 - s); cp_wait<1>(); }
        else      { cp_wait<0>(); }
        __syncthreads();
        const u32 base = sb + (u32)s * 49152u;
        const u32 abase_h = base + a_rb;
        const u32 abase_l = base + 16384u + a_rb;
        const u32 bbase   = base + 32768u + b_rb;
        #pragma unroll
        for (int ks = 0; ks < 4; ks++) {
            const u32 aoff = (u32)(((ks * 2 + a_hi) ^ xr) << 4);
            const u32 boff = (u32)(((ks * 2 + b_hi) ^ xr) << 4);
            u32 b[4][4], ah0[4], ah1[4], al0[4], al1[4];
            #pragma unroll
            for (int p = 0; p < 4; p++)
                ldsm4(b[p], bbase + boff + p * 2048);
            ldsm4(ah0, abase_h + aoff);
            ldsm4(ah1, abase_h + aoff + 2048);
            ldsm4(al0, abase_l + aoff);
            ldsm4(al1, abase_l + aoff + 2048);
            #pragma unroll
            for (int nj = 0; nj < 8; nj++) {
                u32 bb0 = b[nj >> 1][(nj & 1) * 2], bb1 = b[nj >> 1][(nj & 1) * 2 + 1];
                mma_f16(acc[0][nj], ah0, bb0, bb1);
                mma_f16(acc[1][nj], ah1, bb0, bb1);
                mma_f16(acc[0][nj], al0, bb0, bb1);
                mma_f16(acc[1][nj], al1, bb0, bb1);
            }
        }
        __syncthreads();
    }

    // ---- stage C to SMEM (pitch 132 floats), then output ----
    float* Cs = reinterpret_cast<float*>(sm);
    const int g = lane >> 2, q2 = (lane & 3) * 2;
    #pragma unroll
    for (int mi = 0; mi < 2; mi++)
        #pragma unroll
        for (int nj = 0; nj < 8; nj++) {
            int r = m0w + mi * 16 + g;
            int c = n0w + nj * 8 + q2;
            Cs[r * 132 + c]           = acc[mi][nj][0];
            Cs[r * 132 + c + 1]       = acc[mi][nj][1];
            Cs[(r + 8) * 132 + c]     = acc[mi][nj][2];
            Cs[(r + 8) * 132 + c + 1] = acc[mi][nj][3];
        }
    __syncthreads();

    const int rr = tid >> 1, hh = tid & 1;
    const float* srow = Cs + rr * 132 + hh * 64;
    if (GS) {
        i64 drow = (i64)__ldg(si + rr);
        float* p = C + drow * (i64)ldc + col0 + hh * 64;
        #pragma unroll
        for (int j = 0; j < 16; j++) {
            float4 vv = *reinterpret_cast<const float4*>(srow + j * 4);
            red4(p + j * 4, vv.x, vv.y, vv.z, vv.w);
        }
    } else {
        const i64 ro = (i64)(row0 + rr) * ldc + col0 + hh * 64;
        const float* fp = RES ? (Fres + ro) : (const float*)0;
        float* p = OF32 ? (C + ro) : (float*)0;
        #pragma unroll
        for (int j = 0; j < 16; j++) {
            float4 vv = *reinterpret_cast<const float4*>(srow + j * 4);
            vv.x *= scale; vv.y *= scale; vv.z *= scale; vv.w *= scale;
            if (RES) {
                float4 f = *reinterpret_cast<const float4*>(fp + j * 4);
                vv.x += f.x; vv.y += f.y; vv.z += f.z; vv.w += f.w;
            }
            if (OF32) *reinterpret_cast<float4*>(p + j * 4) = vv;
            if (OSPLIT) {
                uint2 hv, lv;
                split4(vv, hv, lv);
                *reinterpret_cast<uint2*>(Ch + ro + j * 4) = hv;
                *reinterpret_cast<uint2*>(Cl + ro + j * 4) = lv;
            }
        }
    }
}

// ---------------- GEMM wrapper kernels -----------------------------------------
template<bool GS, bool RES, bool OF32, bool OSPLIT>
__global__ __launch_bounds__(256, 2)
void gemm_k(const f16* Ah, const f16* Al, int lda, i64 aZ,
            const f16* Bh, int ldb, i64 bZ,
            float* C, int ldc, i64 cZ,
            f16* Ch, f16* Cl,
            const float* Fres, i64 fZ,
            const int* gidx, const int* sidx, i64 iZ,
            float scale, int KT)
{
    const int z = blockIdx.z;
    const int row0 = blockIdx.x * 128, col0 = blockIdx.y * 128;
    gemm_core<GS, RES, OF32, OSPLIT>(
        Ah + (i64)z * aZ, Al + (i64)z * aZ, lda,
        Bh + (i64)z * bZ, ldb,
        C + (i64)z * cZ, ldc,
        OSPLIT ? Ch + (i64)z * cZ : (f16*)0, OSPLIT ? Cl + (i64)z * cZ : (f16*)0,
        RES ? Fres + (i64)z * fZ : (const float*)0,
        GS ? gidx + (i64)z * iZ + row0 : (const int*)0,
        GS ? sidx + (i64)z * iZ + row0 : (const int*)0,
        row0, col0, scale, KT);
}

// ---------------- fused per-layer scatter launch (3712 CTAs) -------------------
__global__ __launch_bounds__(256, 2)
void layer_scatter(const f16* Xh, const f16* Xl,
                   const f16* wch, const f16* wph, const f16* wsh,
                   const f16* wlh, const f16* wrh,
                   float* T,
                   const int* iota,
                   const int* pre_u, const int* pre_v,
                   const int* suc_u, const int* suc_v,
                   const int* left_u, const int* left_v,
                   const int* right_u, const int* right_v)
{
    const int t = blockIdx.x;
    const int* gi; const int* si; const f16* Bh;
    if (t < 128) {
        gi = iota + t * 128; si = gi; Bh = wch;
    } else if (t < 1664) {
        int u = t - 128, z = u >> 8, e = (u & 255) * 128;
        gi = pre_v + z * NE + e; si = pre_u + z * NE + e;
        Bh = wph + (i64)z * DD;
    } else if (t < 3200) {
        int u = t - 1664, z = u >> 8, e = (u & 255) * 128;
        gi = suc_v + z * NE + e; si = suc_u + z * NE + e;
        Bh = wsh + (i64)z * DD;
    } else if (t < 3456) {
        int e = (t - 3200) * 128;
        gi = left_v + e; si = left_u + e; Bh = wlh;
    } else {
        int e = (t - 3456) * 128;
        gi = right_v + e; si = right_u + e; Bh = wrh;
    }
    gemm_core<true, false, false, false>(
        Xh, Xl, D, Bh, D, T, D, 0, 0, 0, gi, si, 0, 0, 1.f, 1);
}

// ---------------- small kernels -------------------------------------------------
__global__ void split_f32(const float4* __restrict__ in, uint2* __restrict__ oh,
                          uint2* __restrict__ ol, int n4)
{
    int i = blockIdx.x * 256 + threadIdx.x;
    if (i < n4) {
        uint2 h, l;
        split4(in[i], h, l);
        oh[i] = h;
        if (ol) ol[i] = l;
    }
}
__global__ void iota_k(int* p) {
    int i = blockIdx.x * 256 + threadIdx.x;
    if (i < M_ROWS) p[i] = i;
}
__global__ void zero_k(float4* p) {
    p[blockIdx.x * 256 + threadIdx.x] = make_float4(0.f, 0.f, 0.f, 0.f);
}

// V transpose: vt[b][d][j] = v[b][j][d], emit fp16 hi (B-side only needs hi)
__global__ __launch_bounds__(256)
void transpose_vt(const float* __restrict__ v, f16* __restrict__ vth)
{
    __shared__ float ts[32][33];
    const int b = blockIdx.z;
    const int j0 = blockIdx.x * 32, d0 = blockIdx.y * 32;
    const float* vb = v + (i64)b * NSEQ * D;
    const i64 ob = (i64)b * D * NSEQ;
    const int tx = threadIdx.x, ty = threadIdx.y;
    #pragma unroll
    for (int i = 0; i < 32; i += 8)
        ts[ty + i][tx] = vb[(i64)(j0 + ty + i) * D + d0 + tx];
    __syncthreads();
    #pragma unroll
    for (int i = 0; i < 32; i += 8) {
        i64 o = ob + (i64)(d0 + ty + i) * NSEQ + j0 + tx;
        vth[o] = __float2half(ts[tx][ty + i]);
    }
}

// row softmax over 1024, emit fp16 hi/lo splits (A-side of PV)
__global__ __launch_bounds__(256)
void softmax_k(const float* __restrict__ Sc, f16* __restrict__ oh, f16* __restrict__ ol)
{
    i64 row = blockIdx.x;
    const float4* p = reinterpret_cast<const float4*>(Sc + row * NSEQ);
    int t = threadIdx.x;
    float4 v = p[t];
    float mx = fmaxf(fmaxf(v.x, v.y), fmaxf(v.z, v.w));
    #pragma unroll
    for (int o = 16; o; o >>= 1) mx = fmaxf(mx, __shfl_xor_sync(0xffffffffu, mx, o));
    __shared__ float red8[8];
    int w = t >> 5;
    if ((t & 31) == 0) red8[w] = mx;
    __syncthreads();
    mx = red8[0];
    #pragma unroll
    for (int i = 1; i < 8; i++) mx = fmaxf(mx, red8[i]);
    v.x = expf(v.x - mx); v.y = expf(v.y - mx);
    v.z = expf(v.z - mx); v.w = expf(v.w - mx);
    float s = v.x + v.y + v.z + v.w;
    #pragma unroll
    for (int o = 16; o; o >>= 1) s += __shfl_xor_sync(0xffffffffu, s, o);
    __syncthreads();
    if ((t & 31) == 0) red8[w] = s;
    __syncthreads();
    s = red8[0] + red8[1] + red8[2] + red8[3] + red8[4] + red8[5] + red8[6] + red8[7];
    float inv = 1.0f / s;
    v.x *= inv; v.y *= inv; v.z *= inv; v.w *= inv;
    uint2 hv, lv;
    split4(v, hv, lv);
    *reinterpret_cast<uint2*>(oh + row * NSEQ + t * 4) = hv;
    *reinterpret_cast<uint2*>(ol + row * NSEQ + t * 4) = lv;
}

// group norm; OF32: write fp32 out; OSPLIT: write fp16 hi/lo; RES: add res + relu
template<bool RES, bool OF32, bool OSPLIT>
__global__ __launch_bounds__(128)
void gn_kernel(const float* __restrict__ in, float* __restrict__ out,
               f16* __restrict__ outh, f16* __restrict__ outl,
               const float* __restrict__ gw, const float* __restrict__ bw,
               const float* __restrict__ res)
{
    const i64 row = blockIdx.x;
    const int t = threadIdx.x;
    float v = in[row * D + t];
    float s1 = v, s2 = v * v;
    #pragma unroll
    for (int o = 16; o; o >>= 1) {
        s1 += __shfl_xor_sync(0xffffffffu, s1, o);
        s2 += __shfl_xor_sync(0xffffffffu, s2, o);
    }
    __shared__ float a1[4], a2[4];
    int w = t >> 5;
    if ((t & 31) == 0) { a1[w] = s1; a2[w] = s2; }
    __syncthreads();
    s1 = a1[0] + a1[1] + a1[2] + a1[3];
    s2 = a2[0] + a2[1] + a2[2] + a2[3];
    float mu = s1 * (1.0f / D);
    float var = s2 * (1.0f / D) - mu * mu;
    float y = (v - mu) * rsqrtf(var + 1e-5f) * gw[t] + bw[t];
    if (RES) y = fmaxf(y + res[row * D + t], 0.f);
    else     y = fmaxf(y, 0.f);
    if (OF32) out[row * D + t] = y;
    if (OSPLIT) {
        f16 h = __float2half(y);
        f16 l = __float2half(y - __half2float(h));
        outh[row * D + t] = h;
        outl[row * D + t] = l;
    }
}

// ---------------- driver ---------------------------------------------------------
#define SMEM_SZ 98304

extern "C" void kernel_launch(void* const* d_in, const int* in_sizes, int n_in,
                              void* d_out, int out_size)
{
    (void)in_sizes; (void)n_in; (void)out_size;
    const float* ctrs   = (const float*)d_in[0];
    const float* feats  = (const float*)d_in[1];
    const float* Wq     = (const float*)d_in[2];
    const float* Wk     = (const float*)d_in[3];
    const float* Wv     = (const float*)d_in[4];
    const float* Wc     = (const float*)d_in[5];
    const float* Wp     = (const float*)d_in[6];
    const float* Ws     = (const float*)d_in[7];
    const float* Wl     = (const float*)d_in[8];
    const float* Wr     = (const float*)d_in[9];
    const float* Wc2    = (const float*)d_in[10];
    const float* g1     = (const float*)d_in[11];
    const float* b1     = (const float*)d_in[12];
    const float* g2     = (const float*)d_in[13];
    const float* b2     = (const float*)d_in[14];
    const int* pre_u    = (const int*)d_in[15];
    const int* pre_v    = (const int*)d_in[16];
    const int* suc_u    = (const int*)d_in[17];
    const int* suc_v    = (const int*)d_in[18];
    const int* left_u   = (const int*)d_in[19];
    const int* left_v   = (const int*)d_in[20];
    const int* right_u  = (const int*)d_in[21];
    const int* right_v  = (const int*)d_in[22];
    float* X = (float*)d_out;

    float *v, *sc, *T, *Z; int* iota;
    cudaGetSymbolAddress((void**)&v,  g_v);
    cudaGetSymbolAddress((void**)&sc, g_sc);
    cudaGetSymbolAddress((void**)&T,  g_T);
    cudaGetSymbolAddress((void**)&Z,  g_Z);
    cudaGetSymbolAddress((void**)&iota, g_iota);
    f16 *ctrs_h, *ctrs_l, *feat_h, *feat_l, *q_h, *q_l, *k_h, *k_l, *vt_h;
    f16 *x_h, *x_l, *y_h, *y_l, *sc_h, *sc_l;
    f16 *wq_h, *wk_h, *wv_h;
    f16 *wc_h, *wp_h, *ws_h, *wl_h, *wr_h, *w2_h;
    cudaGetSymbolAddress((void**)&ctrs_h, s_ctrs_h); cudaGetSymbolAddress((void**)&ctrs_l, s_ctrs_l);
    cudaGetSymbolAddress((void**)&feat_h, s_feat_h); cudaGetSymbolAddress((void**)&feat_l, s_feat_l);
    cudaGetSymbolAddress((void**)&q_h, s_q_h);       cudaGetSymbolAddress((void**)&q_l, s_q_l);
    cudaGetSymbolAddress((void**)&k_h, s_k_h);       cudaGetSymbolAddress((void**)&k_l, s_k_l);
    cudaGetSymbolAddress((void**)&vt_h, s_vt_h);
    cudaGetSymbolAddress((void**)&x_h, s_x_h);       cudaGetSymbolAddress((void**)&x_l, s_x_l);
    cudaGetSymbolAddress((void**)&y_h, s_y_h);       cudaGetSymbolAddress((void**)&y_l, s_y_l);
    cudaGetSymbolAddress((void**)&sc_h, s_sc_h);     cudaGetSymbolAddress((void**)&sc_l, s_sc_l);
    cudaGetSymbolAddress((void**)&wq_h, s_wq_h);
    cudaGetSymbolAddress((void**)&wk_h, s_wk_h);
    cudaGetSymbolAddress((void**)&wv_h, s_wv_h);
    cudaGetSymbolAddress((void**)&wc_h, s_wc_h);
    cudaGetSymbolAddress((void**)&wp_h, s_wp_h);
    cudaGetSymbolAddress((void**)&ws_h, s_ws_h);
    cudaGetSymbolAddress((void**)&wl_h, s_wl_h);
    cudaGetSymbolAddress((void**)&wr_h, s_wr_h);
    cudaGetSymbolAddress((void**)&w2_h, s_w2_h);

    cudaFuncSetAttribute((const void*)gemm_k<false,false,false,true >, cudaFuncAttributeMaxDynamicSharedMemorySize, SMEM_SZ);
    cudaFuncSetAttribute((const void*)gemm_k<false,false,true ,false>, cudaFuncAttributeMaxDynamicSharedMemorySize, SMEM_SZ);
    cudaFuncSetAttribute((const void*)gemm_k<false,true ,true ,true >, cudaFuncAttributeMaxDynamicSharedMemorySize, SMEM_SZ);
    cudaFuncSetAttribute((const void*)layer_scatter, cudaFuncAttributeMaxDynamicSharedMemorySize, SMEM_SZ);

    const float NF = 0.08838834764831845f;  // 1/sqrt(128)
    dim3 blk(256);

    // ---- one-shot conversions (weights/B-side: hi only) ----
    auto spl = [&](const float* src, f16* dh, f16* dl, int n) {
        int n4 = n / 4;
        split_f32<<<(n4 + 255) / 256, 256>>>((const float4*)src, (uint2*)dh, (uint2*)dl, n4);
    };
    spl(ctrs,  ctrs_h, ctrs_l, M_ROWS * D);
    spl(feats, feat_h, feat_l, M_ROWS * D);
    spl(Wq, wq_h, 0, DD);
    spl(Wk, wk_h, 0, DD);
    spl(Wv, wv_h, 0, DD);
    spl(Wc, wc_h, 0, NL * DD);
    spl(Wp, wp_h, 0, NL * NS * DD);
    spl(Ws, ws_h, 0, NL * NS * DD);
    spl(Wl, wl_h, 0, NL * DD);
    spl(Wr, wr_h, 0, NL * DD);
    spl(Wc2, w2_h, 0, NL * DD);
    iota_k<<<M_ROWS / 256, 256>>>(iota);

    // ---- attention ----
    gemm_k<false,false,false,true><<<dim3(128,1,1), blk, SMEM_SZ>>>(
        ctrs_h, ctrs_l, D, 0, wq_h, D, 0, (float*)0, D, 0, q_h, q_l, 0, 0, 0, 0, 0, 1.f, 1);
    gemm_k<false,false,false,true><<<dim3(128,1,1), blk, SMEM_SZ>>>(
        feat_h, feat_l, D, 0, wk_h, D, 0, (float*)0, D, 0, k_h, k_l, 0, 0, 0, 0, 0, 1.f, 1);
    gemm_k<false,false,true,false><<<dim3(128,1,1), blk, SMEM_SZ>>>(
        feat_h, feat_l, D, 0, wv_h, D, 0, v, D, 0, 0, 0, 0, 0, 0, 0, 0, 1.f, 1);
    transpose_vt<<<dim3(NSEQ/32, D/32, BATCH), dim3(32,8)>>>(v, vt_h);
    gemm_k<false,false,true,false><<<dim3(8,8,16), blk, SMEM_SZ>>>(
        q_h, q_l, D, (i64)NSEQ*D, k_h, D, (i64)NSEQ*D,
        sc, NSEQ, (i64)NSEQ*NSEQ, 0, 0, 0, 0, 0, 0, 0, NF, 1);
    softmax_k<<<M_ROWS, 256>>>(sc, sc_h, sc_l);
    gemm_k<false,true,true,true><<<dim3(8,1,16), blk, SMEM_SZ>>>(
        sc_h, sc_l, NSEQ, (i64)NSEQ*NSEQ, vt_h, NSEQ, (i64)D*NSEQ,
        X, D, (i64)NSEQ*D, x_h, x_l, feats, (i64)NSEQ*D, 0, 0, 0, 1.f, 8);

    // ---- 4-layer fusion loop ----
    for (int i = 0; i < NL; i++) {
        zero_k<<<M_ROWS * D / 4 / 256, 256>>>((float4*)T);
        layer_scatter<<<3712, blk, SMEM_SZ>>>(
            x_h, x_l,
            wc_h + (i64)i*DD,
            wp_h + (i64)i*NS*DD,
            ws_h + (i64)i*NS*DD,
            wl_h + (i64)i*DD,
            wr_h + (i64)i*DD,
            T, iota, pre_u, pre_v, suc_u, suc_v, left_u, left_v, right_u, right_v);
        gn_kernel<false,false,true><<<M_ROWS, 128>>>(T, (float*)0, y_h, y_l,
                                                     g1 + i*D, b1 + i*D, (const float*)0);
        gemm_k<false,false,true,false><<<dim3(128,1,1), blk, SMEM_SZ>>>(
            y_h, y_l, D, 0, w2_h + (i64)i*DD, D, 0,
            Z, D, 0, 0, 0, 0, 0, 0, 0, 0, 1.f, 1);
        gn_kernel<true,true,true><<<M_ROWS, 128>>>(Z, X, x_h, x_l,
                                                   g2 + i*D, b2 + i*D, X);
    }
}

// round 7
// speedup vs baseline: 1.5757x; 1.1286x over previous
#include <cuda_runtime.h>
#include <cuda_fp16.h>
#include <math.h>
#include <stdint.h>

#define D 128
#define DD 16384
#define BATCH 16
#define NSEQ 1024
#define M_ROWS 16384
#define NE 32768
#define NS 6
#define NL 4

typedef unsigned long long u64;
typedef unsigned int u32;
typedef long long i64;
typedef __half f16;

// ---------------- scratch (fp32) ---------------------------------------------
__device__ __align__(256) float g_v [M_ROWS * D];
__device__ __align__(256) float g_sc[(size_t)BATCH * NSEQ * NSEQ];
__device__ __align__(256) float g_T [M_ROWS * D];
__device__ __align__(256) float g_Z [M_ROWS * D];
__device__ __align__(256) int   g_iota[M_ROWS];

// ---------------- scratch (fp16) -----------------------------------------------
__device__ __align__(256) f16 s_ctrs_h[M_ROWS*D];
__device__ __align__(256) f16 s_feat_h[M_ROWS*D];
__device__ __align__(256) f16 s_q_h[M_ROWS*D];
__device__ __align__(256) f16 s_k_h[M_ROWS*D];
__device__ __align__(256) f16 s_vt_h[M_ROWS*D];
__device__ __align__(256) f16 s_x_h[M_ROWS*D];
__device__ __align__(256) f16 s_y_h[M_ROWS*D];
__device__ __align__(256) f16 s_sc_h[(size_t)BATCH*NSEQ*NSEQ];
__device__ __align__(256) f16 s_wq_h[DD], s_wk_h[DD], s_wv_h[DD];
__device__ __align__(256) f16 s_wc_h[NL*DD];
__device__ __align__(256) f16 s_wp_h[NL*NS*DD];
__device__ __align__(256) f16 s_ws_h[NL*NS*DD];
__device__ __align__(256) f16 s_wl_h[NL*DD];
__device__ __align__(256) f16 s_wr_h[NL*DD];
__device__ __align__(256) f16 s_w2_h[NL*DD];

// ---------------- PTX helpers ------------------------------------------------
__device__ __forceinline__ u32 smem_u32(const void* p) {
    u32 a;
    asm("{ .reg .u64 t; cvta.to.shared.u64 t, %1; cvt.u32.u64 %0, t; }" : "=r"(a) : "l"(p));
    return a;
}
__device__ __forceinline__ void ldsm4(u32* r, u32 addr) {
    asm volatile("ldmatrix.sync.aligned.m8n8.x4.shared.b16 {%0,%1,%2,%3}, [%4];"
                 : "=r"(r[0]), "=r"(r[1]), "=r"(r[2]), "=r"(r[3]) : "r"(addr));
}
__device__ __forceinline__ void mma_f16(float* d, const u32* a, u32 b0, u32 b1) {
    asm volatile("mma.sync.aligned.m16n8k16.row.col.f32.f16.f16.f32 "
                 "{%0,%1,%2,%3}, {%4,%5,%6,%7}, {%8,%9}, {%0,%1,%2,%3};"
                 : "+f"(d[0]), "+f"(d[1]), "+f"(d[2]), "+f"(d[3])
                 : "r"(a[0]), "r"(a[1]), "r"(a[2]), "r"(a[3]), "r"(b0), "r"(b1));
}
__device__ __forceinline__ void red4(float* p, float a, float b, float c, float d) {
    asm volatile("red.global.add.v4.f32 [%0], {%1,%2,%3,%4};"
                 :: "l"(p), "f"(a), "f"(b), "f"(c), "f"(d) : "memory");
}
__device__ __forceinline__ void cp16_cg(u32 dst, const void* src) {
    asm volatile("cp.async.cg.shared.global [%0], [%1], 16;" :: "r"(dst), "l"(src));
}
__device__ __forceinline__ void cp16_ca(u32 dst, const void* src) {
    asm volatile("cp.async.ca.shared.global [%0], [%1], 16;" :: "r"(dst), "l"(src));
}
__device__ __forceinline__ void cp_commit() { asm volatile("cp.async.commit_group;" ::: "memory"); }
template<int N> __device__ __forceinline__ void cp_wait() {
    asm volatile("cp.async.wait_group %0;" :: "n"(N) : "memory");
}
// fp32 float4 -> packed half2 pair
__device__ __forceinline__ uint2 cvt4(float4 v) {
    __half2 h0 = __floats2half2_rn(v.x, v.y);
    __half2 h1 = __floats2half2_rn(v.z, v.w);
    return make_uint2(*(u32*)&h0, *(u32*)&h1);
}

// ---------------- GEMM core ----------------------------------------------------
// C[m,n] (+)= scale * sum_k A[m,k]*B[n,k]; fp16 operands, fp32 accumulate.
// K = KT*128, double-buffered 64-wide K-halves via cp.async.
// SMEM: 2 stages x 2 x 16KB = 64KB (+ epilogue staging 66KB reuse) -> 2 CTAs/SM.
template<bool GS, bool RES, bool OF32, bool OF16>
__device__ __forceinline__ void gemm_core(
    const f16* __restrict__ Ah, int lda,
    const f16* __restrict__ Bh, int ldb,
    float* __restrict__ C, int ldc,
    f16* __restrict__ Ch,
    const float* __restrict__ Fres,
    const int* __restrict__ gi, const int* __restrict__ si,
    int row0, int col0, float scale, int KT)
{
    extern __shared__ char sm[];
    const u32 sb = smem_u32(sm);
    const int tid = threadIdx.x;
    const int wid = tid >> 5, lane = tid & 31;
    const int m0w = (wid >> 1) * 32, n0w = (wid & 1) * 64;

    float acc[2][8][4];
    #pragma unroll
    for (int mi = 0; mi < 2; mi++)
        #pragma unroll
        for (int nj = 0; nj < 8; nj++)
            #pragma unroll
            for (int e = 0; e < 4; e++) acc[mi][nj][e] = 0.f;

    // per-lane ldmatrix components (pitch 128B, xor-by-(row&7) swizzle)
    const u32 a_rb = (u32)(m0w + (lane & 15)) * 128;
    const u32 b_rb = (u32)(n0w + ((lane >> 4) << 3) + (lane & 7)) * 128;
    const int a_hi = lane >> 4;
    const int b_hi = (lane >> 3) & 1;
    const int xr = lane & 7;

    // loader for half h into stage s (A, B = 8 chunks of 16B per thread)
    const int r_ld = tid >> 1;
    const int c0_ld = (tid & 1) * 4;
    i64 arow_ld = GS ? (i64)__ldg(gi + r_ld) : (i64)(row0 + r_ld);
    const int H = 2 * KT;

    auto load_half = [&](int h, int s) {
        const int kofs = h * 64;
        const u32 base = sb + (u32)s * 32768u;
        const f16* ap = Ah + arow_ld * (i64)lda + kofs;
        const f16* bp = Bh + (i64)(col0 + r_ld) * ldb + kofs;
        #pragma unroll
        for (int j = 0; j < 4; j++) {
            int c = c0_ld + j;
            u32 so = (u32)r_ld * 128 + (u32)((c ^ (r_ld & 7)) << 4);
            cp16_cg(base + so,          ap + c * 8);
            cp16_ca(base + 16384 + so,  bp + c * 8);
        }
        cp_commit();
    };

    load_half(0, 0);
    for (int h = 0; h < H; h++) {
        const int s = h & 1;
        const bool more = (h + 1 < H);
        if (more) { load_half(h + 1, 1 - s); cp_wait<1>(); }
        else      { cp_wait<0>(); }
        __syncthreads();
        const u32 base = sb + (u32)s * 32768u;
        const u32 abase = base + a_rb;
        const u32 bbase = base + 16384u + b_rb;
        #pragma unroll
        for (int ks = 0; ks < 4; ks++) {
            const u32 aoff = (u32)(((ks * 2 + a_hi) ^ xr) << 4);
            const u32 boff = (u32)(((ks * 2 + b_hi) ^ xr) << 4);
            u32 b[4][4], a0[4], a1[4];
            #pragma unroll
            for (int p = 0; p < 4; p++)
                ldsm4(b[p], bbase + boff + p * 2048);
            ldsm4(a0, abase + aoff);
            ldsm4(a1, abase + aoff + 2048);
            #pragma unroll
            for (int nj = 0; nj < 8; nj++) {
                u32 bb0 = b[nj >> 1][(nj & 1) * 2], bb1 = b[nj >> 1][(nj & 1) * 2 + 1];
                mma_f16(acc[0][nj], a0, bb0, bb1);
                mma_f16(acc[1][nj], a1, bb0, bb1);
            }
        }
        __syncthreads();
    }

    // ---- stage C to SMEM (pitch 132 floats), then output ----
    float* Cs = reinterpret_cast<float*>(sm);
    const int g = lane >> 2, q2 = (lane & 3) * 2;
    #pragma unroll
    for (int mi = 0; mi < 2; mi++)
        #pragma unroll
        for (int nj = 0; nj < 8; nj++) {
            int r = m0w + mi * 16 + g;
            int c = n0w + nj * 8 + q2;
            Cs[r * 132 + c]           = acc[mi][nj][0];
            Cs[r * 132 + c + 1]       = acc[mi][nj][1];
            Cs[(r + 8) * 132 + c]     = acc[mi][nj][2];
            Cs[(r + 8) * 132 + c + 1] = acc[mi][nj][3];
        }
    __syncthreads();

    const int rr = tid >> 1, hh = tid & 1;
    const float* srow = Cs + rr * 132 + hh * 64;
    if (GS) {
        i64 drow = (i64)__ldg(si + rr);
        float* p = C + drow * (i64)ldc + col0 + hh * 64;
        #pragma unroll
        for (int j = 0; j < 16; j++) {
            float4 vv = *reinterpret_cast<const float4*>(srow + j * 4);
            red4(p + j * 4, vv.x, vv.y, vv.z, vv.w);
        }
    } else {
        const i64 ro = (i64)(row0 + rr) * ldc + col0 + hh * 64;
        const float* fp = RES ? (Fres + ro) : (const float*)0;
        float* p = OF32 ? (C + ro) : (float*)0;
        #pragma unroll
        for (int j = 0; j < 16; j++) {
            float4 vv = *reinterpret_cast<const float4*>(srow + j * 4);
            vv.x *= scale; vv.y *= scale; vv.z *= scale; vv.w *= scale;
            if (RES) {
                float4 f = *reinterpret_cast<const float4*>(fp + j * 4);
                vv.x += f.x; vv.y += f.y; vv.z += f.z; vv.w += f.w;
            }
            if (OF32) *reinterpret_cast<float4*>(p + j * 4) = vv;
            if (OF16) *reinterpret_cast<uint2*>(Ch + ro + j * 4) = cvt4(vv);
        }
    }
}

// ---------------- GEMM wrapper kernels -----------------------------------------
template<bool GS, bool RES, bool OF32, bool OF16>
__global__ __launch_bounds__(256, 2)
void gemm_k(const f16* Ah, int lda, i64 aZ,
            const f16* Bh, int ldb, i64 bZ,
            float* C, int ldc, i64 cZ,
            f16* Ch,
            const float* Fres, i64 fZ,
            const int* gidx, const int* sidx, i64 iZ,
            float scale, int KT)
{
    const int z = blockIdx.z;
    const int row0 = blockIdx.x * 128, col0 = blockIdx.y * 128;
    gemm_core<GS, RES, OF32, OF16>(
        Ah + (i64)z * aZ, lda,
        Bh + (i64)z * bZ, ldb,
        C + (i64)z * cZ, ldc,
        OF16 ? Ch + (i64)z * cZ : (f16*)0,
        RES ? Fres + (i64)z * fZ : (const float*)0,
        GS ? gidx + (i64)z * iZ + row0 : (const int*)0,
        GS ? sidx + (i64)z * iZ + row0 : (const int*)0,
        row0, col0, scale, KT);
}

// ---------------- fused per-layer scatter launch (3712 CTAs) -------------------
__global__ __launch_bounds__(256, 2)
void layer_scatter(const f16* Xh,
                   const f16* wch, const f16* wph, const f16* wsh,
                   const f16* wlh, const f16* wrh,
                   float* T,
                   const int* iota,
                   const int* pre_u, const int* pre_v,
                   const int* suc_u, const int* suc_v,
                   const int* left_u, const int* left_v,
                   const int* right_u, const int* right_v)
{
    const int t = blockIdx.x;
    const int* gi; const int* si; const f16* Bh;
    if (t < 128) {
        gi = iota + t * 128; si = gi; Bh = wch;
    } else if (t < 1664) {
        int u = t - 128, z = u >> 8, e = (u & 255) * 128;
        gi = pre_v + z * NE + e; si = pre_u + z * NE + e;
        Bh = wph + (i64)z * DD;
    } else if (t < 3200) {
        int u = t - 1664, z = u >> 8, e = (u & 255) * 128;
        gi = suc_v + z * NE + e; si = suc_u + z * NE + e;
        Bh = wsh + (i64)z * DD;
    } else if (t < 3456) {
        int e = (t - 3200) * 128;
        gi = left_v + e; si = left_u + e; Bh = wlh;
    } else {
        int e = (t - 3456) * 128;
        gi = right_v + e; si = right_u + e; Bh = wrh;
    }
    gemm_core<true, false, false, false>(
        Xh, D, Bh, D, T, D, 0, 0, gi, si, 0, 0, 1.f, 1);
}

// ---------------- small kernels -------------------------------------------------
__global__ void cvt_f32(const float4* __restrict__ in, uint2* __restrict__ oh, int n4)
{
    int i = blockIdx.x * 256 + threadIdx.x;
    if (i < n4) oh[i] = cvt4(in[i]);
}
__global__ void iota_k(int* p) {
    int i = blockIdx.x * 256 + threadIdx.x;
    if (i < M_ROWS) p[i] = i;
}
__global__ void zero_k(float4* p) {
    p[blockIdx.x * 256 + threadIdx.x] = make_float4(0.f, 0.f, 0.f, 0.f);
}

// V transpose: vt[b][d][j] = v[b][j][d], emit fp16
__global__ __launch_bounds__(256)
void transpose_vt(const float* __restrict__ v, f16* __restrict__ vth)
{
    __shared__ float ts[32][33];
    const int b = blockIdx.z;
    const int j0 = blockIdx.x * 32, d0 = blockIdx.y * 32;
    const float* vb = v + (i64)b * NSEQ * D;
    const i64 ob = (i64)b * D * NSEQ;
    const int tx = threadIdx.x, ty = threadIdx.y;
    #pragma unroll
    for (int i = 0; i < 32; i += 8)
        ts[ty + i][tx] = vb[(i64)(j0 + ty + i) * D + d0 + tx];
    __syncthreads();
    #pragma unroll
    for (int i = 0; i < 32; i += 8) {
        i64 o = ob + (i64)(d0 + ty + i) * NSEQ + j0 + tx;
        vth[o] = __float2half(ts[tx][ty + i]);
    }
}

// row softmax over 1024, emit fp16
__global__ __launch_bounds__(256)
void softmax_k(const float* __restrict__ Sc, f16* __restrict__ oh)
{
    i64 row = blockIdx.x;
    const float4* p = reinterpret_cast<const float4*>(Sc + row * NSEQ);
    int t = threadIdx.x;
    float4 v = p[t];
    float mx = fmaxf(fmaxf(v.x, v.y), fmaxf(v.z, v.w));
    #pragma unroll
    for (int o = 16; o; o >>= 1) mx = fmaxf(mx, __shfl_xor_sync(0xffffffffu, mx, o));
    __shared__ float red8[8];
    int w = t >> 5;
    if ((t & 31) == 0) red8[w] = mx;
    __syncthreads();
    mx = red8[0];
    #pragma unroll
    for (int i = 1; i < 8; i++) mx = fmaxf(mx, red8[i]);
    v.x = expf(v.x - mx); v.y = expf(v.y - mx);
    v.z = expf(v.z - mx); v.w = expf(v.w - mx);
    float s = v.x + v.y + v.z + v.w;
    #pragma unroll
    for (int o = 16; o; o >>= 1) s += __shfl_xor_sync(0xffffffffu, s, o);
    __syncthreads();
    if ((t & 31) == 0) red8[w] = s;
    __syncthreads();
    s = red8[0] + red8[1] + red8[2] + red8[3] + red8[4] + red8[5] + red8[6] + red8[7];
    float inv = 1.0f / s;
    v.x *= inv; v.y *= inv; v.z *= inv; v.w *= inv;
    *reinterpret_cast<uint2*>(oh + row * NSEQ + t * 4) = cvt4(v);
}

// group norm; OF32: write fp32 out; OF16: write fp16; RES: add res + relu
template<bool RES, bool OF32, bool OF16>
__global__ __launch_bounds__(128)
void gn_kernel(const float* __restrict__ in, float* __restrict__ out,
               f16* __restrict__ outh,
               const float* __restrict__ gw, const float* __restrict__ bw,
               const float* __restrict__ res)
{
    const i64 row = blockIdx.x;
    const int t = threadIdx.x;
    float v = in[row * D + t];
    float s1 = v, s2 = v * v;
    #pragma unroll
    for (int o = 16; o; o >>= 1) {
        s1 += __shfl_xor_sync(0xffffffffu, s1, o);
        s2 += __shfl_xor_sync(0xffffffffu, s2, o);
    }
    __shared__ float a1[4], a2[4];
    int w = t >> 5;
    if ((t & 31) == 0) { a1[w] = s1; a2[w] = s2; }
    __syncthreads();
    s1 = a1[0] + a1[1] + a1[2] + a1[3];
    s2 = a2[0] + a2[1] + a2[2] + a2[3];
    float mu = s1 * (1.0f / D);
    float var = s2 * (1.0f / D) - mu * mu;
    float y = (v - mu) * rsqrtf(var + 1e-5f) * gw[t] + bw[t];
    if (RES) y = fmaxf(y + res[row * D + t], 0.f);
    else     y = fmaxf(y, 0.f);
    if (OF32) out[row * D + t] = y;
    if (OF16) outh[row * D + t] = __float2half(y);
}

// ---------------- driver ---------------------------------------------------------
#define SMEM_SZ 67584   // max(2*32KB operand stages, 128x132 f32 epilogue staging)

extern "C" void kernel_launch(void* const* d_in, const int* in_sizes, int n_in,
                              void* d_out, int out_size)
{
    (void)in_sizes; (void)n_in; (void)out_size;
    const float* ctrs   = (const float*)d_in[0];
    const float* feats  = (const float*)d_in[1];
    const float* Wq     = (const float*)d_in[2];
    const float* Wk     = (const float*)d_in[3];
    const float* Wv     = (const float*)d_in[4];
    const float* Wc     = (const float*)d_in[5];
    const float* Wp     = (const float*)d_in[6];
    const float* Ws     = (const float*)d_in[7];
    const float* Wl     = (const float*)d_in[8];
    const float* Wr     = (const float*)d_in[9];
    const float* Wc2    = (const float*)d_in[10];
    const float* g1     = (const float*)d_in[11];
    const float* b1     = (const float*)d_in[12];
    const float* g2     = (const float*)d_in[13];
    const float* b2     = (const float*)d_in[14];
    const int* pre_u    = (const int*)d_in[15];
    const int* pre_v    = (const int*)d_in[16];
    const int* suc_u    = (const int*)d_in[17];
    const int* suc_v    = (const int*)d_in[18];
    const int* left_u   = (const int*)d_in[19];
    const int* left_v   = (const int*)d_in[20];
    const int* right_u  = (const int*)d_in[21];
    const int* right_v  = (const int*)d_in[22];
    float* X = (float*)d_out;

    float *v, *sc, *T, *Z; int* iota;
    cudaGetSymbolAddress((void**)&v,  g_v);
    cudaGetSymbolAddress((void**)&sc, g_sc);
    cudaGetSymbolAddress((void**)&T,  g_T);
    cudaGetSymbolAddress((void**)&Z,  g_Z);
    cudaGetSymbolAddress((void**)&iota, g_iota);
    f16 *ctrs_h, *feat_h, *q_h, *k_h, *vt_h, *x_h, *y_h, *sc_h;
    f16 *wq_h, *wk_h, *wv_h, *wc_h, *wp_h, *ws_h, *wl_h, *wr_h, *w2_h;
    cudaGetSymbolAddress((void**)&ctrs_h, s_ctrs_h);
    cudaGetSymbolAddress((void**)&feat_h, s_feat_h);
    cudaGetSymbolAddress((void**)&q_h, s_q_h);
    cudaGetSymbolAddress((void**)&k_h, s_k_h);
    cudaGetSymbolAddress((void**)&vt_h, s_vt_h);
    cudaGetSymbolAddress((void**)&x_h, s_x_h);
    cudaGetSymbolAddress((void**)&y_h, s_y_h);
    cudaGetSymbolAddress((void**)&sc_h, s_sc_h);
    cudaGetSymbolAddress((void**)&wq_h, s_wq_h);
    cudaGetSymbolAddress((void**)&wk_h, s_wk_h);
    cudaGetSymbolAddress((void**)&wv_h, s_wv_h);
    cudaGetSymbolAddress((void**)&wc_h, s_wc_h);
    cudaGetSymbolAddress((void**)&wp_h, s_wp_h);
    cudaGetSymbolAddress((void**)&ws_h, s_ws_h);
    cudaGetSymbolAddress((void**)&wl_h, s_wl_h);
    cudaGetSymbolAddress((void**)&wr_h, s_wr_h);
    cudaGetSymbolAddress((void**)&w2_h, s_w2_h);

    cudaFuncSetAttribute((const void*)gemm_k<false,false,false,true >, cudaFuncAttributeMaxDynamicSharedMemorySize, SMEM_SZ);
    cudaFuncSetAttribute((const void*)gemm_k<false,false,true ,false>, cudaFuncAttributeMaxDynamicSharedMemorySize, SMEM_SZ);
    cudaFuncSetAttribute((const void*)gemm_k<false,true ,true ,true >, cudaFuncAttributeMaxDynamicSharedMemorySize, SMEM_SZ);
    cudaFuncSetAttribute((const void*)layer_scatter, cudaFuncAttributeMaxDynamicSharedMemorySize, SMEM_SZ);

    const float NF = 0.08838834764831845f;  // 1/sqrt(128)
    dim3 blk(256);

    // ---- one-shot conversions ----
    auto cvt = [&](const float* src, f16* dh, int n) {
        int n4 = n / 4;
        cvt_f32<<<(n4 + 255) / 256, 256>>>((const float4*)src, (uint2*)dh, n4);
    };
    cvt(ctrs,  ctrs_h, M_ROWS * D);
    cvt(feats, feat_h, M_ROWS * D);
    cvt(Wq, wq_h, DD);
    cvt(Wk, wk_h, DD);
    cvt(Wv, wv_h, DD);
    cvt(Wc, wc_h, NL * DD);
    cvt(Wp, wp_h, NL * NS * DD);
    cvt(Ws, ws_h, NL * NS * DD);
    cvt(Wl, wl_h, NL * DD);
    cvt(Wr, wr_h, NL * DD);
    cvt(Wc2, w2_h, NL * DD);
    iota_k<<<M_ROWS / 256, 256>>>(iota);

    // ---- attention ----
    gemm_k<false,false,false,true><<<dim3(128,1,1), blk, SMEM_SZ>>>(
        ctrs_h, D, 0, wq_h, D, 0, (float*)0, D, 0, q_h, 0, 0, 0, 0, 0, 1.f, 1);
    gemm_k<false,false,false,true><<<dim3(128,1,1), blk, SMEM_SZ>>>(
        feat_h, D, 0, wk_h, D, 0, (float*)0, D, 0, k_h, 0, 0, 0, 0, 0, 1.f, 1);
    gemm_k<false,false,true,false><<<dim3(128,1,1), blk, SMEM_SZ>>>(
        feat_h, D, 0, wv_h, D, 0, v, D, 0, 0, 0, 0, 0, 0, 0, 1.f, 1);
    transpose_vt<<<dim3(NSEQ/32, D/32, BATCH), dim3(32,8)>>>(v, vt_h);
    gemm_k<false,false,true,false><<<dim3(8,8,16), blk, SMEM_SZ>>>(
        q_h, D, (i64)NSEQ*D, k_h, D, (i64)NSEQ*D,
        sc, NSEQ, (i64)NSEQ*NSEQ, 0, 0, 0, 0, 0, 0, NF, 1);
    softmax_k<<<M_ROWS, 256>>>(sc, sc_h);
    gemm_k<false,true,true,true><<<dim3(8,1,16), blk, SMEM_SZ>>>(
        sc_h, NSEQ, (i64)NSEQ*NSEQ, vt_h, NSEQ, (i64)D*NSEQ,
        X, D, (i64)NSEQ*D, x_h, feats, (i64)NSEQ*D, 0, 0, 0, 1.f, 8);

    // ---- 4-layer fusion loop ----
    for (int i = 0; i < NL; i++) {
        zero_k<<<M_ROWS * D / 4 / 256, 256>>>((float4*)T);
        layer_scatter<<<3712, blk, SMEM_SZ>>>(
            x_h,
            wc_h + (i64)i*DD,
            wp_h + (i64)i*NS*DD,
            ws_h + (i64)i*NS*DD,
            wl_h + (i64)i*DD,
            wr_h + (i64)i*DD,
            T, iota, pre_u, pre_v, suc_u, suc_v, left_u, left_v, right_u, right_v);
        gn_kernel<false,false,true><<<M_ROWS, 128>>>(T, (float*)0, y_h,
                                                     g1 + i*D, b1 + i*D, (const float*)0);
        gemm_k<false,false,true,false><<<dim3(128,1,1), blk, SMEM_SZ>>>(
            y_h, D, 0, w2_h + (i64)i*DD, D, 0,
            Z, D, 0, 0, 0, 0, 0, 0, 0, 1.f, 1);
        gn_kernel<true,true,true><<<M_ROWS, 128>>>(Z, X, x_h,
                                                   g2 + i*D, b2 + i*D, X);
    }
}

// round 8
// speedup vs baseline: 1.6290x; 1.0338x over previous
#include <cuda_runtime.h>
#include <cuda_fp16.h>
#include <math.h>
#include <stdint.h>

#define D 128
#define DD 16384
#define BATCH 16
#define NSEQ 1024
#define M_ROWS 16384
#define NE 32768
#define NS 6
#define NL 4

typedef unsigned long long u64;
typedef unsigned int u32;
typedef long long i64;
typedef __half f16;

// ---------------- scratch (fp32) ---------------------------------------------
__device__ __align__(256) float g_v [M_ROWS * D];
__device__ __align__(256) float g_sc[(size_t)BATCH * NSEQ * NSEQ];
__device__ __align__(256) float g_T [M_ROWS * D];

// ---------------- scratch (fp16) -----------------------------------------------
__device__ __align__(256) f16 s_ctrs_h[M_ROWS*D];
__device__ __align__(256) f16 s_feat_h[M_ROWS*D];
__device__ __align__(256) f16 s_q_h[M_ROWS*D];
__device__ __align__(256) f16 s_k_h[M_ROWS*D];
__device__ __align__(256) f16 s_vt_h[M_ROWS*D];
__device__ __align__(256) f16 s_x_h[M_ROWS*D];
__device__ __align__(256) f16 s_y_h[M_ROWS*D];
__device__ __align__(256) f16 s_sc_h[(size_t)BATCH*NSEQ*NSEQ];
__device__ __align__(256) f16 s_wq_h[DD], s_wk_h[DD], s_wv_h[DD];
__device__ __align__(256) f16 s_wc_h[NL*DD];
__device__ __align__(256) f16 s_wp_h[NL*NS*DD];
__device__ __align__(256) f16 s_ws_h[NL*NS*DD];
__device__ __align__(256) f16 s_wl_h[NL*DD];
__device__ __align__(256) f16 s_wr_h[NL*DD];
__device__ __align__(256) f16 s_w2_h[NL*DD];

// ---------------- PTX helpers ------------------------------------------------
__device__ __forceinline__ u32 smem_u32(const void* p) {
    u32 a;
    asm("{ .reg .u64 t; cvta.to.shared.u64 t, %1; cvt.u32.u64 %0, t; }" : "=r"(a) : "l"(p));
    return a;
}
__device__ __forceinline__ void ldsm4(u32* r, u32 addr) {
    asm volatile("ldmatrix.sync.aligned.m8n8.x4.shared.b16 {%0,%1,%2,%3}, [%4];"
                 : "=r"(r[0]), "=r"(r[1]), "=r"(r[2]), "=r"(r[3]) : "r"(addr));
}
__device__ __forceinline__ void mma_f16(float* d, const u32* a, u32 b0, u32 b1) {
    asm volatile("mma.sync.aligned.m16n8k16.row.col.f32.f16.f16.f32 "
                 "{%0,%1,%2,%3}, {%4,%5,%6,%7}, {%8,%9}, {%0,%1,%2,%3};"
                 : "+f"(d[0]), "+f"(d[1]), "+f"(d[2]), "+f"(d[3])
                 : "r"(a[0]), "r"(a[1]), "r"(a[2]), "r"(a[3]), "r"(b0), "r"(b1));
}
__device__ __forceinline__ void red4(float* p, float a, float b, float c, float d) {
    asm volatile("red.global.add.v4.f32 [%0], {%1,%2,%3,%4};"
                 :: "l"(p), "f"(a), "f"(b), "f"(c), "f"(d) : "memory");
}
__device__ __forceinline__ void cp16_cg(u32 dst, const void* src) {
    asm volatile("cp.async.cg.shared.global [%0], [%1], 16;" :: "r"(dst), "l"(src));
}
__device__ __forceinline__ void cp16_ca(u32 dst, const void* src) {
    asm volatile("cp.async.ca.shared.global [%0], [%1], 16;" :: "r"(dst), "l"(src));
}
__device__ __forceinline__ void cp_commit() { asm volatile("cp.async.commit_group;" ::: "memory"); }
template<int N> __device__ __forceinline__ void cp_wait() {
    asm volatile("cp.async.wait_group %0;" :: "n"(N) : "memory");
}
__device__ __forceinline__ uint2 cvt4(float4 v) {
    __half2 h0 = __floats2half2_rn(v.x, v.y);
    __half2 h1 = __floats2half2_rn(v.z, v.w);
    return make_uint2(*(u32*)&h0, *(u32*)&h1);
}

// ---------------- GEMM core ----------------------------------------------------
// C[m,n] (+)= scale * sum_k A[m,k]*B[n,k]; fp16 operands, fp32 accumulate.
// K = KT*128, double-buffered 64-wide K-halves via cp.async.
// GS: gather A rows / scatter-add out.  GN2: fused GroupNorm+res+relu epilogue.
template<bool GS, bool RES, bool OF32, bool OF16, bool GN2>
__device__ __forceinline__ void gemm_core(
    const f16* __restrict__ Ah, int lda,
    const f16* __restrict__ Bh, int ldb,
    float* __restrict__ C, int ldc,
    f16* __restrict__ Ch,
    const float* __restrict__ Fres,
    const int* __restrict__ gi, const int* __restrict__ si,
    const float* __restrict__ gw, const float* __restrict__ bw,
    int row0, int col0, float scale, int KT)
{
    extern __shared__ char sm[];
    const u32 sb = smem_u32(sm);
    const int tid = threadIdx.x;
    const int wid = tid >> 5, lane = tid & 31;
    const int m0w = (wid >> 1) * 32, n0w = (wid & 1) * 64;

    float acc[2][8][4];
    #pragma unroll
    for (int mi = 0; mi < 2; mi++)
        #pragma unroll
        for (int nj = 0; nj < 8; nj++)
            #pragma unroll
            for (int e = 0; e < 4; e++) acc[mi][nj][e] = 0.f;

    const u32 a_rb = (u32)(m0w + (lane & 15)) * 128;
    const u32 b_rb = (u32)(n0w + ((lane >> 4) << 3) + (lane & 7)) * 128;
    const int a_hi = lane >> 4;
    const int b_hi = (lane >> 3) & 1;
    const int xr = lane & 7;

    const int r_ld = tid >> 1;
    const int c0_ld = (tid & 1) * 4;
    i64 arow_ld = GS ? (i64)__ldg(gi + r_ld) : (i64)(row0 + r_ld);
    const int H = 2 * KT;

    auto load_half = [&](int h, int s) {
        const int kofs = h * 64;
        const u32 base = sb + (u32)s * 32768u;
        const f16* ap = Ah + arow_ld * (i64)lda + kofs;
        const f16* bp = Bh + (i64)(col0 + r_ld) * ldb + kofs;
        #pragma unroll
        for (int j = 0; j < 4; j++) {
            int c = c0_ld + j;
            u32 so = (u32)r_ld * 128 + (u32)((c ^ (r_ld & 7)) << 4);
            cp16_cg(base + so,          ap + c * 8);
            cp16_ca(base + 16384 + so,  bp + c * 8);
        }
        cp_commit();
    };

    load_half(0, 0);
    for (int h = 0; h < H; h++) {
        const int s = h & 1;
        const bool more = (h + 1 < H);
        if (more) { load_half(h + 1, 1 - s); cp_wait<1>(); }
        else      { cp_wait<0>(); }
        __syncthreads();
        const u32 base = sb + (u32)s * 32768u;
        const u32 abase = base + a_rb;
        const u32 bbase = base + 16384u + b_rb;
        #pragma unroll
        for (int ks = 0; ks < 4; ks++) {
            const u32 aoff = (u32)(((ks * 2 + a_hi) ^ xr) << 4);
            const u32 boff = (u32)(((ks * 2 + b_hi) ^ xr) << 4);
            u32 b[4][4], a0[4], a1[4];
            #pragma unroll
            for (int p = 0; p < 4; p++)
                ldsm4(b[p], bbase + boff + p * 2048);
            ldsm4(a0, abase + aoff);
            ldsm4(a1, abase + aoff + 2048);
            #pragma unroll
            for (int nj = 0; nj < 8; nj++) {
                u32 bb0 = b[nj >> 1][(nj & 1) * 2], bb1 = b[nj >> 1][(nj & 1) * 2 + 1];
                mma_f16(acc[0][nj], a0, bb0, bb1);
                mma_f16(acc[1][nj], a1, bb0, bb1);
            }
        }
        __syncthreads();
    }

    // ---- stage C to SMEM (pitch 132 floats), then output ----
    float* Cs = reinterpret_cast<float*>(sm);
    const int g = lane >> 2, q2 = (lane & 3) * 2;
    #pragma unroll
    for (int mi = 0; mi < 2; mi++)
        #pragma unroll
        for (int nj = 0; nj < 8; nj++) {
            int r = m0w + mi * 16 + g;
            int c = n0w + nj * 8 + q2;
            Cs[r * 132 + c]           = acc[mi][nj][0];
            Cs[r * 132 + c + 1]       = acc[mi][nj][1];
            Cs[(r + 8) * 132 + c]     = acc[mi][nj][2];
            Cs[(r + 8) * 132 + c + 1] = acc[mi][nj][3];
        }
    __syncthreads();

    const int rr = tid >> 1, hh = tid & 1;
    const float* srow = Cs + rr * 132 + hh * 64;
    if (GS) {
        i64 drow = (i64)__ldg(si + rr);
        float* p = C + drow * (i64)ldc + col0 + hh * 64;
        #pragma unroll
        for (int j = 0; j < 16; j++) {
            float4 vv = *reinterpret_cast<const float4*>(srow + j * 4);
            red4(p + j * 4, vv.x, vv.y, vv.z, vv.w);
        }
    } else if (GN2) {
        // fused GroupNorm(1,D) + residual + relu over complete rows (col0==0, ldc==D)
        float s1 = 0.f, s2 = 0.f;
        #pragma unroll
        for (int j = 0; j < 16; j++) {
            float4 vv = *reinterpret_cast<const float4*>(srow + j * 4);
            s1 += vv.x + vv.y + vv.z + vv.w;
            s2 += vv.x * vv.x + vv.y * vv.y + vv.z * vv.z + vv.w * vv.w;
        }
        s1 += __shfl_xor_sync(0xffffffffu, s1, 1);
        s2 += __shfl_xor_sync(0xffffffffu, s2, 1);
        const float mu = s1 * (1.f / 128.f);
        const float var = s2 * (1.f / 128.f) - mu * mu;
        const float rstd = rsqrtf(var + 1e-5f);
        const i64 ro = (i64)(row0 + rr) * D + hh * 64;
        const float* fp = Fres + ro;
        float* p = C + ro;
        const float* gp = gw + hh * 64;
        const float* bp = bw + hh * 64;
        #pragma unroll
        for (int j = 0; j < 16; j++) {
            float4 vv = *reinterpret_cast<const float4*>(srow + j * 4);
            float4 g4 = *reinterpret_cast<const float4*>(gp + j * 4);
            float4 b4 = *reinterpret_cast<const float4*>(bp + j * 4);
            float4 f4 = *reinterpret_cast<const float4*>(fp + j * 4);
            vv.x = fmaxf((vv.x - mu) * rstd * g4.x + b4.x + f4.x, 0.f);
            vv.y = fmaxf((vv.y - mu) * rstd * g4.y + b4.y + f4.y, 0.f);
            vv.z = fmaxf((vv.z - mu) * rstd * g4.z + b4.z + f4.z, 0.f);
            vv.w = fmaxf((vv.w - mu) * rstd * g4.w + b4.w + f4.w, 0.f);
            *reinterpret_cast<float4*>(p + j * 4) = vv;
            *reinterpret_cast<uint2*>(Ch + ro + j * 4) = cvt4(vv);
        }
    } else {
        const i64 ro = (i64)(row0 + rr) * ldc + col0 + hh * 64;
        const float* fp = RES ? (Fres + ro) : (const float*)0;
        float* p = OF32 ? (C + ro) : (float*)0;
        #pragma unroll
        for (int j = 0; j < 16; j++) {
            float4 vv = *reinterpret_cast<const float4*>(srow + j * 4);
            vv.x *= scale; vv.y *= scale; vv.z *= scale; vv.w *= scale;
            if (RES) {
                float4 f = *reinterpret_cast<const float4*>(fp + j * 4);
                vv.x += f.x; vv.y += f.y; vv.z += f.z; vv.w += f.w;
            }
            if (OF32) *reinterpret_cast<float4*>(p + j * 4) = vv;
            if (OF16) *reinterpret_cast<uint2*>(Ch + ro + j * 4) = cvt4(vv);
        }
    }
}

// ---------------- GEMM wrapper kernels -----------------------------------------
template<bool GS, bool RES, bool OF32, bool OF16, bool GN2>
__global__ __launch_bounds__(256, 2)
void gemm_k(const f16* Ah, int lda, i64 aZ,
            const f16* Bh, int ldb, i64 bZ,
            float* C, int ldc, i64 cZ,
            f16* Ch,
            const float* Fres, i64 fZ,
            const int* gidx, const int* sidx, i64 iZ,
            const float* gw, const float* bw,
            float scale, int KT)
{
    const int z = blockIdx.z;
    const int row0 = blockIdx.x * 128, col0 = blockIdx.y * 128;
    gemm_core<GS, RES, OF32, OF16, GN2>(
        Ah + (i64)z * aZ, lda,
        Bh + (i64)z * bZ, ldb,
        C + (i64)z * cZ, ldc,
        (OF16 || GN2) ? Ch + (i64)z * cZ : (f16*)0,
        (RES || GN2) ? Fres + (i64)z * fZ : (const float*)0,
        GS ? gidx + (i64)z * iZ + row0 : (const int*)0,
        GS ? sidx + (i64)z * iZ + row0 : (const int*)0,
        gw, bw, row0, col0, scale, KT);
}

// ---------------- fused per-layer scatter launch (3584 CTAs) -------------------
__global__ __launch_bounds__(256, 2)
void layer_scatter(const f16* Xh,
                   const f16* wph, const f16* wsh,
                   const f16* wlh, const f16* wrh,
                   float* T,
                   const int* pre_u, const int* pre_v,
                   const int* suc_u, const int* suc_v,
                   const int* left_u, const int* left_v,
                   const int* right_u, const int* right_v)
{
    const int t = blockIdx.x;
    const int* gi; const int* si; const f16* Bh;
    if (t < 1536) {
        int z = t >> 8, e = (t & 255) * 128;
        gi = pre_v + z * NE + e; si = pre_u + z * NE + e;
        Bh = wph + (i64)z * DD;
    } else if (t < 3072) {
        int u = t - 1536, z = u >> 8, e = (u & 255) * 128;
        gi = suc_v + z * NE + e; si = suc_u + z * NE + e;
        Bh = wsh + (i64)z * DD;
    } else if (t < 3328) {
        int e = (t - 3072) * 128;
        gi = left_v + e; si = left_u + e; Bh = wlh;
    } else {
        int e = (t - 3328) * 128;
        gi = right_v + e; si = right_u + e; Bh = wrh;
    }
    gemm_core<true, false, false, false, false>(
        Xh, D, Bh, D, T, D, 0, 0, gi, si, 0, 0, 0, 0, 1.f, 1);
}

// ---------------- fused conversion kernel (all fp32->fp16 in one launch) --------
#define NSEG 11
struct CvtArgs {
    const float4* src[NSEG];
    uint2* dst[NSEG];
    int n4[NSEG];
};
__global__ __launch_bounds__(256)
void cvt_all(CvtArgs a)
{
    const int seg = blockIdx.y;
    const int i = blockIdx.x * 256 + threadIdx.x;
    if (i < a.n4[seg]) a.dst[seg][i] = cvt4(a.src[seg][i]);
}

// V transpose: vt[b][d][j] = v[b][j][d], emit fp16
__global__ __launch_bounds__(256)
void transpose_vt(const float* __restrict__ v, f16* __restrict__ vth)
{
    __shared__ float ts[32][33];
    const int b = blockIdx.z;
    const int j0 = blockIdx.x * 32, d0 = blockIdx.y * 32;
    const float* vb = v + (i64)b * NSEQ * D;
    const i64 ob = (i64)b * D * NSEQ;
    const int tx = threadIdx.x, ty = threadIdx.y;
    #pragma unroll
    for (int i = 0; i < 32; i += 8)
        ts[ty + i][tx] = vb[(i64)(j0 + ty + i) * D + d0 + tx];
    __syncthreads();
    #pragma unroll
    for (int i = 0; i < 32; i += 8) {
        i64 o = ob + (i64)(d0 + ty + i) * NSEQ + j0 + tx;
        vth[o] = __float2half(ts[tx][ty + i]);
    }
}

// row softmax over 1024, emit fp16
__global__ __launch_bounds__(256)
void softmax_k(const float* __restrict__ Sc, f16* __restrict__ oh)
{
    i64 row = blockIdx.x;
    const float4* p = reinterpret_cast<const float4*>(Sc + row * NSEQ);
    int t = threadIdx.x;
    float4 v = p[t];
    float mx = fmaxf(fmaxf(v.x, v.y), fmaxf(v.z, v.w));
    #pragma unroll
    for (int o = 16; o; o >>= 1) mx = fmaxf(mx, __shfl_xor_sync(0xffffffffu, mx, o));
    __shared__ float red8[8];
    int w = t >> 5;
    if ((t & 31) == 0) red8[w] = mx;
    __syncthreads();
    mx = red8[0];
    #pragma unroll
    for (int i = 1; i < 8; i++) mx = fmaxf(mx, red8[i]);
    v.x = expf(v.x - mx); v.y = expf(v.y - mx);
    v.z = expf(v.z - mx); v.w = expf(v.w - mx);
    float s = v.x + v.y + v.z + v.w;
    #pragma unroll
    for (int o = 16; o; o >>= 1) s += __shfl_xor_sync(0xffffffffu, s, o);
    __syncthreads();
    if ((t & 31) == 0) red8[w] = s;
    __syncthreads();
    s = red8[0] + red8[1] + red8[2] + red8[3] + red8[4] + red8[5] + red8[6] + red8[7];
    float inv = 1.0f / s;
    v.x *= inv; v.y *= inv; v.z *= inv; v.w *= inv;
    *reinterpret_cast<uint2*>(oh + row * NSEQ + t * 4) = cvt4(v);
}

// group norm (gn1): relu, emit fp16 only
__global__ __launch_bounds__(128)
void gn1_kernel(const float* __restrict__ in, f16* __restrict__ outh,
                const float* __restrict__ gw, const float* __restrict__ bw)
{
    const i64 row = blockIdx.x;
    const int t = threadIdx.x;
    float v = in[row * D + t];
    float s1 = v, s2 = v * v;
    #pragma unroll
    for (int o = 16; o; o >>= 1) {
        s1 += __shfl_xor_sync(0xffffffffu, s1, o);
        s2 += __shfl_xor_sync(0xffffffffu, s2, o);
    }
    __shared__ float a1[4], a2[4];
    int w = t >> 5;
    if ((t & 31) == 0) { a1[w] = s1; a2[w] = s2; }
    __syncthreads();
    s1 = a1[0] + a1[1] + a1[2] + a1[3];
    s2 = a2[0] + a2[1] + a2[2] + a2[3];
    float mu = s1 * (1.0f / D);
    float var = s2 * (1.0f / D) - mu * mu;
    float y = fmaxf((v - mu) * rsqrtf(var + 1e-5f) * gw[t] + bw[t], 0.f);
    outh[row * D + t] = __float2half(y);
}

// ---------------- driver ---------------------------------------------------------
#define SMEM_SZ 67584   // max(2*32KB operand stages, 128x132 f32 epilogue staging)

extern "C" void kernel_launch(void* const* d_in, const int* in_sizes, int n_in,
                              void* d_out, int out_size)
{
    (void)in_sizes; (void)n_in; (void)out_size;
    const float* ctrs   = (const float*)d_in[0];
    const float* feats  = (const float*)d_in[1];
    const float* Wq     = (const float*)d_in[2];
    const float* Wk     = (const float*)d_in[3];
    const float* Wv     = (const float*)d_in[4];
    const float* Wc     = (const float*)d_in[5];
    const float* Wp     = (const float*)d_in[6];
    const float* Ws     = (const float*)d_in[7];
    const float* Wl     = (const float*)d_in[8];
    const float* Wr     = (const float*)d_in[9];
    const float* Wc2    = (const float*)d_in[10];
    const float* g1     = (const float*)d_in[11];
    const float* b1     = (const float*)d_in[12];
    const float* g2     = (const float*)d_in[13];
    const float* b2     = (const float*)d_in[14];
    const int* pre_u    = (const int*)d_in[15];
    const int* pre_v    = (const int*)d_in[16];
    const int* suc_u    = (const int*)d_in[17];
    const int* suc_v    = (const int*)d_in[18];
    const int* left_u   = (const int*)d_in[19];
    const int* left_v   = (const int*)d_in[20];
    const int* right_u  = (const int*)d_in[21];
    const int* right_v  = (const int*)d_in[22];
    float* X = (float*)d_out;

    float *v, *sc, *T;
    cudaGetSymbolAddress((void**)&v,  g_v);
    cudaGetSymbolAddress((void**)&sc, g_sc);
    cudaGetSymbolAddress((void**)&T,  g_T);
    f16 *ctrs_h, *feat_h, *q_h, *k_h, *vt_h, *x_h, *y_h, *sc_h;
    f16 *wq_h, *wk_h, *wv_h, *wc_h, *wp_h, *ws_h, *wl_h, *wr_h, *w2_h;
    cudaGetSymbolAddress((void**)&ctrs_h, s_ctrs_h);
    cudaGetSymbolAddress((void**)&feat_h, s_feat_h);
    cudaGetSymbolAddress((void**)&q_h, s_q_h);
    cudaGetSymbolAddress((void**)&k_h, s_k_h);
    cudaGetSymbolAddress((void**)&vt_h, s_vt_h);
    cudaGetSymbolAddress((void**)&x_h, s_x_h);
    cudaGetSymbolAddress((void**)&y_h, s_y_h);
    cudaGetSymbolAddress((void**)&sc_h, s_sc_h);
    cudaGetSymbolAddress((void**)&wq_h, s_wq_h);
    cudaGetSymbolAddress((void**)&wk_h, s_wk_h);
    cudaGetSymbolAddress((void**)&wv_h, s_wv_h);
    cudaGetSymbolAddress((void**)&wc_h, s_wc_h);
    cudaGetSymbolAddress((void**)&wp_h, s_wp_h);
    cudaGetSymbolAddress((void**)&ws_h, s_ws_h);
    cudaGetSymbolAddress((void**)&wl_h, s_wl_h);
    cudaGetSymbolAddress((void**)&wr_h, s_wr_h);
    cudaGetSymbolAddress((void**)&w2_h, s_w2_h);

    cudaFuncSetAttribute((const void*)gemm_k<false,false,false,true ,false>, cudaFuncAttributeMaxDynamicSharedMemorySize, SMEM_SZ);
    cudaFuncSetAttribute((const void*)gemm_k<false,false,true ,false,false>, cudaFuncAttributeMaxDynamicSharedMemorySize, SMEM_SZ);
    cudaFuncSetAttribute((const void*)gemm_k<false,true ,true ,true ,false>, cudaFuncAttributeMaxDynamicSharedMemorySize, SMEM_SZ);
    cudaFuncSetAttribute((const void*)gemm_k<false,false,false,false,true >, cudaFuncAttributeMaxDynamicSharedMemorySize, SMEM_SZ);
    cudaFuncSetAttribute((const void*)layer_scatter, cudaFuncAttributeMaxDynamicSharedMemorySize, SMEM_SZ);

    const float NF = 0.08838834764831845f;  // 1/sqrt(128)
    dim3 blk(256);

    // ---- one fused conversion launch ----
    CvtArgs ca;
    const float* srcs[NSEG] = {ctrs, feats, Wq, Wk, Wv, Wc, Wp, Ws, Wl, Wr, Wc2};
    f16* dsts[NSEG] = {ctrs_h, feat_h, wq_h, wk_h, wv_h, wc_h, wp_h, ws_h, wl_h, wr_h, w2_h};
    const int ns[NSEG] = {M_ROWS*D, M_ROWS*D, DD, DD, DD, NL*DD, NL*NS*DD, NL*NS*DD, NL*DD, NL*DD, NL*DD};
    int maxn4 = 0;
    for (int i = 0; i < NSEG; i++) {
        ca.src[i] = (const float4*)srcs[i];
        ca.dst[i] = (uint2*)dsts[i];
        ca.n4[i] = ns[i] / 4;
        if (ca.n4[i] > maxn4) maxn4 = ca.n4[i];
    }
    cvt_all<<<dim3((maxn4 + 255) / 256, NSEG), 256>>>(ca);

    // ---- attention ----
    gemm_k<false,false,false,true,false><<<dim3(128,1,1), blk, SMEM_SZ>>>(
        ctrs_h, D, 0, wq_h, D, 0, (float*)0, D, 0, q_h, 0, 0, 0, 0, 0, 0, 0, 1.f, 1);
    gemm_k<false,false,false,true,false><<<dim3(128,1,1), blk, SMEM_SZ>>>(
        feat_h, D, 0, wk_h, D, 0, (float*)0, D, 0, k_h, 0, 0, 0, 0, 0, 0, 0, 1.f, 1);
    gemm_k<false,false,true,false,false><<<dim3(128,1,1), blk, SMEM_SZ>>>(
        feat_h, D, 0, wv_h, D, 0, v, D, 0, 0, 0, 0, 0, 0, 0, 0, 0, 1.f, 1);
    transpose_vt<<<dim3(NSEQ/32, D/32, BATCH), dim3(32,8)>>>(v, vt_h);
    gemm_k<false,false,true,false,false><<<dim3(8,8,16), blk, SMEM_SZ>>>(
        q_h, D, (i64)NSEQ*D, k_h, D, (i64)NSEQ*D,
        sc, NSEQ, (i64)NSEQ*NSEQ, 0, 0, 0, 0, 0, 0, 0, 0, NF, 1);
    softmax_k<<<M_ROWS, 256>>>(sc, sc_h);
    gemm_k<false,true,true,true,false><<<dim3(8,1,16), blk, SMEM_SZ>>>(
        sc_h, NSEQ, (i64)NSEQ*NSEQ, vt_h, NSEQ, (i64)D*NSEQ,
        X, D, (i64)NSEQ*D, x_h, feats, (i64)NSEQ*D, 0, 0, 0, 0, 0, 1.f, 8);

    // ---- 4-layer fusion loop ----
    for (int i = 0; i < NL; i++) {
        // ctr GEMM: plain store initializes T (no zeroing needed)
        gemm_k<false,false,true,false,false><<<dim3(128,1,1), blk, SMEM_SZ>>>(
            x_h, D, 0, wc_h + (i64)i*DD, D, 0,
            T, D, 0, 0, 0, 0, 0, 0, 0, 0, 0, 1.f, 1);
        // edge scatter: red.v4 adds into T
        layer_scatter<<<3584, blk, SMEM_SZ>>>(
            x_h,
            wp_h + (i64)i*NS*DD,
            ws_h + (i64)i*NS*DD,
            wl_h + (i64)i*DD,
            wr_h + (i64)i*DD,
            T, pre_u, pre_v, suc_u, suc_v, left_u, left_v, right_u, right_v);
        // gn1 + relu -> y_h (fp16)
        gn1_kernel<<<M_ROWS, 128>>>(T, y_h, g1 + i*D, b1 + i*D);
        // ctr2 GEMM with fused gn2 + residual + relu epilogue -> X (fp32) + x_h (fp16)
        gemm_k<false,false,false,false,true><<<dim3(128,1,1), blk, SMEM_SZ>>>(
            y_h, D, 0, w2_h + (i64)i*DD, D, 0,
            X, D, 0, x_h, X, 0, 0, 0, 0, g2 + i*D, b2 + i*D, 1.f, 1);
    }
}

// round 9
// speedup vs baseline: 2.0103x; 1.2340x over previous
#include <cuda_runtime.h>
#include <cuda_fp16.h>
#include <math.h>
#include <stdint.h>

#define D 128
#define DD 16384
#define BATCH 16
#define NSEQ 1024
#define M_ROWS 16384
#define NE 32768
#define NS 6
#define NL 4

typedef unsigned long long u64;
typedef unsigned int u32;
typedef long long i64;
typedef __half f16;

// ---------------- scratch (fp32) ---------------------------------------------
__device__ __align__(256) float g_v [M_ROWS * D];
__device__ __align__(256) float g_sc[(size_t)BATCH * NSEQ * NSEQ];
__device__ __align__(256) float g_T [M_ROWS * D];

// ---------------- scratch (fp16) -----------------------------------------------
__device__ __align__(256) f16 s_ctrs_h[M_ROWS*D];
__device__ __align__(256) f16 s_feat_h[M_ROWS*D];
__device__ __align__(256) f16 s_q_h[M_ROWS*D];
__device__ __align__(256) f16 s_k_h[M_ROWS*D];
__device__ __align__(256) f16 s_vt_h[M_ROWS*D];
__device__ __align__(256) f16 s_x_h[M_ROWS*D];
__device__ __align__(256) f16 s_y_h[M_ROWS*D];
__device__ __align__(256) f16 s_sc_h[(size_t)BATCH*NSEQ*NSEQ];
__device__ __align__(256) f16 s_wq_h[DD], s_wk_h[DD], s_wv_h[DD];
__device__ __align__(256) f16 s_wc_h[NL*DD];
__device__ __align__(256) f16 s_wp_h[NL*NS*DD];
__device__ __align__(256) f16 s_ws_h[NL*NS*DD];
__device__ __align__(256) f16 s_wl_h[NL*DD];
__device__ __align__(256) f16 s_wr_h[NL*DD];
__device__ __align__(256) f16 s_w2_h[NL*DD];

// ---------------- PTX helpers ------------------------------------------------
__device__ __forceinline__ u32 smem_u32(const void* p) {
    u32 a;
    asm("{ .reg .u64 t; cvta.to.shared.u64 t, %1; cvt.u32.u64 %0, t; }" : "=r"(a) : "l"(p));
    return a;
}
__device__ __forceinline__ void ldsm4(u32* r, u32 addr) {
    asm volatile("ldmatrix.sync.aligned.m8n8.x4.shared.b16 {%0,%1,%2,%3}, [%4];"
                 : "=r"(r[0]), "=r"(r[1]), "=r"(r[2]), "=r"(r[3]) : "r"(addr));
}
__device__ __forceinline__ void mma_f16(float* d, const u32* a, u32 b0, u32 b1) {
    asm volatile("mma.sync.aligned.m16n8k16.row.col.f32.f16.f16.f32 "
                 "{%0,%1,%2,%3}, {%4,%5,%6,%7}, {%8,%9}, {%0,%1,%2,%3};"
                 : "+f"(d[0]), "+f"(d[1]), "+f"(d[2]), "+f"(d[3])
                 : "r"(a[0]), "r"(a[1]), "r"(a[2]), "r"(a[3]), "r"(b0), "r"(b1));
}
__device__ __forceinline__ void red4(float* p, float a, float b, float c, float d) {
    asm volatile("red.global.add.v4.f32 [%0], {%1,%2,%3,%4};"
                 :: "l"(p), "f"(a), "f"(b), "f"(c), "f"(d) : "memory");
}
__device__ __forceinline__ void red2(float* p, float a, float b) {
    asm volatile("red.global.add.v2.f32 [%0], {%1,%2};"
                 :: "l"(p), "f"(a), "f"(b) : "memory");
}
__device__ __forceinline__ void cp16_cg(u32 dst, const void* src) {
    asm volatile("cp.async.cg.shared.global [%0], [%1], 16;" :: "r"(dst), "l"(src));
}
__device__ __forceinline__ void cp16_ca(u32 dst, const void* src) {
    asm volatile("cp.async.ca.shared.global [%0], [%1], 16;" :: "r"(dst), "l"(src));
}
__device__ __forceinline__ void cp_commit() { asm volatile("cp.async.commit_group;" ::: "memory"); }
template<int N> __device__ __forceinline__ void cp_wait() {
    asm volatile("cp.async.wait_group %0;" :: "n"(N) : "memory");
}
__device__ __forceinline__ uint2 cvt4(float4 v) {
    __half2 h0 = __floats2half2_rn(v.x, v.y);
    __half2 h1 = __floats2half2_rn(v.z, v.w);
    return make_uint2(*(u32*)&h0, *(u32*)&h1);
}

// ---------------- generic GEMM core (dense paths; unchanged from R8) ------------
template<bool GS, bool RES, bool OF32, bool OF16, bool GN2>
__device__ __forceinline__ void gemm_core(
    const f16* __restrict__ Ah, int lda,
    const f16* __restrict__ Bh, int ldb,
    float* __restrict__ C, int ldc,
    f16* __restrict__ Ch,
    const float* __restrict__ Fres,
    const int* __restrict__ gi, const int* __restrict__ si,
    const float* __restrict__ gw, const float* __restrict__ bw,
    int row0, int col0, float scale, int KT)
{
    extern __shared__ char sm[];
    const u32 sb = smem_u32(sm);
    const int tid = threadIdx.x;
    const int wid = tid >> 5, lane = tid & 31;
    const int m0w = (wid >> 1) * 32, n0w = (wid & 1) * 64;

    float acc[2][8][4];
    #pragma unroll
    for (int mi = 0; mi < 2; mi++)
        #pragma unroll
        for (int nj = 0; nj < 8; nj++)
            #pragma unroll
            for (int e = 0; e < 4; e++) acc[mi][nj][e] = 0.f;

    const u32 a_rb = (u32)(m0w + (lane & 15)) * 128;
    const u32 b_rb = (u32)(n0w + ((lane >> 4) << 3) + (lane & 7)) * 128;
    const int a_hi = lane >> 4;
    const int b_hi = (lane >> 3) & 1;
    const int xr = lane & 7;

    const int r_ld = tid >> 1;
    const int c0_ld = (tid & 1) * 4;
    i64 arow_ld = GS ? (i64)__ldg(gi + r_ld) : (i64)(row0 + r_ld);
    const int H = 2 * KT;

    auto load_half = [&](int h, int s) {
        const int kofs = h * 64;
        const u32 base = sb + (u32)s * 32768u;
        const f16* ap = Ah + arow_ld * (i64)lda + kofs;
        const f16* bp = Bh + (i64)(col0 + r_ld) * ldb + kofs;
        #pragma unroll
        for (int j = 0; j < 4; j++) {
            int c = c0_ld + j;
            u32 so = (u32)r_ld * 128 + (u32)((c ^ (r_ld & 7)) << 4);
            cp16_cg(base + so,          ap + c * 8);
            cp16_ca(base + 16384 + so,  bp + c * 8);
        }
        cp_commit();
    };

    load_half(0, 0);
    for (int h = 0; h < H; h++) {
        const int s = h & 1;
        const bool more = (h + 1 < H);
        if (more) { load_half(h + 1, 1 - s); cp_wait<1>(); }
        else      { cp_wait<0>(); }
        __syncthreads();
        const u32 base = sb + (u32)s * 32768u;
        const u32 abase = base + a_rb;
        const u32 bbase = base + 16384u + b_rb;
        #pragma unroll
        for (int ks = 0; ks < 4; ks++) {
            const u32 aoff = (u32)(((ks * 2 + a_hi) ^ xr) << 4);
            const u32 boff = (u32)(((ks * 2 + b_hi) ^ xr) << 4);
            u32 b[4][4], a0[4], a1[4];
            #pragma unroll
            for (int p = 0; p < 4; p++)
                ldsm4(b[p], bbase + boff + p * 2048);
            ldsm4(a0, abase + aoff);
            ldsm4(a1, abase + aoff + 2048);
            #pragma unroll
            for (int nj = 0; nj < 8; nj++) {
                u32 bb0 = b[nj >> 1][(nj & 1) * 2], bb1 = b[nj >> 1][(nj & 1) * 2 + 1];
                mma_f16(acc[0][nj], a0, bb0, bb1);
                mma_f16(acc[1][nj], a1, bb0, bb1);
            }
        }
        __syncthreads();
    }

    // ---- stage C to SMEM (pitch 132 floats), then output ----
    float* Cs = reinterpret_cast<float*>(sm);
    const int g = lane >> 2, q2 = (lane & 3) * 2;
    #pragma unroll
    for (int mi = 0; mi < 2; mi++)
        #pragma unroll
        for (int nj = 0; nj < 8; nj++) {
            int r = m0w + mi * 16 + g;
            int c = n0w + nj * 8 + q2;
            Cs[r * 132 + c]           = acc[mi][nj][0];
            Cs[r * 132 + c + 1]       = acc[mi][nj][1];
            Cs[(r + 8) * 132 + c]     = acc[mi][nj][2];
            Cs[(r + 8) * 132 + c + 1] = acc[mi][nj][3];
        }
    __syncthreads();

    const int rr = tid >> 1, hh = tid & 1;
    const float* srow = Cs + rr * 132 + hh * 64;
    if (GS) {
        i64 drow = (i64)__ldg(si + rr);
        float* p = C + drow * (i64)ldc + col0 + hh * 64;
        #pragma unroll
        for (int j = 0; j < 16; j++) {
            float4 vv = *reinterpret_cast<const float4*>(srow + j * 4);
            red4(p + j * 4, vv.x, vv.y, vv.z, vv.w);
        }
    } else if (GN2) {
        float s1 = 0.f, s2 = 0.f;
        #pragma unroll
        for (int j = 0; j < 16; j++) {
            float4 vv = *reinterpret_cast<const float4*>(srow + j * 4);
            s1 += vv.x + vv.y + vv.z + vv.w;
            s2 += vv.x * vv.x + vv.y * vv.y + vv.z * vv.z + vv.w * vv.w;
        }
        s1 += __shfl_xor_sync(0xffffffffu, s1, 1);
        s2 += __shfl_xor_sync(0xffffffffu, s2, 1);
        const float mu = s1 * (1.f / 128.f);
        const float var = s2 * (1.f / 128.f) - mu * mu;
        const float rstd = rsqrtf(var + 1e-5f);
        const i64 ro = (i64)(row0 + rr) * D + hh * 64;
        const float* fp = Fres + ro;
        float* p = C + ro;
        const float* gp = gw + hh * 64;
        const float* bp = bw + hh * 64;
        #pragma unroll
        for (int j = 0; j < 16; j++) {
            float4 vv = *reinterpret_cast<const float4*>(srow + j * 4);
            float4 g4 = *reinterpret_cast<const float4*>(gp + j * 4);
            float4 b4 = *reinterpret_cast<const float4*>(bp + j * 4);
            float4 f4 = *reinterpret_cast<const float4*>(fp + j * 4);
            vv.x = fmaxf((vv.x - mu) * rstd * g4.x + b4.x + f4.x, 0.f);
            vv.y = fmaxf((vv.y - mu) * rstd * g4.y + b4.y + f4.y, 0.f);
            vv.z = fmaxf((vv.z - mu) * rstd * g4.z + b4.z + f4.z, 0.f);
            vv.w = fmaxf((vv.w - mu) * rstd * g4.w + b4.w + f4.w, 0.f);
            *reinterpret_cast<float4*>(p + j * 4) = vv;
            *reinterpret_cast<uint2*>(Ch + ro + j * 4) = cvt4(vv);
        }
    } else {
        const i64 ro = (i64)(row0 + rr) * ldc + col0 + hh * 64;
        const float* fp = RES ? (Fres + ro) : (const float*)0;
        float* p = OF32 ? (C + ro) : (float*)0;
        #pragma unroll
        for (int j = 0; j < 16; j++) {
            float4 vv = *reinterpret_cast<const float4*>(srow + j * 4);
            vv.x *= scale; vv.y *= scale; vv.z *= scale; vv.w *= scale;
            if (RES) {
                float4 f = *reinterpret_cast<const float4*>(fp + j * 4);
                vv.x += f.x; vv.y += f.y; vv.z += f.z; vv.w += f.w;
            }
            if (OF32) *reinterpret_cast<float4*>(p + j * 4) = vv;
            if (OF16) *reinterpret_cast<uint2*>(Ch + ro + j * 4) = cvt4(vv);
        }
    }
}

template<bool GS, bool RES, bool OF32, bool OF16, bool GN2>
__global__ __launch_bounds__(256, 2)
void gemm_k(const f16* Ah, int lda, i64 aZ,
            const f16* Bh, int ldb, i64 bZ,
            float* C, int ldc, i64 cZ,
            f16* Ch,
            const float* Fres, i64 fZ,
            const int* gidx, const int* sidx, i64 iZ,
            const float* gw, const float* bw,
            float scale, int KT)
{
    const int z = blockIdx.z;
    const int row0 = blockIdx.x * 128, col0 = blockIdx.y * 128;
    gemm_core<GS, RES, OF32, OF16, GN2>(
        Ah + (i64)z * aZ, lda,
        Bh + (i64)z * bZ, ldb,
        C + (i64)z * cZ, ldc,
        (OF16 || GN2) ? Ch + (i64)z * cZ : (f16*)0,
        (RES || GN2) ? Fres + (i64)z * fZ : (const float*)0,
        GS ? gidx + (i64)z * iZ + row0 : (const int*)0,
        GS ? sidx + (i64)z * iZ + row0 : (const int*)0,
        gw, bw, row0, col0, scale, KT);
}

// ---------------- persistent-B scatter kernel -----------------------------------
// 3584 tiles (14 weight groups x 256). Each CTA: contiguous tile chunk, keeps the
// current group's B tile (32KB) resident in SMEM; A (gathered rows) double-buffered
// across tiles; epilogue = red.v2 directly from MMA fragments (no staging).
// SMEM: A stage0 @0 (16KB), A stage1 @16KB, B halves @32KB,48KB = 64KB total.
#define NTILES_SC 3584
#define CHUNK_SC 12
#define GRID_SC ((NTILES_SC + CHUNK_SC - 1) / CHUNK_SC)   // 299

__global__ __launch_bounds__(256, 2)
void layer_scatter_p(const f16* __restrict__ Xh,
                     const f16* __restrict__ wph, const f16* __restrict__ wsh,
                     const f16* __restrict__ wlh, const f16* __restrict__ wrh,
                     float* __restrict__ T,
                     const int* __restrict__ pre_u, const int* __restrict__ pre_v,
                     const int* __restrict__ suc_u, const int* __restrict__ suc_v,
                     const int* __restrict__ left_u, const int* __restrict__ left_v,
                     const int* __restrict__ right_u, const int* __restrict__ right_v)
{
    extern __shared__ char sm[];
    const u32 sb = smem_u32(sm);
    const int t0 = blockIdx.x * CHUNK_SC;
    const int t1 = (t0 + CHUNK_SC < NTILES_SC) ? t0 + CHUNK_SC : NTILES_SC;
    if (t0 >= NTILES_SC) return;

    const int tid = threadIdx.x;
    const int wid = tid >> 5, lane = tid & 31;
    const int m0w = (wid >> 1) * 32, n0w = (wid & 1) * 64;
    const u32 a_rb = (u32)(m0w + (lane & 15)) * 128;
    const u32 b_rb = (u32)(n0w + ((lane >> 4) << 3) + (lane & 7)) * 128;
    const int a_hi = lane >> 4;
    const int b_hi = (lane >> 3) & 1;
    const int xr = lane & 7;
    const int r_ld = tid >> 1;
    const int c0_ld = (tid & 1) * 4;

    auto group_of = [&](int t, const f16*& Bw, const int*& gv, const int*& su) {
        int g = t >> 8, e = (t & 255) * 128;
        if (g < 6)        { Bw = wph + (i64)g * DD;       gv = pre_v + g * NE + e;        su = pre_u + g * NE + e; }
        else if (g < 12)  { int z = g - 6; Bw = wsh + (i64)z * DD; gv = suc_v + z * NE + e; su = suc_u + z * NE + e; }
        else if (g == 12) { Bw = wlh;                     gv = left_v + e;                 su = left_u + e; }
        else              { Bw = wrh;                     gv = right_v + e;                su = right_u + e; }
    };

    auto load_B = [&](const f16* Bw) {
        const f16* bp = Bw + (i64)r_ld * D;
        #pragma unroll
        for (int h = 0; h < 2; h++) {
            const u32 base = sb + 32768u + (u32)h * 16384u;
            #pragma unroll
            for (int j = 0; j < 4; j++) {
                int c = c0_ld + j;
                u32 so = (u32)r_ld * 128 + (u32)((c ^ (r_ld & 7)) << 4);
                cp16_ca(base + so, bp + h * 64 + c * 8);
            }
        }
        cp_commit();
    };
    auto load_A = [&](const int* gv, int h, int s) {
        i64 arow = (i64)__ldg(gv + r_ld);
        const f16* ap = Xh + arow * D + h * 64;
        const u32 base = sb + (u32)s * 16384u;
        #pragma unroll
        for (int j = 0; j < 4; j++) {
            int c = c0_ld + j;
            u32 so = (u32)r_ld * 128 + (u32)((c ^ (r_ld & 7)) << 4);
            cp16_cg(base + so, ap + c * 8);
        }
        cp_commit();
    };

    const int g = lane >> 2, q2 = (lane & 3) * 2;
    const f16* Bw; const int* gv; const int* su;
    group_of(t0, Bw, gv, su);
    int curg = t0 >> 8;
    load_B(Bw);
    load_A(gv, 0, 0);
    load_A(gv, 1, 1);

    for (int t = t0; t < t1; t++) {
        const f16* Bw_n = 0; const int* gv_n = 0; const int* su_n = 0;
        const bool have_next = (t + 1 < t1);
        int g_n = curg;
        if (have_next) { group_of(t + 1, Bw_n, gv_n, su_n); g_n = (t + 1) >> 8; }
        const bool pref0 = have_next && (g_n == curg);

        float acc[2][8][4];
        #pragma unroll
        for (int mi = 0; mi < 2; mi++)
            #pragma unroll
            for (int nj = 0; nj < 8; nj++)
                #pragma unroll
                for (int e = 0; e < 4; e++) acc[mi][nj][e] = 0.f;

        // half 0
        cp_wait<1>(); __syncthreads();
        {
            const u32 abase = sb + a_rb;
            const u32 bbase = sb + 32768u + b_rb;
            #pragma unroll
            for (int ks = 0; ks < 4; ks++) {
                const u32 aoff = (u32)(((ks * 2 + a_hi) ^ xr) << 4);
                const u32 boff = (u32)(((ks * 2 + b_hi) ^ xr) << 4);
                u32 b[4][4], a0[4], a1[4];
                #pragma unroll
                for (int p = 0; p < 4; p++)
                    ldsm4(b[p], bbase + boff + p * 2048);
                ldsm4(a0, abase + aoff);
                ldsm4(a1, abase + aoff + 2048);
                #pragma unroll
                for (int nj = 0; nj < 8; nj++) {
                    u32 bb0 = b[nj >> 1][(nj & 1) * 2], bb1 = b[nj >> 1][(nj & 1) * 2 + 1];
                    mma_f16(acc[0][nj], a0, bb0, bb1);
                    mma_f16(acc[1][nj], a1, bb0, bb1);
                }
            }
        }
        __syncthreads();
        if (pref0) load_A(gv_n, 0, 0);

        // half 1
        if (pref0) cp_wait<1>(); else cp_wait<0>();
        __syncthreads();
        {
            const u32 abase = sb + 16384u + a_rb;
            const u32 bbase = sb + 49152u + b_rb;
            #pragma unroll
            for (int ks = 0; ks < 4; ks++) {
                const u32 aoff = (u32)(((ks * 2 + a_hi) ^ xr) << 4);
                const u32 boff = (u32)(((ks * 2 + b_hi) ^ xr) << 4);
                u32 b[4][4], a0[4], a1[4];
                #pragma unroll
                for (int p = 0; p < 4; p++)
                    ldsm4(b[p], bbase + boff + p * 2048);
                ldsm4(a0, abase + aoff);
                ldsm4(a1, abase + aoff + 2048);
                #pragma unroll
                for (int nj = 0; nj < 8; nj++) {
                    u32 bb0 = b[nj >> 1][(nj & 1) * 2], bb1 = b[nj >> 1][(nj & 1) * 2 + 1];
                    mma_f16(acc[0][nj], a0, bb0, bb1);
                    mma_f16(acc[1][nj], a1, bb0, bb1);
                }
            }
        }

        // epilogue: red.v2 directly from fragments
        #pragma unroll
        for (int mi = 0; mi < 2; mi++) {
            i64 dr1 = (i64)__ldg(su + m0w + mi * 16 + g);
            i64 dr2 = (i64)__ldg(su + m0w + mi * 16 + g + 8);
            float* p1 = T + dr1 * D + n0w + q2;
            float* p2 = T + dr2 * D + n0w + q2;
            #pragma unroll
            for (int nj = 0; nj < 8; nj++) {
                red2(p1 + nj * 8, acc[mi][nj][0], acc[mi][nj][1]);
                red2(p2 + nj * 8, acc[mi][nj][2], acc[mi][nj][3]);
            }
        }
        __syncthreads();

        if (have_next) {
            if (g_n == curg) {
                load_A(gv_n, 1, 1);
            } else {
                cp_wait<0>(); __syncthreads();
                load_B(Bw_n);
                load_A(gv_n, 0, 0);
                load_A(gv_n, 1, 1);
                curg = g_n;
            }
            gv = gv_n; su = su_n;
        }
    }
}

// ---------------- fused conversion kernel ----------------------------------------
#define NSEG 11
struct CvtArgs {
    const float4* src[NSEG];
    uint2* dst[NSEG];
    int n4[NSEG];
};
__global__ __launch_bounds__(256)
void cvt_all(CvtArgs a)
{
    const int seg = blockIdx.y;
    const int i = blockIdx.x * 256 + threadIdx.x;
    if (i < a.n4[seg]) a.dst[seg][i] = cvt4(a.src[seg][i]);
}

// V transpose: vt[b][d][j] = v[b][j][d], emit fp16
__global__ __launch_bounds__(256)
void transpose_vt(const float* __restrict__ v, f16* __restrict__ vth)
{
    __shared__ float ts[32][33];
    const int b = blockIdx.z;
    const int j0 = blockIdx.x * 32, d0 = blockIdx.y * 32;
    const float* vb = v + (i64)b * NSEQ * D;
    const i64 ob = (i64)b * D * NSEQ;
    const int tx = threadIdx.x, ty = threadIdx.y;
    #pragma unroll
    for (int i = 0; i < 32; i += 8)
        ts[ty + i][tx] = vb[(i64)(j0 + ty + i) * D + d0 + tx];
    __syncthreads();
    #pragma unroll
    for (int i = 0; i < 32; i += 8) {
        i64 o = ob + (i64)(d0 + ty + i) * NSEQ + j0 + tx;
        vth[o] = __float2half(ts[tx][ty + i]);
    }
}

// row softmax over 1024, emit fp16
__global__ __launch_bounds__(256)
void softmax_k(const float* __restrict__ Sc, f16* __restrict__ oh)
{
    i64 row = blockIdx.x;
    const float4* p = reinterpret_cast<const float4*>(Sc + row * NSEQ);
    int t = threadIdx.x;
    float4 v = p[t];
    float mx = fmaxf(fmaxf(v.x, v.y), fmaxf(v.z, v.w));
    #pragma unroll
    for (int o = 16; o; o >>= 1) mx = fmaxf(mx, __shfl_xor_sync(0xffffffffu, mx, o));
    __shared__ float red8[8];
    int w = t >> 5;
    if ((t & 31) == 0) red8[w] = mx;
    __syncthreads();
    mx = red8[0];
    #pragma unroll
    for (int i = 1; i < 8; i++) mx = fmaxf(mx, red8[i]);
    v.x = expf(v.x - mx); v.y = expf(v.y - mx);
    v.z = expf(v.z - mx); v.w = expf(v.w - mx);
    float s = v.x + v.y + v.z + v.w;
    #pragma unroll
    for (int o = 16; o; o >>= 1) s += __shfl_xor_sync(0xffffffffu, s, o);
    __syncthreads();
    if ((t & 31) == 0) red8[w] = s;
    __syncthreads();
    s = red8[0] + red8[1] + red8[2] + red8[3] + red8[4] + red8[5] + red8[6] + red8[7];
    float inv = 1.0f / s;
    v.x *= inv; v.y *= inv; v.z *= inv; v.w *= inv;
    *reinterpret_cast<uint2*>(oh + row * NSEQ + t * 4) = cvt4(v);
}

// group norm (gn1): relu, emit fp16 only
__global__ __launch_bounds__(128)
void gn1_kernel(const float* __restrict__ in, f16* __restrict__ outh,
                const float* __restrict__ gw, const float* __restrict__ bw)
{
    const i64 row = blockIdx.x;
    const int t = threadIdx.x;
    float v = in[row * D + t];
    float s1 = v, s2 = v * v;
    #pragma unroll
    for (int o = 16; o; o >>= 1) {
        s1 += __shfl_xor_sync(0xffffffffu, s1, o);
        s2 += __shfl_xor_sync(0xffffffffu, s2, o);
    }
    __shared__ float a1[4], a2[4];
    int w = t >> 5;
    if ((t & 31) == 0) { a1[w] = s1; a2[w] = s2; }
    __syncthreads();
    s1 = a1[0] + a1[1] + a1[2] + a1[3];
    s2 = a2[0] + a2[1] + a2[2] + a2[3];
    float mu = s1 * (1.0f / D);
    float var = s2 * (1.0f / D) - mu * mu;
    float y = fmaxf((v - mu) * rsqrtf(var + 1e-5f) * gw[t] + bw[t], 0.f);
    outh[row * D + t] = __float2half(y);
}

// ---------------- driver ---------------------------------------------------------
#define SMEM_SZ 67584   // dense path: 2x32KB operand stages / epilogue staging
#define SMEM_SC 65536   // persistent scatter: 2x16KB A + 32KB B

extern "C" void kernel_launch(void* const* d_in, const int* in_sizes, int n_in,
                              void* d_out, int out_size)
{
    (void)in_sizes; (void)n_in; (void)out_size;
    const float* ctrs   = (const float*)d_in[0];
    const float* feats  = (const float*)d_in[1];
    const float* Wq     = (const float*)d_in[2];
    const float* Wk     = (const float*)d_in[3];
    const float* Wv     = (const float*)d_in[4];
    const float* Wc     = (const float*)d_in[5];
    const float* Wp     = (const float*)d_in[6];
    const float* Ws     = (const float*)d_in[7];
    const float* Wl     = (const float*)d_in[8];
    const float* Wr     = (const float*)d_in[9];
    const float* Wc2    = (const float*)d_in[10];
    const float* g1     = (const float*)d_in[11];
    const float* b1     = (const float*)d_in[12];
    const float* g2     = (const float*)d_in[13];
    const float* b2     = (const float*)d_in[14];
    const int* pre_u    = (const int*)d_in[15];
    const int* pre_v    = (const int*)d_in[16];
    const int* suc_u    = (const int*)d_in[17];
    const int* suc_v    = (const int*)d_in[18];
    const int* left_u   = (const int*)d_in[19];
    const int* left_v   = (const int*)d_in[20];
    const int* right_u  = (const int*)d_in[21];
    const int* right_v  = (const int*)d_in[22];
    float* X = (float*)d_out;

    float *v, *sc, *T;
    cudaGetSymbolAddress((void**)&v,  g_v);
    cudaGetSymbolAddress((void**)&sc, g_sc);
    cudaGetSymbolAddress((void**)&T,  g_T);
    f16 *ctrs_h, *feat_h, *q_h, *k_h, *vt_h, *x_h, *y_h, *sc_h;
    f16 *wq_h, *wk_h, *wv_h, *wc_h, *wp_h, *ws_h, *wl_h, *wr_h, *w2_h;
    cudaGetSymbolAddress((void**)&ctrs_h, s_ctrs_h);
    cudaGetSymbolAddress((void**)&feat_h, s_feat_h);
    cudaGetSymbolAddress((void**)&q_h, s_q_h);
    cudaGetSymbolAddress((void**)&k_h, s_k_h);
    cudaGetSymbolAddress((void**)&vt_h, s_vt_h);
    cudaGetSymbolAddress((void**)&x_h, s_x_h);
    cudaGetSymbolAddress((void**)&y_h, s_y_h);
    cudaGetSymbolAddress((void**)&sc_h, s_sc_h);
    cudaGetSymbolAddress((void**)&wq_h, s_wq_h);
    cudaGetSymbolAddress((void**)&wk_h, s_wk_h);
    cudaGetSymbolAddress((void**)&wv_h, s_wv_h);
    cudaGetSymbolAddress((void**)&wc_h, s_wc_h);
    cudaGetSymbolAddress((void**)&wp_h, s_wp_h);
    cudaGetSymbolAddress((void**)&ws_h, s_ws_h);
    cudaGetSymbolAddress((void**)&wl_h, s_wl_h);
    cudaGetSymbolAddress((void**)&wr_h, s_wr_h);
    cudaGetSymbolAddress((void**)&w2_h, s_w2_h);

    cudaFuncSetAttribute((const void*)gemm_k<false,false,false,true ,false>, cudaFuncAttributeMaxDynamicSharedMemorySize, SMEM_SZ);
    cudaFuncSetAttribute((const void*)gemm_k<false,false,true ,false,false>, cudaFuncAttributeMaxDynamicSharedMemorySize, SMEM_SZ);
    cudaFuncSetAttribute((const void*)gemm_k<false,true ,true ,true ,false>, cudaFuncAttributeMaxDynamicSharedMemorySize, SMEM_SZ);
    cudaFuncSetAttribute((const void*)gemm_k<false,false,false,false,true >, cudaFuncAttributeMaxDynamicSharedMemorySize, SMEM_SZ);
    cudaFuncSetAttribute((const void*)layer_scatter_p, cudaFuncAttributeMaxDynamicSharedMemorySize, SMEM_SC);

    const float NF = 0.08838834764831845f;  // 1/sqrt(128)
    dim3 blk(256);

    // ---- one fused conversion launch ----
    CvtArgs ca;
    const float* srcs[NSEG] = {ctrs, feats, Wq, Wk, Wv, Wc, Wp, Ws, Wl, Wr, Wc2};
    f16* dsts[NSEG] = {ctrs_h, feat_h, wq_h, wk_h, wv_h, wc_h, wp_h, ws_h, wl_h, wr_h, w2_h};
    const int ns[NSEG] = {M_ROWS*D, M_ROWS*D, DD, DD, DD, NL*DD, NL*NS*DD, NL*NS*DD, NL*DD, NL*DD, NL*DD};
    int maxn4 = 0;
    for (int i = 0; i < NSEG; i++) {
        ca.src[i] = (const float4*)srcs[i];
        ca.dst[i] = (uint2*)dsts[i];
        ca.n4[i] = ns[i] / 4;
        if (ca.n4[i] > maxn4) maxn4 = ca.n4[i];
    }
    cvt_all<<<dim3((maxn4 + 255) / 256, NSEG), 256>>>(ca);

    // ---- attention ----
    gemm_k<false,false,false,true,false><<<dim3(128,1,1), blk, SMEM_SZ>>>(
        ctrs_h, D, 0, wq_h, D, 0, (float*)0, D, 0, q_h, 0, 0, 0, 0, 0, 0, 0, 1.f, 1);
    gemm_k<false,false,false,true,false><<<dim3(128,1,1), blk, SMEM_SZ>>>(
        feat_h, D, 0, wk_h, D, 0, (float*)0, D, 0, k_h, 0, 0, 0, 0, 0, 0, 0, 1.f, 1);
    gemm_k<false,false,true,false,false><<<dim3(128,1,1), blk, SMEM_SZ>>>(
        feat_h, D, 0, wv_h, D, 0, v, D, 0, 0, 0, 0, 0, 0, 0, 0, 0, 1.f, 1);
    transpose_vt<<<dim3(NSEQ/32, D/32, BATCH), dim3(32,8)>>>(v, vt_h);
    gemm_k<false,false,true,false,false><<<dim3(8,8,16), blk, SMEM_SZ>>>(
        q_h, D, (i64)NSEQ*D, k_h, D, (i64)NSEQ*D,
        sc, NSEQ, (i64)NSEQ*NSEQ, 0, 0, 0, 0, 0, 0, 0, 0, NF, 1);
    softmax_k<<<M_ROWS, 256>>>(sc, sc_h);
    gemm_k<false,true,true,true,false><<<dim3(8,1,16), blk, SMEM_SZ>>>(
        sc_h, NSEQ, (i64)NSEQ*NSEQ, vt_h, NSEQ, (i64)D*NSEQ,
        X, D, (i64)NSEQ*D, x_h, feats, (i64)NSEQ*D, 0, 0, 0, 0, 0, 1.f, 8);

    // ---- 4-layer fusion loop ----
    for (int i = 0; i < NL; i++) {
        // ctr GEMM: plain store initializes T
        gemm_k<false,false,true,false,false><<<dim3(128,1,1), blk, SMEM_SZ>>>(
            x_h, D, 0, wc_h + (i64)i*DD, D, 0,
            T, D, 0, 0, 0, 0, 0, 0, 0, 0, 0, 1.f, 1);
        // persistent-B edge scatter: red.v2 adds into T
        layer_scatter_p<<<GRID_SC, blk, SMEM_SC>>>(
            x_h,
            wp_h + (i64)i*NS*DD,
            ws_h + (i64)i*NS*DD,
            wl_h + (i64)i*DD,
            wr_h + (i64)i*DD,
            T, pre_u, pre_v, suc_u, suc_v, left_u, left_v, right_u, right_v);
        // gn1 + relu -> y_h (fp16)
        gn1_kernel<<<M_ROWS, 128>>>(T, y_h, g1 + i*D, b1 + i*D);
        // ctr2 GEMM with fused gn2 + residual + relu epilogue -> X (fp32) + x_h (fp16)
        gemm_k<false,false,false,false,true><<<dim3(128,1,1), blk, SMEM_SZ>>>(
            y_h, D, 0, w2_h + (i64)i*DD, D, 0,
            X, D, 0, x_h, X, 0, 0, 0, 0, g2 + i*D, b2 + i*D, 1.f, 1);
    }
}

// round 10
// speedup vs baseline: 2.0767x; 1.0331x over previous
#include <cuda_runtime.h>
#include <cuda_fp16.h>
#include <math.h>
#include <stdint.h>

#define D 128
#define DD 16384
#define BATCH 16
#define NSEQ 1024
#define M_ROWS 16384
#define NE 32768
#define NS 6
#define NL 4

typedef unsigned long long u64;
typedef unsigned int u32;
typedef long long i64;
typedef __half f16;

// ---------------- scratch (fp32) ---------------------------------------------
__device__ __align__(256) float g_sc[(size_t)BATCH * NSEQ * NSEQ];
__device__ __align__(256) float g_T [M_ROWS * D];

// ---------------- scratch (fp16) -----------------------------------------------
__device__ __align__(256) f16 s_ctrs_h[M_ROWS*D];
__device__ __align__(256) f16 s_feat_h[M_ROWS*D];
__device__ __align__(256) f16 s_q_h[M_ROWS*D];
__device__ __align__(256) f16 s_k_h[M_ROWS*D];
__device__ __align__(256) f16 s_vt_h[M_ROWS*D];
__device__ __align__(256) f16 s_x_h[M_ROWS*D];
__device__ __align__(256) f16 s_y_h[M_ROWS*D];
__device__ __align__(256) f16 s_sc_h[(size_t)BATCH*NSEQ*NSEQ];
__device__ __align__(256) f16 s_wq_h[DD], s_wk_h[DD], s_wv_h[DD];
__device__ __align__(256) f16 s_wc_h[NL*DD];
__device__ __align__(256) f16 s_wp_h[NL*NS*DD];
__device__ __align__(256) f16 s_ws_h[NL*NS*DD];
__device__ __align__(256) f16 s_wl_h[NL*DD];
__device__ __align__(256) f16 s_wr_h[NL*DD];
__device__ __align__(256) f16 s_w2_h[NL*DD];

// ---------------- PTX helpers ------------------------------------------------
__device__ __forceinline__ u32 smem_u32(const void* p) {
    u32 a;
    asm("{ .reg .u64 t; cvta.to.shared.u64 t, %1; cvt.u32.u64 %0, t; }" : "=r"(a) : "l"(p));
    return a;
}
__device__ __forceinline__ void ldsm4(u32* r, u32 addr) {
    asm volatile("ldmatrix.sync.aligned.m8n8.x4.shared.b16 {%0,%1,%2,%3}, [%4];"
                 : "=r"(r[0]), "=r"(r[1]), "=r"(r[2]), "=r"(r[3]) : "r"(addr));
}
__device__ __forceinline__ void mma_f16(float* d, const u32* a, u32 b0, u32 b1) {
    asm volatile("mma.sync.aligned.m16n8k16.row.col.f32.f16.f16.f32 "
                 "{%0,%1,%2,%3}, {%4,%5,%6,%7}, {%8,%9}, {%0,%1,%2,%3};"
                 : "+f"(d[0]), "+f"(d[1]), "+f"(d[2]), "+f"(d[3])
                 : "r"(a[0]), "r"(a[1]), "r"(a[2]), "r"(a[3]), "r"(b0), "r"(b1));
}
__device__ __forceinline__ void red4(float* p, float a, float b, float c, float d) {
    asm volatile("red.global.add.v4.f32 [%0], {%1,%2,%3,%4};"
                 :: "l"(p), "f"(a), "f"(b), "f"(c), "f"(d) : "memory");
}
__device__ __forceinline__ void cp16_cg(u32 dst, const void* src) {
    asm volatile("cp.async.cg.shared.global [%0], [%1], 16;" :: "r"(dst), "l"(src));
}
__device__ __forceinline__ void cp16_ca(u32 dst, const void* src) {
    asm volatile("cp.async.ca.shared.global [%0], [%1], 16;" :: "r"(dst), "l"(src));
}
__device__ __forceinline__ void cp_commit() { asm volatile("cp.async.commit_group;" ::: "memory"); }
template<int N> __device__ __forceinline__ void cp_wait() {
    asm volatile("cp.async.wait_group %0;" :: "n"(N) : "memory");
}
__device__ __forceinline__ uint2 cvt4(float4 v) {
    __half2 h0 = __floats2half2_rn(v.x, v.y);
    __half2 h1 = __floats2half2_rn(v.z, v.w);
    return make_uint2(*(u32*)&h0, *(u32*)&h1);
}

// ---------------- generic GEMM core (dense paths) -------------------------------
template<bool RES, bool OF32, bool OF16, bool GN2>
__device__ __forceinline__ void gemm_core(
    const f16* __restrict__ Ah, int lda,
    const f16* __restrict__ Bh, int ldb,
    float* __restrict__ C, int ldc,
    f16* __restrict__ Ch,
    const float* __restrict__ Fres,
    const float* __restrict__ gw, const float* __restrict__ bw,
    int row0, int col0, float scale, int KT)
{
    extern __shared__ char sm[];
    const u32 sb = smem_u32(sm);
    const int tid = threadIdx.x;
    const int wid = tid >> 5, lane = tid & 31;
    const int m0w = (wid >> 1) * 32, n0w = (wid & 1) * 64;

    float acc[2][8][4];
    #pragma unroll
    for (int mi = 0; mi < 2; mi++)
        #pragma unroll
        for (int nj = 0; nj < 8; nj++)
            #pragma unroll
            for (int e = 0; e < 4; e++) acc[mi][nj][e] = 0.f;

    const u32 a_rb = (u32)(m0w + (lane & 15)) * 128;
    const u32 b_rb = (u32)(n0w + ((lane >> 4) << 3) + (lane & 7)) * 128;
    const int a_hi = lane >> 4;
    const int b_hi = (lane >> 3) & 1;
    const int xr = lane & 7;

    const int r_ld = tid >> 1;
    const int c0_ld = (tid & 1) * 4;
    const int H = 2 * KT;

    auto load_half = [&](int h, int s) {
        const int kofs = h * 64;
        const u32 base = sb + (u32)s * 32768u;
        const f16* ap = Ah + (i64)(row0 + r_ld) * lda + kofs;
        const f16* bp = Bh + (i64)(col0 + r_ld) * ldb + kofs;
        #pragma unroll
        for (int j = 0; j < 4; j++) {
            int c = c0_ld + j;
            u32 so = (u32)r_ld * 128 + (u32)((c ^ (r_ld & 7)) << 4);
            cp16_cg(base + so,          ap + c * 8);
            cp16_ca(base + 16384 + so,  bp + c * 8);
        }
        cp_commit();
    };

    load_half(0, 0);
    for (int h = 0; h < H; h++) {
        const int s = h & 1;
        const bool more = (h + 1 < H);
        if (more) { load_half(h + 1, 1 - s); cp_wait<1>(); }
        else      { cp_wait<0>(); }
        __syncthreads();
        const u32 base = sb + (u32)s * 32768u;
        const u32 abase = base + a_rb;
        const u32 bbase = base + 16384u + b_rb;
        #pragma unroll
        for (int ks = 0; ks < 4; ks++) {
            const u32 aoff = (u32)(((ks * 2 + a_hi) ^ xr) << 4);
            const u32 boff = (u32)(((ks * 2 + b_hi) ^ xr) << 4);
            u32 b[4][4], a0[4], a1[4];
            #pragma unroll
            for (int p = 0; p < 4; p++)
                ldsm4(b[p], bbase + boff + p * 2048);
            ldsm4(a0, abase + aoff);
            ldsm4(a1, abase + aoff + 2048);
            #pragma unroll
            for (int nj = 0; nj < 8; nj++) {
                u32 bb0 = b[nj >> 1][(nj & 1) * 2], bb1 = b[nj >> 1][(nj & 1) * 2 + 1];
                mma_f16(acc[0][nj], a0, bb0, bb1);
                mma_f16(acc[1][nj], a1, bb0, bb1);
            }
        }
        __syncthreads();
    }

    // ---- stage C to SMEM (pitch 132 floats), then output ----
    float* Cs = reinterpret_cast<float*>(sm);
    const int g = lane >> 2, q2 = (lane & 3) * 2;
    #pragma unroll
    for (int mi = 0; mi < 2; mi++)
        #pragma unroll
        for (int nj = 0; nj < 8; nj++) {
            int r = m0w + mi * 16 + g;
            int c = n0w + nj * 8 + q2;
            Cs[r * 132 + c]           = acc[mi][nj][0];
            Cs[r * 132 + c + 1]       = acc[mi][nj][1];
            Cs[(r + 8) * 132 + c]     = acc[mi][nj][2];
            Cs[(r + 8) * 132 + c + 1] = acc[mi][nj][3];
        }
    __syncthreads();

    const int rr = tid >> 1, hh = tid & 1;
    const float* srow = Cs + rr * 132 + hh * 64;
    if (GN2) {
        float s1 = 0.f, s2 = 0.f;
        #pragma unroll
        for (int j = 0; j < 16; j++) {
            float4 vv = *reinterpret_cast<const float4*>(srow + j * 4);
            s1 += vv.x + vv.y + vv.z + vv.w;
            s2 += vv.x * vv.x + vv.y * vv.y + vv.z * vv.z + vv.w * vv.w;
        }
        s1 += __shfl_xor_sync(0xffffffffu, s1, 1);
        s2 += __shfl_xor_sync(0xffffffffu, s2, 1);
        const float mu = s1 * (1.f / 128.f);
        const float var = s2 * (1.f / 128.f) - mu * mu;
        const float rstd = rsqrtf(var + 1e-5f);
        const i64 ro = (i64)(row0 + rr) * D + hh * 64;
        const float* fp = Fres + ro;
        float* p = C + ro;
        const float* gp = gw + hh * 64;
        const float* bp = bw + hh * 64;
        #pragma unroll
        for (int j = 0; j < 16; j++) {
            float4 vv = *reinterpret_cast<const float4*>(srow + j * 4);
            float4 g4 = *reinterpret_cast<const float4*>(gp + j * 4);
            float4 b4 = *reinterpret_cast<const float4*>(bp + j * 4);
            float4 f4 = *reinterpret_cast<const float4*>(fp + j * 4);
            vv.x = fmaxf((vv.x - mu) * rstd * g4.x + b4.x + f4.x, 0.f);
            vv.y = fmaxf((vv.y - mu) * rstd * g4.y + b4.y + f4.y, 0.f);
            vv.z = fmaxf((vv.z - mu) * rstd * g4.z + b4.z + f4.z, 0.f);
            vv.w = fmaxf((vv.w - mu) * rstd * g4.w + b4.w + f4.w, 0.f);
            *reinterpret_cast<float4*>(p + j * 4) = vv;
            *reinterpret_cast<uint2*>(Ch + ro + j * 4) = cvt4(vv);
        }
    } else {
        const i64 ro = (i64)(row0 + rr) * ldc + col0 + hh * 64;
        const float* fp = RES ? (Fres + ro) : (const float*)0;
        float* p = OF32 ? (C + ro) : (float*)0;
        #pragma unroll
        for (int j = 0; j < 16; j++) {
            float4 vv = *reinterpret_cast<const float4*>(srow + j * 4);
            vv.x *= scale; vv.y *= scale; vv.z *= scale; vv.w *= scale;
            if (RES) {
                float4 f = *reinterpret_cast<const float4*>(fp + j * 4);
                vv.x += f.x; vv.y += f.y; vv.z += f.z; vv.w += f.w;
            }
            if (OF32) *reinterpret_cast<float4*>(p + j * 4) = vv;
            if (OF16) *reinterpret_cast<uint2*>(Ch + ro + j * 4) = cvt4(vv);
        }
    }
}

template<bool RES, bool OF32, bool OF16, bool GN2>
__global__ __launch_bounds__(256, 2)
void gemm_k(const f16* Ah, int lda, i64 aZ,
            const f16* Bh, int ldb, i64 bZ,
            float* C, int ldc, i64 cZ,
            f16* Ch,
            const float* Fres, i64 fZ,
            const float* gw, const float* bw,
            float scale, int KT)
{
    const int z = blockIdx.z;
    const int row0 = blockIdx.x * 128, col0 = blockIdx.y * 128;
    gemm_core<RES, OF32, OF16, GN2>(
        Ah + (i64)z * aZ, lda,
        Bh + (i64)z * bZ, ldb,
        C + (i64)z * cZ, ldc,
        (OF16 || GN2) ? Ch + (i64)z * cZ : (f16*)0,
        (RES || GN2) ? Fres + (i64)z * fZ : (const float*)0,
        gw, bw, row0, col0, scale, KT);
}

// ---------------- fused QKV kernel (z=0:Q, z=1:K, z=2:V->transposed) ------------
__global__ __launch_bounds__(256, 2)
void qkv_k(const f16* __restrict__ ctrs_h, const f16* __restrict__ feat_h,
           const f16* __restrict__ wq, const f16* __restrict__ wk, const f16* __restrict__ wv,
           f16* __restrict__ q_h, f16* __restrict__ k_h, f16* __restrict__ vt_h)
{
    extern __shared__ char sm[];
    const u32 sb = smem_u32(sm);
    const int z = blockIdx.z;
    const int row0 = blockIdx.x * 128;
    const f16* Ah = (z == 0) ? ctrs_h : feat_h;
    const f16* Bh = (z == 0) ? wq : (z == 1) ? wk : wv;

    const int tid = threadIdx.x;
    const int wid = tid >> 5, lane = tid & 31;
    const int m0w = (wid >> 1) * 32, n0w = (wid & 1) * 64;

    float acc[2][8][4];
    #pragma unroll
    for (int mi = 0; mi < 2; mi++)
        #pragma unroll
        for (int nj = 0; nj < 8; nj++)
            #pragma unroll
            for (int e = 0; e < 4; e++) acc[mi][nj][e] = 0.f;

    const u32 a_rb = (u32)(m0w + (lane & 15)) * 128;
    const u32 b_rb = (u32)(n0w + ((lane >> 4) << 3) + (lane & 7)) * 128;
    const int a_hi = lane >> 4;
    const int b_hi = (lane >> 3) & 1;
    const int xr = lane & 7;
    const int r_ld = tid >> 1;
    const int c0_ld = (tid & 1) * 4;

    auto load_half = [&](int h, int s) {
        const int kofs = h * 64;
        const u32 base = sb + (u32)s * 32768u;
        const f16* ap = Ah + (i64)(row0 + r_ld) * D + kofs;
        const f16* bp = Bh + (i64)r_ld * D + kofs;
        #pragma unroll
        for (int j = 0; j < 4; j++) {
            int c = c0_ld + j;
            u32 so = (u32)r_ld * 128 + (u32)((c ^ (r_ld & 7)) << 4);
            cp16_cg(base + so,          ap + c * 8);
            cp16_ca(base + 16384 + so,  bp + c * 8);
        }
        cp_commit();
    };

    load_half(0, 0);
    for (int h = 0; h < 2; h++) {
        if (h == 0) { load_half(1, 1); cp_wait<1>(); }
        else        { cp_wait<0>(); }
        __syncthreads();
        const u32 base = sb + (u32)(h & 1) * 32768u;
        const u32 abase = base + a_rb;
        const u32 bbase = base + 16384u + b_rb;
        #pragma unroll
        for (int ks = 0; ks < 4; ks++) {
            const u32 aoff = (u32)(((ks * 2 + a_hi) ^ xr) << 4);
            const u32 boff = (u32)(((ks * 2 + b_hi) ^ xr) << 4);
            u32 b[4][4], a0[4], a1[4];
            #pragma unroll
            for (int p = 0; p < 4; p++)
                ldsm4(b[p], bbase + boff + p * 2048);
            ldsm4(a0, abase + aoff);
            ldsm4(a1, abase + aoff + 2048);
            #pragma unroll
            for (int nj = 0; nj < 8; nj++) {
                u32 bb0 = b[nj >> 1][(nj & 1) * 2], bb1 = b[nj >> 1][(nj & 1) * 2 + 1];
                mma_f16(acc[0][nj], a0, bb0, bb1);
                mma_f16(acc[1][nj], a1, bb0, bb1);
            }
        }
        __syncthreads();
    }

    float* Cs = reinterpret_cast<float*>(sm);
    const int g = lane >> 2, q2 = (lane & 3) * 2;
    #pragma unroll
    for (int mi = 0; mi < 2; mi++)
        #pragma unroll
        for (int nj = 0; nj < 8; nj++) {
            int r = m0w + mi * 16 + g;
            int c = n0w + nj * 8 + q2;
            Cs[r * 132 + c]           = acc[mi][nj][0];
            Cs[r * 132 + c + 1]       = acc[mi][nj][1];
            Cs[(r + 8) * 132 + c]     = acc[mi][nj][2];
            Cs[(r + 8) * 132 + c + 1] = acc[mi][nj][3];
        }
    __syncthreads();

    if (z < 2) {
        f16* out = (z == 0) ? q_h : k_h;
        const int rr = tid >> 1, hh = tid & 1;
        const float* srow = Cs + rr * 132 + hh * 64;
        const i64 ro = (i64)(row0 + rr) * D + hh * 64;
        #pragma unroll
        for (int j = 0; j < 16; j++) {
            float4 vv = *reinterpret_cast<const float4*>(srow + j * 4);
            *reinterpret_cast<uint2*>(out + ro + j * 4) = cvt4(vv);
        }
    } else {
        // transposed fp16 store: vt[b][d][j] = C[j][d]
        const int d = tid >> 1, hh = tid & 1;
        const int jg0 = row0 + hh * 64;
        const int b = jg0 >> 10, jin = jg0 & 1023;
        f16* dst = vt_h + (i64)b * D * NSEQ + (i64)d * NSEQ + jin;
        #pragma unroll
        for (int j = 0; j < 64; j += 2) {
            float a0 = Cs[(hh * 64 + j) * 132 + d];
            float a1 = Cs[(hh * 64 + j + 1) * 132 + d];
            __half2 hv = __floats2half2_rn(a0, a1);
            *reinterpret_cast<u32*>(dst + j) = *(u32*)&hv;
        }
    }
}

// ---------------- persistent-B scatter kernel -----------------------------------
#define NTILES_SC 3584
#define CHUNK_SC 12
#define GRID_SC ((NTILES_SC + CHUNK_SC - 1) / CHUNK_SC)   // 299

__global__ __launch_bounds__(256, 2)
void layer_scatter_p(const f16* __restrict__ Xh,
                     const f16* __restrict__ wph, const f16* __restrict__ wsh,
                     const f16* __restrict__ wlh, const f16* __restrict__ wrh,
                     float* __restrict__ T,
                     const int* __restrict__ pre_u, const int* __restrict__ pre_v,
                     const int* __restrict__ suc_u, const int* __restrict__ suc_v,
                     const int* __restrict__ left_u, const int* __restrict__ left_v,
                     const int* __restrict__ right_u, const int* __restrict__ right_v)
{
    extern __shared__ char sm[];
    const u32 sb = smem_u32(sm);
    const int t0 = blockIdx.x * CHUNK_SC;
    const int t1 = (t0 + CHUNK_SC < NTILES_SC) ? t0 + CHUNK_SC : NTILES_SC;
    if (t0 >= NTILES_SC) return;

    const int tid = threadIdx.x;
    const int wid = tid >> 5, lane = tid & 31;
    const int m0w = (wid >> 1) * 32, n0w = (wid & 1) * 64;
    const u32 a_rb = (u32)(m0w + (lane & 15)) * 128;
    const u32 b_rb = (u32)(n0w + ((lane >> 4) << 3) + (lane & 7)) * 128;
    const int a_hi = lane >> 4;
    const int b_hi = (lane >> 3) & 1;
    const int xr = lane & 7;
    const int r_ld = tid >> 1;
    const int c0_ld = (tid & 1) * 4;

    auto group_of = [&](int t, const f16*& Bw, const int*& gv, const int*& su) {
        int g = t >> 8, e = (t & 255) * 128;
        if (g < 6)        { Bw = wph + (i64)g * DD;       gv = pre_v + g * NE + e;        su = pre_u + g * NE + e; }
        else if (g < 12)  { int z = g - 6; Bw = wsh + (i64)z * DD; gv = suc_v + z * NE + e; su = suc_u + z * NE + e; }
        else if (g == 12) { Bw = wlh;                     gv = left_v + e;                 su = left_u + e; }
        else              { Bw = wrh;                     gv = right_v + e;                su = right_u + e; }
    };

    auto load_B = [&](const f16* Bw) {
        const f16* bp = Bw + (i64)r_ld * D;
        #pragma unroll
        for (int h = 0; h < 2; h++) {
            const u32 base = sb + 32768u + (u32)h * 16384u;
            #pragma unroll
            for (int j = 0; j < 4; j++) {
                int c = c0_ld + j;
                u32 so = (u32)r_ld * 128 + (u32)((c ^ (r_ld & 7)) << 4);
                cp16_ca(base + so, bp + h * 64 + c * 8);
            }
        }
        cp_commit();
    };
    auto load_A = [&](const int* gv, int h, int s) {
        i64 arow = (i64)__ldg(gv + r_ld);
        const f16* ap = Xh + arow * D + h * 64;
        const u32 base = sb + (u32)s * 16384u;
        #pragma unroll
        for (int j = 0; j < 4; j++) {
            int c = c0_ld + j;
            u32 so = (u32)r_ld * 128 + (u32)((c ^ (r_ld & 7)) << 4);
            cp16_cg(base + so, ap + c * 8);
        }
        cp_commit();
    };

    const int g = lane >> 2;
    const int q = lane & 3;
    const int cb = n0w + ((q >> 1) << 2);   // q 0,1 -> +0 ; q 2,3 -> +4
    const bool evenlane = ((lane & 1) == 0);
    const f16* Bw; const int* gv; const int* su;
    group_of(t0, Bw, gv, su);
    int curg = t0 >> 8;
    load_B(Bw);
    load_A(gv, 0, 0);
    load_A(gv, 1, 1);

    for (int t = t0; t < t1; t++) {
        const f16* Bw_n = 0; const int* gv_n = 0; const int* su_n = 0;
        const bool have_next = (t + 1 < t1);
        int g_n = curg;
        if (have_next) { group_of(t + 1, Bw_n, gv_n, su_n); g_n = (t + 1) >> 8; }
        const bool pref0 = have_next && (g_n == curg);

        float acc[2][8][4];
        #pragma unroll
        for (int mi = 0; mi < 2; mi++)
            #pragma unroll
            for (int nj = 0; nj < 8; nj++)
                #pragma unroll
                for (int e = 0; e < 4; e++) acc[mi][nj][e] = 0.f;

        // half 0
        cp_wait<1>(); __syncthreads();
        {
            const u32 abase = sb + a_rb;
            const u32 bbase = sb + 32768u + b_rb;
            #pragma unroll
            for (int ks = 0; ks < 4; ks++) {
                const u32 aoff = (u32)(((ks * 2 + a_hi) ^ xr) << 4);
                const u32 boff = (u32)(((ks * 2 + b_hi) ^ xr) << 4);
                u32 b[4][4], a0[4], a1[4];
                #pragma unroll
                for (int p = 0; p < 4; p++)
                    ldsm4(b[p], bbase + boff + p * 2048);
                ldsm4(a0, abase + aoff);
                ldsm4(a1, abase + aoff + 2048);
                #pragma unroll
                for (int nj = 0; nj < 8; nj++) {
                    u32 bb0 = b[nj >> 1][(nj & 1) * 2], bb1 = b[nj >> 1][(nj & 1) * 2 + 1];
                    mma_f16(acc[0][nj], a0, bb0, bb1);
                    mma_f16(acc[1][nj], a1, bb0, bb1);
                }
            }
        }
        __syncthreads();
        if (pref0) load_A(gv_n, 0, 0);

        // half 1
        if (pref0) cp_wait<1>(); else cp_wait<0>();
        __syncthreads();
        {
            const u32 abase = sb + 16384u + a_rb;
            const u32 bbase = sb + 49152u + b_rb;
            #pragma unroll
            for (int ks = 0; ks < 4; ks++) {
                const u32 aoff = (u32)(((ks * 2 + a_hi) ^ xr) << 4);
                const u32 boff = (u32)(((ks * 2 + b_hi) ^ xr) << 4);
                u32 b[4][4], a0[4], a1[4];
                #pragma unroll
                for (int p = 0; p < 4; p++)
                    ldsm4(b[p], bbase + boff + p * 2048);
                ldsm4(a0, abase + aoff);
                ldsm4(a1, abase + aoff + 2048);
                #pragma unroll
                for (int nj = 0; nj < 8; nj++) {
                    u32 bb0 = b[nj >> 1][(nj & 1) * 2], bb1 = b[nj >> 1][(nj & 1) * 2 + 1];
                    mma_f16(acc[0][nj], a0, bb0, bb1);
                    mma_f16(acc[1][nj], a1, bb0, bb1);
                }
            }
        }

        // epilogue: lane-pair shfl -> red.v4 (even lane: row r, odd lane: row r+8)
        #pragma unroll
        for (int mi = 0; mi < 2; mi++) {
            i64 dr1 = (i64)__ldg(su + m0w + mi * 16 + g);
            i64 dr2 = (i64)__ldg(su + m0w + mi * 16 + g + 8);
            float* pr = evenlane ? (T + dr1 * D) : (T + dr2 * D);
            #pragma unroll
            for (int nj = 0; nj < 8; nj++) {
                float v0 = acc[mi][nj][0], v1 = acc[mi][nj][1];
                float v2 = acc[mi][nj][2], v3 = acc[mi][nj][3];
                float p0 = __shfl_xor_sync(0xffffffffu, v0, 1);
                float p1 = __shfl_xor_sync(0xffffffffu, v1, 1);
                float p2 = __shfl_xor_sync(0xffffffffu, v2, 1);
                float p3 = __shfl_xor_sync(0xffffffffu, v3, 1);
                if (evenlane) red4(pr + cb + nj * 8, v0, v1, p0, p1);
                else          red4(pr + cb + nj * 8, p2, p3, v2, v3);
            }
        }
        __syncthreads();

        if (have_next) {
            if (g_n == curg) {
                load_A(gv_n, 1, 1);
            } else {
                cp_wait<0>(); __syncthreads();
                load_B(Bw_n);
                load_A(gv_n, 0, 0);
                load_A(gv_n, 1, 1);
                curg = g_n;
            }
            gv = gv_n; su = su_n;
        }
    }
}

// ---------------- fused conversion kernel ----------------------------------------
#define NSEG 11
struct CvtArgs {
    const float4* src[NSEG];
    uint2* dst[NSEG];
    int n4[NSEG];
};
__global__ __launch_bounds__(256)
void cvt_all(CvtArgs a)
{
    const int seg = blockIdx.y;
    const int i = blockIdx.x * 256 + threadIdx.x;
    if (i < a.n4[seg]) a.dst[seg][i] = cvt4(a.src[seg][i]);
}

// row softmax over 1024, emit fp16
__global__ __launch_bounds__(256)
void softmax_k(const float* __restrict__ Sc, f16* __restrict__ oh)
{
    i64 row = blockIdx.x;
    const float4* p = reinterpret_cast<const float4*>(Sc + row * NSEQ);
    int t = threadIdx.x;
    float4 v = p[t];
    float mx = fmaxf(fmaxf(v.x, v.y), fmaxf(v.z, v.w));
    #pragma unroll
    for (int o = 16; o; o >>= 1) mx = fmaxf(mx, __shfl_xor_sync(0xffffffffu, mx, o));
    __shared__ float red8[8];
    int w = t >> 5;
    if ((t & 31) == 0) red8[w] = mx;
    __syncthreads();
    mx = red8[0];
    #pragma unroll
    for (int i = 1; i < 8; i++) mx = fmaxf(mx, red8[i]);
    v.x = expf(v.x - mx); v.y = expf(v.y - mx);
    v.z = expf(v.z - mx); v.w = expf(v.w - mx);
    float s = v.x + v.y + v.z + v.w;
    #pragma unroll
    for (int o = 16; o; o >>= 1) s += __shfl_xor_sync(0xffffffffu, s, o);
    __syncthreads();
    if ((t & 31) == 0) red8[w] = s;
    __syncthreads();
    s = red8[0] + red8[1] + red8[2] + red8[3] + red8[4] + red8[5] + red8[6] + red8[7];
    float inv = 1.0f / s;
    v.x *= inv; v.y *= inv; v.z *= inv; v.w *= inv;
    *reinterpret_cast<uint2*>(oh + row * NSEQ + t * 4) = cvt4(v);
}

// group norm (gn1): relu, emit fp16 only
__global__ __launch_bounds__(128)
void gn1_kernel(const float* __restrict__ in, f16* __restrict__ outh,
                const float* __restrict__ gw, const float* __restrict__ bw)
{
    const i64 row = blockIdx.x;
    const int t = threadIdx.x;
    float v = in[row * D + t];
    float s1 = v, s2 = v * v;
    #pragma unroll
    for (int o = 16; o; o >>= 1) {
        s1 += __shfl_xor_sync(0xffffffffu, s1, o);
        s2 += __shfl_xor_sync(0xffffffffu, s2, o);
    }
    __shared__ float a1[4], a2[4];
    int w = t >> 5;
    if ((t & 31) == 0) { a1[w] = s1; a2[w] = s2; }
    __syncthreads();
    s1 = a1[0] + a1[1] + a1[2] + a1[3];
    s2 = a2[0] + a2[1] + a2[2] + a2[3];
    float mu = s1 * (1.0f / D);
    float var = s2 * (1.0f / D) - mu * mu;
    float y = fmaxf((v - mu) * rsqrtf(var + 1e-5f) * gw[t] + bw[t], 0.f);
    outh[row * D + t] = __float2half(y);
}

// ---------------- driver ---------------------------------------------------------
#define SMEM_SZ 67584   // dense path: 2x32KB operand stages / epilogue staging
#define SMEM_SC 65536   // persistent scatter: 2x16KB A + 32KB B

extern "C" void kernel_launch(void* const* d_in, const int* in_sizes, int n_in,
                              void* d_out, int out_size)
{
    (void)in_sizes; (void)n_in; (void)out_size;
    const float* ctrs   = (const float*)d_in[0];
    const float* feats  = (const float*)d_in[1];
    const float* Wq     = (const float*)d_in[2];
    const float* Wk     = (const float*)d_in[3];
    const float* Wv     = (const float*)d_in[4];
    const float* Wc     = (const float*)d_in[5];
    const float* Wp     = (const float*)d_in[6];
    const float* Ws     = (const float*)d_in[7];
    const float* Wl     = (const float*)d_in[8];
    const float* Wr     = (const float*)d_in[9];
    const float* Wc2    = (const float*)d_in[10];
    const float* g1     = (const float*)d_in[11];
    const float* b1     = (const float*)d_in[12];
    const float* g2     = (const float*)d_in[13];
    const float* b2     = (const float*)d_in[14];
    const int* pre_u    = (const int*)d_in[15];
    const int* pre_v    = (const int*)d_in[16];
    const int* suc_u    = (const int*)d_in[17];
    const int* suc_v    = (const int*)d_in[18];
    const int* left_u   = (const int*)d_in[19];
    const int* left_v   = (const int*)d_in[20];
    const int* right_u  = (const int*)d_in[21];
    const int* right_v  = (const int*)d_in[22];
    float* X = (float*)d_out;

    float *sc, *T;
    cudaGetSymbolAddress((void**)&sc, g_sc);
    cudaGetSymbolAddress((void**)&T,  g_T);
    f16 *ctrs_h, *feat_h, *q_h, *k_h, *vt_h, *x_h, *y_h, *sc_h;
    f16 *wq_h, *wk_h, *wv_h, *wc_h, *wp_h, *ws_h, *wl_h, *wr_h, *w2_h;
    cudaGetSymbolAddress((void**)&ctrs_h, s_ctrs_h);
    cudaGetSymbolAddress((void**)&feat_h, s_feat_h);
    cudaGetSymbolAddress((void**)&q_h, s_q_h);
    cudaGetSymbolAddress((void**)&k_h, s_k_h);
    cudaGetSymbolAddress((void**)&vt_h, s_vt_h);
    cudaGetSymbolAddress((void**)&x_h, s_x_h);
    cudaGetSymbolAddress((void**)&y_h, s_y_h);
    cudaGetSymbolAddress((void**)&sc_h, s_sc_h);
    cudaGetSymbolAddress((void**)&wq_h, s_wq_h);
    cudaGetSymbolAddress((void**)&wk_h, s_wk_h);
    cudaGetSymbolAddress((void**)&wv_h, s_wv_h);
    cudaGetSymbolAddress((void**)&wc_h, s_wc_h);
    cudaGetSymbolAddress((void**)&wp_h, s_wp_h);
    cudaGetSymbolAddress((void**)&ws_h, s_ws_h);
    cudaGetSymbolAddress((void**)&wl_h, s_wl_h);
    cudaGetSymbolAddress((void**)&wr_h, s_wr_h);
    cudaGetSymbolAddress((void**)&w2_h, s_w2_h);

    cudaFuncSetAttribute((const void*)gemm_k<false,true ,false,false>, cudaFuncAttributeMaxDynamicSharedMemorySize, SMEM_SZ);
    cudaFuncSetAttribute((const void*)gemm_k<true ,true ,true ,false>, cudaFuncAttributeMaxDynamicSharedMemorySize, SMEM_SZ);
    cudaFuncSetAttribute((const void*)gemm_k<false,false,false,true >, cudaFuncAttributeMaxDynamicSharedMemorySize, SMEM_SZ);
    cudaFuncSetAttribute((const void*)qkv_k, cudaFuncAttributeMaxDynamicSharedMemorySize, SMEM_SZ);
    cudaFuncSetAttribute((const void*)layer_scatter_p, cudaFuncAttributeMaxDynamicSharedMemorySize, SMEM_SC);

    const float NF = 0.08838834764831845f;  // 1/sqrt(128)
    dim3 blk(256);

    // ---- one fused conversion launch ----
    CvtArgs ca;
    const float* srcs[NSEG] = {ctrs, feats, Wq, Wk, Wv, Wc, Wp, Ws, Wl, Wr, Wc2};
    f16* dsts[NSEG] = {ctrs_h, feat_h, wq_h, wk_h, wv_h, wc_h, wp_h, ws_h, wl_h, wr_h, w2_h};
    const int ns[NSEG] = {M_ROWS*D, M_ROWS*D, DD, DD, DD, NL*DD, NL*NS*DD, NL*NS*DD, NL*DD, NL*DD, NL*DD};
    int maxn4 = 0;
    for (int i = 0; i < NSEG; i++) {
        ca.src[i] = (const float4*)srcs[i];
        ca.dst[i] = (uint2*)dsts[i];
        ca.n4[i] = ns[i] / 4;
        if (ca.n4[i] > maxn4) maxn4 = ca.n4[i];
    }
    cvt_all<<<dim3((maxn4 + 255) / 256, NSEG), 256>>>(ca);

    // ---- attention ----
    qkv_k<<<dim3(128, 1, 3), blk, SMEM_SZ>>>(ctrs_h, feat_h, wq_h, wk_h, wv_h, q_h, k_h, vt_h);
    gemm_k<false,true,false,false><<<dim3(8,8,16), blk, SMEM_SZ>>>(
        q_h, D, (i64)NSEQ*D, k_h, D, (i64)NSEQ*D,
        sc, NSEQ, (i64)NSEQ*NSEQ, 0, 0, 0, 0, 0, NF, 1);
    softmax_k<<<M_ROWS, 256>>>(sc, sc_h);
    gemm_k<true,true,true,false><<<dim3(8,1,16), blk, SMEM_SZ>>>(
        sc_h, NSEQ, (i64)NSEQ*NSEQ, vt_h, NSEQ, (i64)D*NSEQ,
        X, D, (i64)NSEQ*D, x_h, feats, (i64)NSEQ*D, 0, 0, 1.f, 8);

    // ---- 4-layer fusion loop ----
    for (int i = 0; i < NL; i++) {
        // ctr GEMM: plain store initializes T
        gemm_k<false,true,false,false><<<dim3(128,1,1), blk, SMEM_SZ>>>(
            x_h, D, 0, wc_h + (i64)i*DD, D, 0,
            T, D, 0, 0, 0, 0, 0, 0, 1.f, 1);
        // persistent-B edge scatter: red.v4 adds into T
        layer_scatter_p<<<GRID_SC, blk, SMEM_SC>>>(
            x_h,
            wp_h + (i64)i*NS*DD,
            ws_h + (i64)i*NS*DD,
            wl_h + (i64)i*DD,
            wr_h + (i64)i*DD,
            T, pre_u, pre_v, suc_u, suc_v, left_u, left_v, right_u, right_v);
        // gn1 + relu -> y_h (fp16)
        gn1_kernel<<<M_ROWS, 128>>>(T, y_h, g1 + i*D, b1 + i*D);
        // ctr2 GEMM with fused gn2 + residual + relu epilogue -> X (fp32) + x_h (fp16)
        gemm_k<false,false,false,true><<<dim3(128,1,1), blk, SMEM_SZ>>>(
            y_h, D, 0, w2_h + (i64)i*DD, D, 0,
            X, D, 0, x_h, X, 0, g2 + i*D, b2 + i*D, 1.f, 1);
    }
}

// round 11
// speedup vs baseline: 2.1829x; 1.0511x over previous
#include <cuda_runtime.h>
#include <cuda_fp16.h>
#include <math.h>
#include <stdint.h>

#define D 128
#define DD 16384
#define BATCH 16
#define NSEQ 1024
#define M_ROWS 16384
#define NE 32768
#define NS 6
#define NL 4

typedef unsigned long long u64;
typedef unsigned int u32;
typedef long long i64;
typedef __half f16;

// ---------------- scratch (fp32) ---------------------------------------------
__device__ __align__(256) float g_sc[(size_t)BATCH * NSEQ * NSEQ];
__device__ __align__(256) float g_T [M_ROWS * D];

// ---------------- scratch (fp16) -----------------------------------------------
__device__ __align__(256) f16 s_ctrs_h[M_ROWS*D];
__device__ __align__(256) f16 s_feat_h[M_ROWS*D];
__device__ __align__(256) f16 s_q_h[M_ROWS*D];
__device__ __align__(256) f16 s_k_h[M_ROWS*D];
__device__ __align__(256) f16 s_vt_h[M_ROWS*D];
__device__ __align__(256) f16 s_x_h[M_ROWS*D];
__device__ __align__(256) f16 s_y_h[M_ROWS*D];
__device__ __align__(256) f16 s_sc_h[(size_t)BATCH*NSEQ*NSEQ];
__device__ __align__(256) f16 s_wq_h[DD], s_wk_h[DD], s_wv_h[DD];
__device__ __align__(256) f16 s_wc_h[NL*DD];
__device__ __align__(256) f16 s_wp_h[NL*NS*DD];
__device__ __align__(256) f16 s_ws_h[NL*NS*DD];
__device__ __align__(256) f16 s_wl_h[NL*DD];
__device__ __align__(256) f16 s_wr_h[NL*DD];
__device__ __align__(256) f16 s_w2_h[NL*DD];

// ---------------- PTX helpers ------------------------------------------------
__device__ __forceinline__ u32 smem_u32(const void* p) {
    u32 a;
    asm("{ .reg .u64 t; cvta.to.shared.u64 t, %1; cvt.u32.u64 %0, t; }" : "=r"(a) : "l"(p));
    return a;
}
__device__ __forceinline__ void ldsm4(u32* r, u32 addr) {
    asm volatile("ldmatrix.sync.aligned.m8n8.x4.shared.b16 {%0,%1,%2,%3}, [%4];"
                 : "=r"(r[0]), "=r"(r[1]), "=r"(r[2]), "=r"(r[3]) : "r"(addr));
}
__device__ __forceinline__ void mma_f16(float* d, const u32* a, u32 b0, u32 b1) {
    asm volatile("mma.sync.aligned.m16n8k16.row.col.f32.f16.f16.f32 "
                 "{%0,%1,%2,%3}, {%4,%5,%6,%7}, {%8,%9}, {%0,%1,%2,%3};"
                 : "+f"(d[0]), "+f"(d[1]), "+f"(d[2]), "+f"(d[3])
                 : "r"(a[0]), "r"(a[1]), "r"(a[2]), "r"(a[3]), "r"(b0), "r"(b1));
}
__device__ __forceinline__ void red4(float* p, float a, float b, float c, float d) {
    asm volatile("red.global.add.v4.f32 [%0], {%1,%2,%3,%4};"
                 :: "l"(p), "f"(a), "f"(b), "f"(c), "f"(d) : "memory");
}
__device__ __forceinline__ void cp16_cg(u32 dst, const void* src) {
    asm volatile("cp.async.cg.shared.global [%0], [%1], 16;" :: "r"(dst), "l"(src));
}
__device__ __forceinline__ void cp16_ca(u32 dst, const void* src) {
    asm volatile("cp.async.ca.shared.global [%0], [%1], 16;" :: "r"(dst), "l"(src));
}
__device__ __forceinline__ void cp_commit() { asm volatile("cp.async.commit_group;" ::: "memory"); }
template<int N> __device__ __forceinline__ void cp_wait() {
    asm volatile("cp.async.wait_group %0;" :: "n"(N) : "memory");
}
__device__ __forceinline__ uint2 cvt4(float4 v) {
    __half2 h0 = __floats2half2_rn(v.x, v.y);
    __half2 h1 = __floats2half2_rn(v.z, v.w);
    return make_uint2(*(u32*)&h0, *(u32*)&h1);
}

// ---------------- generic GEMM core (dense paths) -------------------------------
template<bool RES, bool OF32, bool OF16, bool GN2>
__device__ __forceinline__ void gemm_core(
    const f16* __restrict__ Ah, int lda,
    const f16* __restrict__ Bh, int ldb,
    float* __restrict__ C, int ldc,
    f16* __restrict__ Ch,
    const float* __restrict__ Fres,
    const float* __restrict__ gw, const float* __restrict__ bw,
    int row0, int col0, float scale, int KT)
{
    extern __shared__ char sm[];
    const u32 sb = smem_u32(sm);
    const int tid = threadIdx.x;
    const int wid = tid >> 5, lane = tid & 31;
    const int m0w = (wid >> 1) * 32, n0w = (wid & 1) * 64;

    float acc[2][8][4];
    #pragma unroll
    for (int mi = 0; mi < 2; mi++)
        #pragma unroll
        for (int nj = 0; nj < 8; nj++)
            #pragma unroll
            for (int e = 0; e < 4; e++) acc[mi][nj][e] = 0.f;

    const u32 a_rb = (u32)(m0w + (lane & 15)) * 128;
    const u32 b_rb = (u32)(n0w + ((lane >> 4) << 3) + (lane & 7)) * 128;
    const int a_hi = lane >> 4;
    const int b_hi = (lane >> 3) & 1;
    const int xr = lane & 7;

    const int r_ld = tid >> 1;
    const int c0_ld = (tid & 1) * 4;
    const int H = 2 * KT;

    auto load_half = [&](int h, int s) {
        const int kofs = h * 64;
        const u32 base = sb + (u32)s * 32768u;
        const f16* ap = Ah + (i64)(row0 + r_ld) * lda + kofs;
        const f16* bp = Bh + (i64)(col0 + r_ld) * ldb + kofs;
        #pragma unroll
        for (int j = 0; j < 4; j++) {
            int c = c0_ld + j;
            u32 so = (u32)r_ld * 128 + (u32)((c ^ (r_ld & 7)) << 4);
            cp16_cg(base + so,          ap + c * 8);
            cp16_ca(base + 16384 + so,  bp + c * 8);
        }
        cp_commit();
    };

    load_half(0, 0);
    for (int h = 0; h < H; h++) {
        const int s = h & 1;
        const bool more = (h + 1 < H);
        if (more) { load_half(h + 1, 1 - s); cp_wait<1>(); }
        else      { cp_wait<0>(); }
        __syncthreads();
        const u32 base = sb + (u32)s * 32768u;
        const u32 abase = base + a_rb;
        const u32 bbase = base + 16384u + b_rb;
        #pragma unroll
        for (int ks = 0; ks < 4; ks++) {
            const u32 aoff = (u32)(((ks * 2 + a_hi) ^ xr) << 4);
            const u32 boff = (u32)(((ks * 2 + b_hi) ^ xr) << 4);
            u32 b[4][4], a0[4], a1[4];
            #pragma unroll
            for (int p = 0; p < 4; p++)
                ldsm4(b[p], bbase + boff + p * 2048);
            ldsm4(a0, abase + aoff);
            ldsm4(a1, abase + aoff + 2048);
            #pragma unroll
            for (int nj = 0; nj < 8; nj++) {
                u32 bb0 = b[nj >> 1][(nj & 1) * 2], bb1 = b[nj >> 1][(nj & 1) * 2 + 1];
                mma_f16(acc[0][nj], a0, bb0, bb1);
                mma_f16(acc[1][nj], a1, bb0, bb1);
            }
        }
        __syncthreads();
    }

    // ---- stage C to SMEM (pitch 132 floats), then output ----
    float* Cs = reinterpret_cast<float*>(sm);
    const int g = lane >> 2, q2 = (lane & 3) * 2;
    #pragma unroll
    for (int mi = 0; mi < 2; mi++)
        #pragma unroll
        for (int nj = 0; nj < 8; nj++) {
            int r = m0w + mi * 16 + g;
            int c = n0w + nj * 8 + q2;
            Cs[r * 132 + c]           = acc[mi][nj][0];
            Cs[r * 132 + c + 1]       = acc[mi][nj][1];
            Cs[(r + 8) * 132 + c]     = acc[mi][nj][2];
            Cs[(r + 8) * 132 + c + 1] = acc[mi][nj][3];
        }
    __syncthreads();

    const int rr = tid >> 1, hh = tid & 1;
    const float* srow = Cs + rr * 132 + hh * 64;
    if (GN2) {
        float s1 = 0.f, s2 = 0.f;
        #pragma unroll
        for (int j = 0; j < 16; j++) {
            float4 vv = *reinterpret_cast<const float4*>(srow + j * 4);
            s1 += vv.x + vv.y + vv.z + vv.w;
            s2 += vv.x * vv.x + vv.y * vv.y + vv.z * vv.z + vv.w * vv.w;
        }
        s1 += __shfl_xor_sync(0xffffffffu, s1, 1);
        s2 += __shfl_xor_sync(0xffffffffu, s2, 1);
        const float mu = s1 * (1.f / 128.f);
        const float var = s2 * (1.f / 128.f) - mu * mu;
        const float rstd = rsqrtf(var + 1e-5f);
        const i64 ro = (i64)(row0 + rr) * D + hh * 64;
        const float* fp = Fres + ro;
        float* p = C + ro;
        const float* gp = gw + hh * 64;
        const float* bp = bw + hh * 64;
        #pragma unroll
        for (int j = 0; j < 16; j++) {
            float4 vv = *reinterpret_cast<const float4*>(srow + j * 4);
            float4 g4 = *reinterpret_cast<const float4*>(gp + j * 4);
            float4 b4 = *reinterpret_cast<const float4*>(bp + j * 4);
            float4 f4 = *reinterpret_cast<const float4*>(fp + j * 4);
            vv.x = fmaxf((vv.x - mu) * rstd * g4.x + b4.x + f4.x, 0.f);
            vv.y = fmaxf((vv.y - mu) * rstd * g4.y + b4.y + f4.y, 0.f);
            vv.z = fmaxf((vv.z - mu) * rstd * g4.z + b4.z + f4.z, 0.f);
            vv.w = fmaxf((vv.w - mu) * rstd * g4.w + b4.w + f4.w, 0.f);
            *reinterpret_cast<float4*>(p + j * 4) = vv;
            *reinterpret_cast<uint2*>(Ch + ro + j * 4) = cvt4(vv);
        }
    } else {
        const i64 ro = (i64)(row0 + rr) * ldc + col0 + hh * 64;
        const float* fp = RES ? (Fres + ro) : (const float*)0;
        float* p = OF32 ? (C + ro) : (float*)0;
        #pragma unroll
        for (int j = 0; j < 16; j++) {
            float4 vv = *reinterpret_cast<const float4*>(srow + j * 4);
            vv.x *= scale; vv.y *= scale; vv.z *= scale; vv.w *= scale;
            if (RES) {
                float4 f = *reinterpret_cast<const float4*>(fp + j * 4);
                vv.x += f.x; vv.y += f.y; vv.z += f.z; vv.w += f.w;
            }
            if (OF32) *reinterpret_cast<float4*>(p + j * 4) = vv;
            if (OF16) *reinterpret_cast<uint2*>(Ch + ro + j * 4) = cvt4(vv);
        }
    }
}

template<bool RES, bool OF32, bool OF16, bool GN2>
__global__ __launch_bounds__(256, 2)
void gemm_k(const f16* Ah, int lda, i64 aZ,
            const f16* Bh, int ldb, i64 bZ,
            float* C, int ldc, i64 cZ,
            f16* Ch,
            const float* Fres, i64 fZ,
            const float* gw, const float* bw,
            float scale, int KT)
{
    const int z = blockIdx.z;
    const int row0 = blockIdx.x * 128, col0 = blockIdx.y * 128;
    gemm_core<RES, OF32, OF16, GN2>(
        Ah + (i64)z * aZ, lda,
        Bh + (i64)z * bZ, ldb,
        C + (i64)z * cZ, ldc,
        (OF16 || GN2) ? Ch + (i64)z * cZ : (f16*)0,
        (RES || GN2) ? Fres + (i64)z * fZ : (const float*)0,
        gw, bw, row0, col0, scale, KT);
}

// ---------------- fused QKV kernel (z=0:Q, z=1:K, z=2:V->transposed) ------------
__global__ __launch_bounds__(256, 2)
void qkv_k(const f16* __restrict__ ctrs_h, const f16* __restrict__ feat_h,
           const f16* __restrict__ wq, const f16* __restrict__ wk, const f16* __restrict__ wv,
           f16* __restrict__ q_h, f16* __restrict__ k_h, f16* __restrict__ vt_h)
{
    extern __shared__ char sm[];
    const u32 sb = smem_u32(sm);
    const int z = blockIdx.z;
    const int row0 = blockIdx.x * 128;
    const f16* Ah = (z == 0) ? ctrs_h : feat_h;
    const f16* Bh = (z == 0) ? wq : (z == 1) ? wk : wv;

    const int tid = threadIdx.x;
    const int wid = tid >> 5, lane = tid & 31;
    const int m0w = (wid >> 1) * 32, n0w = (wid & 1) * 64;

    float acc[2][8][4];
    #pragma unroll
    for (int mi = 0; mi < 2; mi++)
        #pragma unroll
        for (int nj = 0; nj < 8; nj++)
            #pragma unroll
            for (int e = 0; e < 4; e++) acc[mi][nj][e] = 0.f;

    const u32 a_rb = (u32)(m0w + (lane & 15)) * 128;
    const u32 b_rb = (u32)(n0w + ((lane >> 4) << 3) + (lane & 7)) * 128;
    const int a_hi = lane >> 4;
    const int b_hi = (lane >> 3) & 1;
    const int xr = lane & 7;
    const int r_ld = tid >> 1;
    const int c0_ld = (tid & 1) * 4;

    auto load_half = [&](int h, int s) {
        const int kofs = h * 64;
        const u32 base = sb + (u32)s * 32768u;
        const f16* ap = Ah + (i64)(row0 + r_ld) * D + kofs;
        const f16* bp = Bh + (i64)r_ld * D + kofs;
        #pragma unroll
        for (int j = 0; j < 4; j++) {
            int c = c0_ld + j;
            u32 so = (u32)r_ld * 128 + (u32)((c ^ (r_ld & 7)) << 4);
            cp16_cg(base + so,          ap + c * 8);
            cp16_ca(base + 16384 + so,  bp + c * 8);
        }
        cp_commit();
    };

    load_half(0, 0);
    for (int h = 0; h < 2; h++) {
        if (h == 0) { load_half(1, 1); cp_wait<1>(); }
        else        { cp_wait<0>(); }
        __syncthreads();
        const u32 base = sb + (u32)(h & 1) * 32768u;
        const u32 abase = base + a_rb;
        const u32 bbase = base + 16384u + b_rb;
        #pragma unroll
        for (int ks = 0; ks < 4; ks++) {
            const u32 aoff = (u32)(((ks * 2 + a_hi) ^ xr) << 4);
            const u32 boff = (u32)(((ks * 2 + b_hi) ^ xr) << 4);
            u32 b[4][4], a0[4], a1[4];
            #pragma unroll
            for (int p = 0; p < 4; p++)
                ldsm4(b[p], bbase + boff + p * 2048);
            ldsm4(a0, abase + aoff);
            ldsm4(a1, abase + aoff + 2048);
            #pragma unroll
            for (int nj = 0; nj < 8; nj++) {
                u32 bb0 = b[nj >> 1][(nj & 1) * 2], bb1 = b[nj >> 1][(nj & 1) * 2 + 1];
                mma_f16(acc[0][nj], a0, bb0, bb1);
                mma_f16(acc[1][nj], a1, bb0, bb1);
            }
        }
        __syncthreads();
    }

    float* Cs = reinterpret_cast<float*>(sm);
    const int g = lane >> 2, q2 = (lane & 3) * 2;
    #pragma unroll
    for (int mi = 0; mi < 2; mi++)
        #pragma unroll
        for (int nj = 0; nj < 8; nj++) {
            int r = m0w + mi * 16 + g;
            int c = n0w + nj * 8 + q2;
            Cs[r * 132 + c]           = acc[mi][nj][0];
            Cs[r * 132 + c + 1]       = acc[mi][nj][1];
            Cs[(r + 8) * 132 + c]     = acc[mi][nj][2];
            Cs[(r + 8) * 132 + c + 1] = acc[mi][nj][3];
        }
    __syncthreads();

    if (z < 2) {
        f16* out = (z == 0) ? q_h : k_h;
        const int rr = tid >> 1, hh = tid & 1;
        const float* srow = Cs + rr * 132 + hh * 64;
        const i64 ro = (i64)(row0 + rr) * D + hh * 64;
        #pragma unroll
        for (int j = 0; j < 16; j++) {
            float4 vv = *reinterpret_cast<const float4*>(srow + j * 4);
            *reinterpret_cast<uint2*>(out + ro + j * 4) = cvt4(vv);
        }
    } else {
        // transposed fp16 store: vt[b][d][j] = C[j][d]
        const int d = tid >> 1, hh = tid & 1;
        const int jg0 = row0 + hh * 64;
        const int b = jg0 >> 10, jin = jg0 & 1023;
        f16* dst = vt_h + (i64)b * D * NSEQ + (i64)d * NSEQ + jin;
        #pragma unroll
        for (int j = 0; j < 64; j += 2) {
            float a0 = Cs[(hh * 64 + j) * 132 + d];
            float a1 = Cs[(hh * 64 + j + 1) * 132 + d];
            __half2 hv = __floats2half2_rn(a0, a1);
            *reinterpret_cast<u32*>(dst + j) = *(u32*)&hv;
        }
    }
}

// ---------------- persistent-B scatter kernel (now includes ctr group) ----------
// 3840 tiles = 15 groups x 256: g=0 ctr (identity gather/scatter), g1-6 pre,
// g7-12 suc, g13 left, g14 right. All outputs red.v4 into pre-zeroed T.
#define NTILES_SC 3840
#define CHUNK_SC 13
#define GRID_SC ((NTILES_SC + CHUNK_SC - 1) / CHUNK_SC)   // 296

__global__ __launch_bounds__(256, 2)
void layer_scatter_p(const f16* __restrict__ Xh,
                     const f16* __restrict__ wch,
                     const f16* __restrict__ wph, const f16* __restrict__ wsh,
                     const f16* __restrict__ wlh, const f16* __restrict__ wrh,
                     float* __restrict__ T,
                     const int* __restrict__ pre_u, const int* __restrict__ pre_v,
                     const int* __restrict__ suc_u, const int* __restrict__ suc_v,
                     const int* __restrict__ left_u, const int* __restrict__ left_v,
                     const int* __restrict__ right_u, const int* __restrict__ right_v)
{
    extern __shared__ char sm[];
    const u32 sb = smem_u32(sm);
    const int t0 = blockIdx.x * CHUNK_SC;
    const int t1 = (t0 + CHUNK_SC < NTILES_SC) ? t0 + CHUNK_SC : NTILES_SC;
    if (t0 >= NTILES_SC) return;

    const int tid = threadIdx.x;
    const int wid = tid >> 5, lane = tid & 31;
    const int m0w = (wid >> 1) * 32, n0w = (wid & 1) * 64;
    const u32 a_rb = (u32)(m0w + (lane & 15)) * 128;
    const u32 b_rb = (u32)(n0w + ((lane >> 4) << 3) + (lane & 7)) * 128;
    const int a_hi = lane >> 4;
    const int b_hi = (lane >> 3) & 1;
    const int xr = lane & 7;
    const int r_ld = tid >> 1;
    const int c0_ld = (tid & 1) * 4;

    auto group_of = [&](int t, const f16*& Bw, const int*& gv, const int*& su, int& base) {
        int g = t >> 8, e = (t & 255) * 128;
        base = e;
        if (g == 0)       { Bw = wch; gv = 0; su = 0; }
        else if (g < 7)   { int z = g - 1; Bw = wph + (i64)z * DD; gv = pre_v + z * NE + e; su = pre_u + z * NE + e; }
        else if (g < 13)  { int z = g - 7; Bw = wsh + (i64)z * DD; gv = suc_v + z * NE + e; su = suc_u + z * NE + e; }
        else if (g == 13) { Bw = wlh; gv = left_v + e; su = left_u + e; }
        else              { Bw = wrh; gv = right_v + e; su = right_u + e; }
    };

    auto load_B = [&](const f16* Bw) {
        const f16* bp = Bw + (i64)r_ld * D;
        #pragma unroll
        for (int h = 0; h < 2; h++) {
            const u32 base = sb + 32768u + (u32)h * 16384u;
            #pragma unroll
            for (int j = 0; j < 4; j++) {
                int c = c0_ld + j;
                u32 so = (u32)r_ld * 128 + (u32)((c ^ (r_ld & 7)) << 4);
                cp16_ca(base + so, bp + h * 64 + c * 8);
            }
        }
        cp_commit();
    };
    auto load_A = [&](const int* gv, int base_row, int h, int s) {
        i64 arow = gv ? (i64)__ldg(gv + r_ld) : (i64)(base_row + r_ld);
        const f16* ap = Xh + arow * D + h * 64;
        const u32 base = sb + (u32)s * 16384u;
        #pragma unroll
        for (int j = 0; j < 4; j++) {
            int c = c0_ld + j;
            u32 so = (u32)r_ld * 128 + (u32)((c ^ (r_ld & 7)) << 4);
            cp16_cg(base + so, ap + c * 8);
        }
        cp_commit();
    };

    const int g = lane >> 2;
    const int q = lane & 3;
    const int cb = n0w + ((q >> 1) << 2);
    const bool evenlane = ((lane & 1) == 0);
    const f16* Bw; const int* gv; const int* su; int base_row;
    group_of(t0, Bw, gv, su, base_row);
    int curg = t0 >> 8;
    load_B(Bw);
    load_A(gv, base_row, 0, 0);
    load_A(gv, base_row, 1, 1);

    for (int t = t0; t < t1; t++) {
        const f16* Bw_n = 0; const int* gv_n = 0; const int* su_n = 0; int base_n = 0;
        const bool have_next = (t + 1 < t1);
        int g_n = curg;
        if (have_next) { group_of(t + 1, Bw_n, gv_n, su_n, base_n); g_n = (t + 1) >> 8; }
        const bool pref0 = have_next && (g_n == curg);

        float acc[2][8][4];
        #pragma unroll
        for (int mi = 0; mi < 2; mi++)
            #pragma unroll
            for (int nj = 0; nj < 8; nj++)
                #pragma unroll
                for (int e = 0; e < 4; e++) acc[mi][nj][e] = 0.f;

        // half 0
        cp_wait<1>(); __syncthreads();
        {
            const u32 abase = sb + a_rb;
            const u32 bbase = sb + 32768u + b_rb;
            #pragma unroll
            for (int ks = 0; ks < 4; ks++) {
                const u32 aoff = (u32)(((ks * 2 + a_hi) ^ xr) << 4);
                const u32 boff = (u32)(((ks * 2 + b_hi) ^ xr) << 4);
                u32 b[4][4], a0[4], a1[4];
                #pragma unroll
                for (int p = 0; p < 4; p++)
                    ldsm4(b[p], bbase + boff + p * 2048);
                ldsm4(a0, abase + aoff);
                ldsm4(a1, abase + aoff + 2048);
                #pragma unroll
                for (int nj = 0; nj < 8; nj++) {
                    u32 bb0 = b[nj >> 1][(nj & 1) * 2], bb1 = b[nj >> 1][(nj & 1) * 2 + 1];
                    mma_f16(acc[0][nj], a0, bb0, bb1);
                    mma_f16(acc[1][nj], a1, bb0, bb1);
                }
            }
        }
        __syncthreads();
        if (pref0) load_A(gv_n, base_n, 0, 0);

        // half 1
        if (pref0) cp_wait<1>(); else cp_wait<0>();
        __syncthreads();
        {
            const u32 abase = sb + 16384u + a_rb;
            const u32 bbase = sb + 49152u + b_rb;
            #pragma unroll
            for (int ks = 0; ks < 4; ks++) {
                const u32 aoff = (u32)(((ks * 2 + a_hi) ^ xr) << 4);
                const u32 boff = (u32)(((ks * 2 + b_hi) ^ xr) << 4);
                u32 b[4][4], a0[4], a1[4];
                #pragma unroll
                for (int p = 0; p < 4; p++)
                    ldsm4(b[p], bbase + boff + p * 2048);
                ldsm4(a0, abase + aoff);
                ldsm4(a1, abase + aoff + 2048);
                #pragma unroll
                for (int nj = 0; nj < 8; nj++) {
                    u32 bb0 = b[nj >> 1][(nj & 1) * 2], bb1 = b[nj >> 1][(nj & 1) * 2 + 1];
                    mma_f16(acc[0][nj], a0, bb0, bb1);
                    mma_f16(acc[1][nj], a1, bb0, bb1);
                }
            }
        }

        // epilogue: lane-pair shfl -> red.v4 (even lane: row r, odd lane: row r+8)
        #pragma unroll
        for (int mi = 0; mi < 2; mi++) {
            int lr1 = m0w + mi * 16 + g;
            i64 dr1 = su ? (i64)__ldg(su + lr1)     : (i64)(base_row + lr1);
            i64 dr2 = su ? (i64)__ldg(su + lr1 + 8) : (i64)(base_row + lr1 + 8);
            float* pr = evenlane ? (T + dr1 * D) : (T + dr2 * D);
            #pragma unroll
            for (int nj = 0; nj < 8; nj++) {
                float v0 = acc[mi][nj][0], v1 = acc[mi][nj][1];
                float v2 = acc[mi][nj][2], v3 = acc[mi][nj][3];
                float p0 = __shfl_xor_sync(0xffffffffu, v0, 1);
                float p1 = __shfl_xor_sync(0xffffffffu, v1, 1);
                float p2 = __shfl_xor_sync(0xffffffffu, v2, 1);
                float p3 = __shfl_xor_sync(0xffffffffu, v3, 1);
                if (evenlane) red4(pr + cb + nj * 8, v0, v1, p0, p1);
                else          red4(pr + cb + nj * 8, p2, p3, v2, v3);
            }
        }
        __syncthreads();

        if (have_next) {
            if (g_n == curg) {
                load_A(gv_n, base_n, 1, 1);
            } else {
                cp_wait<0>(); __syncthreads();
                load_B(Bw_n);
                load_A(gv_n, base_n, 0, 0);
                load_A(gv_n, base_n, 1, 1);
                curg = g_n;
            }
            gv = gv_n; su = su_n; base_row = base_n;
        }
    }
}

// ---------------- fused conversion kernel ----------------------------------------
#define NSEG 11
struct CvtArgs {
    const float4* src[NSEG];
    uint2* dst[NSEG];
    int n4[NSEG];
};
__global__ __launch_bounds__(256)
void cvt_all(CvtArgs a)
{
    const int seg = blockIdx.y;
    const int i = blockIdx.x * 256 + threadIdx.x;
    if (i < a.n4[seg]) a.dst[seg][i] = cvt4(a.src[seg][i]);
}

__global__ __launch_bounds__(256)
void zero_T(float4* p)
{
    p[blockIdx.x * 256 + threadIdx.x] = make_float4(0.f, 0.f, 0.f, 0.f);
}

// row softmax over 1024, emit fp16
__global__ __launch_bounds__(256)
void softmax_k(const float* __restrict__ Sc, f16* __restrict__ oh)
{
    i64 row = blockIdx.x;
    const float4* p = reinterpret_cast<const float4*>(Sc + row * NSEQ);
    int t = threadIdx.x;
    float4 v = p[t];
    float mx = fmaxf(fmaxf(v.x, v.y), fmaxf(v.z, v.w));
    #pragma unroll
    for (int o = 16; o; o >>= 1) mx = fmaxf(mx, __shfl_xor_sync(0xffffffffu, mx, o));
    __shared__ float red8[8];
    int w = t >> 5;
    if ((t & 31) == 0) red8[w] = mx;
    __syncthreads();
    mx = red8[0];
    #pragma unroll
    for (int i = 1; i < 8; i++) mx = fmaxf(mx, red8[i]);
    v.x = expf(v.x - mx); v.y = expf(v.y - mx);
    v.z = expf(v.z - mx); v.w = expf(v.w - mx);
    float s = v.x + v.y + v.z + v.w;
    #pragma unroll
    for (int o = 16; o; o >>= 1) s += __shfl_xor_sync(0xffffffffu, s, o);
    __syncthreads();
    if ((t & 31) == 0) red8[w] = s;
    __syncthreads();
    s = red8[0] + red8[1] + red8[2] + red8[3] + red8[4] + red8[5] + red8[6] + red8[7];
    float inv = 1.0f / s;
    v.x *= inv; v.y *= inv; v.z *= inv; v.w *= inv;
    *reinterpret_cast<uint2*>(oh + row * NSEQ + t * 4) = cvt4(v);
}

// gn1: warp-per-row, float4 lanes, shfl-only reduction; zeroes T in place for the
// next layer's scatter accumulation.
__global__ __launch_bounds__(256)
void gn1_kernel(float* __restrict__ T, f16* __restrict__ outh,
                const float* __restrict__ gw, const float* __restrict__ bw)
{
    const int row = blockIdx.x * 8 + (threadIdx.x >> 5);
    const int lane = threadIdx.x & 31;
    const i64 ro = (i64)row * D + lane * 4;
    float4 v = *reinterpret_cast<const float4*>(T + ro);
    float s1 = v.x + v.y + v.z + v.w;
    float s2 = v.x * v.x + v.y * v.y + v.z * v.z + v.w * v.w;
    #pragma unroll
    for (int o = 16; o; o >>= 1) {
        s1 += __shfl_xor_sync(0xffffffffu, s1, o);
        s2 += __shfl_xor_sync(0xffffffffu, s2, o);
    }
    const float mu = s1 * (1.f / 128.f);
    const float var = s2 * (1.f / 128.f) - mu * mu;
    const float rstd = rsqrtf(var + 1e-5f);
    float4 g4 = *reinterpret_cast<const float4*>(gw + lane * 4);
    float4 b4 = *reinterpret_cast<const float4*>(bw + lane * 4);
    float4 y;
    y.x = fmaxf((v.x - mu) * rstd * g4.x + b4.x, 0.f);
    y.y = fmaxf((v.y - mu) * rstd * g4.y + b4.y, 0.f);
    y.z = fmaxf((v.z - mu) * rstd * g4.z + b4.z, 0.f);
    y.w = fmaxf((v.w - mu) * rstd * g4.w + b4.w, 0.f);
    *reinterpret_cast<uint2*>(outh + ro) = cvt4(y);
    *reinterpret_cast<float4*>(T + ro) = make_float4(0.f, 0.f, 0.f, 0.f);
}

// ---------------- driver ---------------------------------------------------------
#define SMEM_SZ 67584   // dense path: 2x32KB operand stages / epilogue staging
#define SMEM_SC 65536   // persistent scatter: 2x16KB A + 32KB B

extern "C" void kernel_launch(void* const* d_in, const int* in_sizes, int n_in,
                              void* d_out, int out_size)
{
    (void)in_sizes; (void)n_in; (void)out_size;
    const float* ctrs   = (const float*)d_in[0];
    const float* feats  = (const float*)d_in[1];
    const float* Wq     = (const float*)d_in[2];
    const float* Wk     = (const float*)d_in[3];
    const float* Wv     = (const float*)d_in[4];
    const float* Wc     = (const float*)d_in[5];
    const float* Wp     = (const float*)d_in[6];
    const float* Ws     = (const float*)d_in[7];
    const float* Wl     = (const float*)d_in[8];
    const float* Wr     = (const float*)d_in[9];
    const float* Wc2    = (const float*)d_in[10];
    const float* g1     = (const float*)d_in[11];
    const float* b1     = (const float*)d_in[12];
    const float* g2     = (const float*)d_in[13];
    const float* b2     = (const float*)d_in[14];
    const int* pre_u    = (const int*)d_in[15];
    const int* pre_v    = (const int*)d_in[16];
    const int* suc_u    = (const int*)d_in[17];
    const int* suc_v    = (const int*)d_in[18];
    const int* left_u   = (const int*)d_in[19];
    const int* left_v   = (const int*)d_in[20];
    const int* right_u  = (const int*)d_in[21];
    const int* right_v  = (const int*)d_in[22];
    float* X = (float*)d_out;

    float *sc, *T;
    cudaGetSymbolAddress((void**)&sc, g_sc);
    cudaGetSymbolAddress((void**)&T,  g_T);
    f16 *ctrs_h, *feat_h, *q_h, *k_h, *vt_h, *x_h, *y_h, *sc_h;
    f16 *wq_h, *wk_h, *wv_h, *wc_h, *wp_h, *ws_h, *wl_h, *wr_h, *w2_h;
    cudaGetSymbolAddress((void**)&ctrs_h, s_ctrs_h);
    cudaGetSymbolAddress((void**)&feat_h, s_feat_h);
    cudaGetSymbolAddress((void**)&q_h, s_q_h);
    cudaGetSymbolAddress((void**)&k_h, s_k_h);
    cudaGetSymbolAddress((void**)&vt_h, s_vt_h);
    cudaGetSymbolAddress((void**)&x_h, s_x_h);
    cudaGetSymbolAddress((void**)&y_h, s_y_h);
    cudaGetSymbolAddress((void**)&sc_h, s_sc_h);
    cudaGetSymbolAddress((void**)&wq_h, s_wq_h);
    cudaGetSymbolAddress((void**)&wk_h, s_wk_h);
    cudaGetSymbolAddress((void**)&wv_h, s_wv_h);
    cudaGetSymbolAddress((void**)&wc_h, s_wc_h);
    cudaGetSymbolAddress((void**)&wp_h, s_wp_h);
    cudaGetSymbolAddress((void**)&ws_h, s_ws_h);
    cudaGetSymbolAddress((void**)&wl_h, s_wl_h);
    cudaGetSymbolAddress((void**)&wr_h, s_wr_h);
    cudaGetSymbolAddress((void**)&w2_h, s_w2_h);

    cudaFuncSetAttribute((const void*)gemm_k<false,true ,false,false>, cudaFuncAttributeMaxDynamicSharedMemorySize, SMEM_SZ);
    cudaFuncSetAttribute((const void*)gemm_k<true ,true ,true ,false>, cudaFuncAttributeMaxDynamicSharedMemorySize, SMEM_SZ);
    cudaFuncSetAttribute((const void*)gemm_k<false,false,false,true >, cudaFuncAttributeMaxDynamicSharedMemorySize, SMEM_SZ);
    cudaFuncSetAttribute((const void*)qkv_k, cudaFuncAttributeMaxDynamicSharedMemorySize, SMEM_SZ);
    cudaFuncSetAttribute((const void*)layer_scatter_p, cudaFuncAttributeMaxDynamicSharedMemorySize, SMEM_SC);

    const float NF = 0.08838834764831845f;  // 1/sqrt(128)
    dim3 blk(256);

    // ---- one fused conversion launch + one-time T zero ----
    CvtArgs ca;
    const float* srcs[NSEG] = {ctrs, feats, Wq, Wk, Wv, Wc, Wp, Ws, Wl, Wr, Wc2};
    f16* dsts[NSEG] = {ctrs_h, feat_h, wq_h, wk_h, wv_h, wc_h, wp_h, ws_h, wl_h, wr_h, w2_h};
    const int ns[NSEG] = {M_ROWS*D, M_ROWS*D, DD, DD, DD, NL*DD, NL*NS*DD, NL*NS*DD, NL*DD, NL*DD, NL*DD};
    int maxn4 = 0;
    for (int i = 0; i < NSEG; i++) {
        ca.src[i] = (const float4*)srcs[i];
        ca.dst[i] = (uint2*)dsts[i];
        ca.n4[i] = ns[i] / 4;
        if (ca.n4[i] > maxn4) maxn4 = ca.n4[i];
    }
    cvt_all<<<dim3((maxn4 + 255) / 256, NSEG), 256>>>(ca);
    zero_T<<<M_ROWS * D / 4 / 256, 256>>>((float4*)T);

    // ---- attention ----
    qkv_k<<<dim3(128, 1, 3), blk, SMEM_SZ>>>(ctrs_h, feat_h, wq_h, wk_h, wv_h, q_h, k_h, vt_h);
    gemm_k<false,true,false,false><<<dim3(8,8,16), blk, SMEM_SZ>>>(
        q_h, D, (i64)NSEQ*D, k_h, D, (i64)NSEQ*D,
        sc, NSEQ, (i64)NSEQ*NSEQ, 0, 0, 0, 0, 0, NF, 1);
    softmax_k<<<M_ROWS, 256>>>(sc, sc_h);
    gemm_k<true,true,true,false><<<dim3(8,1,16), blk, SMEM_SZ>>>(
        sc_h, NSEQ, (i64)NSEQ*NSEQ, vt_h, NSEQ, (i64)D*NSEQ,
        X, D, (i64)NSEQ*D, x_h, feats, (i64)NSEQ*D, 0, 0, 1.f, 8);

    // ---- 4-layer fusion loop ----
    for (int i = 0; i < NL; i++) {
        // persistent-B scatter (ctr + pre + suc + left + right) into zeroed T
        layer_scatter_p<<<GRID_SC, blk, SMEM_SC>>>(
            x_h,
            wc_h + (i64)i*DD,
            wp_h + (i64)i*NS*DD,
            ws_h + (i64)i*NS*DD,
            wl_h + (i64)i*DD,
            wr_h + (i64)i*DD,
            T, pre_u, pre_v, suc_u, suc_v, left_u, left_v, right_u, right_v);
        // gn1 + relu -> y_h (fp16); re-zeroes T for the next layer
        gn1_kernel<<<M_ROWS / 8, 256>>>(T, y_h, g1 + i*D, b1 + i*D);
        // ctr2 GEMM with fused gn2 + residual + relu epilogue -> X (fp32) + x_h (fp16)
        gemm_k<false,false,false,true><<<dim3(128,1,1), blk, SMEM_SZ>>>(
            y_h, D, 0, w2_h + (i64)i*DD, D, 0,
            X, D, 0, x_h, X, 0, g2 + i*D, b2 + i*D, 1.f, 1);
    }
}

// round 12
// speedup vs baseline: 2.1889x; 1.0028x over previous
#include <cuda_runtime.h>
#include <cuda_fp16.h>
#include <math.h>
#include <stdint.h>

#define D 128
#define DD 16384
#define BATCH 16
#define NSEQ 1024
#define M_ROWS 16384
#define NE 32768
#define NS 6
#define NL 4

typedef unsigned long long u64;
typedef unsigned int u32;
typedef long long i64;
typedef __half f16;

// ---------------- scratch (fp32) ---------------------------------------------
__device__ __align__(256) float g_sc[(size_t)BATCH * NSEQ * NSEQ];
__device__ __align__(256) float g_T [M_ROWS * D];

// ---------------- scratch (fp16) -----------------------------------------------
__device__ __align__(256) f16 s_ctrs_h[M_ROWS*D];
__device__ __align__(256) f16 s_feat_h[M_ROWS*D];
__device__ __align__(256) f16 s_q_h[M_ROWS*D];
__device__ __align__(256) f16 s_k_h[M_ROWS*D];
__device__ __align__(256) f16 s_vt_h[M_ROWS*D];
__device__ __align__(256) f16 s_x_h[M_ROWS*D];
__device__ __align__(256) f16 s_y_h[M_ROWS*D];
__device__ __align__(256) f16 s_sc_h[(size_t)BATCH*NSEQ*NSEQ];
__device__ __align__(256) f16 s_wq_h[DD], s_wk_h[DD], s_wv_h[DD];
__device__ __align__(256) f16 s_wc_h[NL*DD];
__device__ __align__(256) f16 s_wp_h[NL*NS*DD];
__device__ __align__(256) f16 s_ws_h[NL*NS*DD];
__device__ __align__(256) f16 s_wl_h[NL*DD];
__device__ __align__(256) f16 s_wr_h[NL*DD];
__device__ __align__(256) f16 s_w2_h[NL*DD];

// ---------------- PTX helpers ------------------------------------------------
__device__ __forceinline__ u32 smem_u32(const void* p) {
    u32 a;
    asm("{ .reg .u64 t; cvta.to.shared.u64 t, %1; cvt.u32.u64 %0, t; }" : "=r"(a) : "l"(p));
    return a;
}
__device__ __forceinline__ void ldsm4(u32* r, u32 addr) {
    asm volatile("ldmatrix.sync.aligned.m8n8.x4.shared.b16 {%0,%1,%2,%3}, [%4];"
                 : "=r"(r[0]), "=r"(r[1]), "=r"(r[2]), "=r"(r[3]) : "r"(addr));
}
__device__ __forceinline__ void mma_f16(float* d, const u32* a, u32 b0, u32 b1) {
    asm volatile("mma.sync.aligned.m16n8k16.row.col.f32.f16.f16.f32 "
                 "{%0,%1,%2,%3}, {%4,%5,%6,%7}, {%8,%9}, {%0,%1,%2,%3};"
                 : "+f"(d[0]), "+f"(d[1]), "+f"(d[2]), "+f"(d[3])
                 : "r"(a[0]), "r"(a[1]), "r"(a[2]), "r"(a[3]), "r"(b0), "r"(b1));
}
__device__ __forceinline__ void red4(float* p, float a, float b, float c, float d) {
    asm volatile("red.global.add.v4.f32 [%0], {%1,%2,%3,%4};"
                 :: "l"(p), "f"(a), "f"(b), "f"(c), "f"(d) : "memory");
}
__device__ __forceinline__ void cp16_cg(u32 dst, const void* src) {
    asm volatile("cp.async.cg.shared.global [%0], [%1], 16;" :: "r"(dst), "l"(src));
}
__device__ __forceinline__ void cp16_ca(u32 dst, const void* src) {
    asm volatile("cp.async.ca.shared.global [%0], [%1], 16;" :: "r"(dst), "l"(src));
}
__device__ __forceinline__ void cp_commit() { asm volatile("cp.async.commit_group;" ::: "memory"); }
template<int N> __device__ __forceinline__ void cp_wait() {
    asm volatile("cp.async.wait_group %0;" :: "n"(N) : "memory");
}
__device__ __forceinline__ uint2 cvt4(float4 v) {
    __half2 h0 = __floats2half2_rn(v.x, v.y);
    __half2 h1 = __floats2half2_rn(v.z, v.w);
    return make_uint2(*(u32*)&h0, *(u32*)&h1);
}

// =====================================================================
// MMA fragment compute over one resident 128-K tile pair (two halves).
// abase/bbase point at half0 regions; half1 at +16384.
// =====================================================================
__device__ __forceinline__ void compute_tile(
    float acc[2][8][4], u32 abase0, u32 bbase0, int a_hi, int b_hi, int xr)
{
    #pragma unroll
    for (int h = 0; h < 2; h++) {
        const u32 abase = abase0 + (u32)h * 16384u;
        const u32 bbase = bbase0 + (u32)h * 16384u;
        #pragma unroll
        for (int ks = 0; ks < 4; ks++) {
            const u32 aoff = (u32)(((ks * 2 + a_hi) ^ xr) << 4);
            const u32 boff = (u32)(((ks * 2 + b_hi) ^ xr) << 4);
            u32 b[4][4], a0[4], a1[4];
            #pragma unroll
            for (int p = 0; p < 4; p++)
                ldsm4(b[p], bbase + boff + p * 2048);
            ldsm4(a0, abase + aoff);
            ldsm4(a1, abase + aoff + 2048);
            #pragma unroll
            for (int nj = 0; nj < 8; nj++) {
                u32 bb0 = b[nj >> 1][(nj & 1) * 2], bb1 = b[nj >> 1][(nj & 1) * 2 + 1];
                mma_f16(acc[0][nj], a0, bb0, bb1);
                mma_f16(acc[1][nj], a1, bb0, bb1);
            }
        }
    }
}

// ---------------- generic GEMM kernel (ctr2 + gn2 fused path) --------------------
__global__ __launch_bounds__(256, 2)
void gemm_gn2_k(const f16* __restrict__ Ah,
                const f16* __restrict__ Bh,
                float* __restrict__ C, f16* __restrict__ Ch,
                const float* __restrict__ Fres,
                const float* __restrict__ gw, const float* __restrict__ bw)
{
    extern __shared__ char sm[];
    const u32 sb = smem_u32(sm);
    const int row0 = blockIdx.x * 128;
    const int tid = threadIdx.x;
    const int wid = tid >> 5, lane = tid & 31;
    const int m0w = (wid >> 1) * 32, n0w = (wid & 1) * 64;

    float acc[2][8][4];
    #pragma unroll
    for (int mi = 0; mi < 2; mi++)
        #pragma unroll
        for (int nj = 0; nj < 8; nj++)
            #pragma unroll
            for (int e = 0; e < 4; e++) acc[mi][nj][e] = 0.f;

    const u32 a_rb = (u32)(m0w + (lane & 15)) * 128;
    const u32 b_rb = (u32)(n0w + ((lane >> 4) << 3) + (lane & 7)) * 128;
    const int a_hi = lane >> 4;
    const int b_hi = (lane >> 3) & 1;
    const int xr = lane & 7;
    const int r_ld = tid >> 1;
    const int c0_ld = (tid & 1) * 4;

    // load both halves of A and B (resident; 64KB)
    {
        const f16* ap = Ah + (i64)(row0 + r_ld) * D;
        const f16* bp = Bh + (i64)r_ld * D;
        #pragma unroll
        for (int h = 0; h < 2; h++)
            #pragma unroll
            for (int j = 0; j < 4; j++) {
                int c = c0_ld + j;
                u32 so = (u32)r_ld * 128 + (u32)((c ^ (r_ld & 7)) << 4);
                cp16_cg(sb + (u32)h * 16384u + so,          ap + h * 64 + c * 8);
                cp16_ca(sb + 32768u + (u32)h * 16384u + so, bp + h * 64 + c * 8);
            }
        cp_commit();
    }
    cp_wait<0>();
    __syncthreads();
    compute_tile(acc, sb + a_rb, sb + 32768u + b_rb, a_hi, b_hi, xr);
    __syncthreads();

    // stage to SMEM for row-wise GN
    float* Cs = reinterpret_cast<float*>(sm);
    const int g = lane >> 2, q2 = (lane & 3) * 2;
    #pragma unroll
    for (int mi = 0; mi < 2; mi++)
        #pragma unroll
        for (int nj = 0; nj < 8; nj++) {
            int r = m0w + mi * 16 + g;
            int c = n0w + nj * 8 + q2;
            Cs[r * 132 + c]           = acc[mi][nj][0];
            Cs[r * 132 + c + 1]       = acc[mi][nj][1];
            Cs[(r + 8) * 132 + c]     = acc[mi][nj][2];
            Cs[(r + 8) * 132 + c + 1] = acc[mi][nj][3];
        }
    __syncthreads();

    const int rr = tid >> 1, hh = tid & 1;
    const float* srow = Cs + rr * 132 + hh * 64;
    float s1 = 0.f, s2 = 0.f;
    #pragma unroll
    for (int j = 0; j < 16; j++) {
        float4 vv = *reinterpret_cast<const float4*>(srow + j * 4);
        s1 += vv.x + vv.y + vv.z + vv.w;
        s2 += vv.x * vv.x + vv.y * vv.y + vv.z * vv.z + vv.w * vv.w;
    }
    s1 += __shfl_xor_sync(0xffffffffu, s1, 1);
    s2 += __shfl_xor_sync(0xffffffffu, s2, 1);
    const float mu = s1 * (1.f / 128.f);
    const float var = s2 * (1.f / 128.f) - mu * mu;
    const float rstd = rsqrtf(var + 1e-5f);
    const i64 ro = (i64)(row0 + rr) * D + hh * 64;
    const float* fp = Fres + ro;
    float* p = C + ro;
    const float* gp = gw + hh * 64;
    const float* bp = bw + hh * 64;
    #pragma unroll
    for (int j = 0; j < 16; j++) {
        float4 vv = *reinterpret_cast<const float4*>(srow + j * 4);
        float4 g4 = *reinterpret_cast<const float4*>(gp + j * 4);
        float4 b4 = *reinterpret_cast<const float4*>(bp + j * 4);
        float4 f4 = *reinterpret_cast<const float4*>(fp + j * 4);
        vv.x = fmaxf((vv.x - mu) * rstd * g4.x + b4.x + f4.x, 0.f);
        vv.y = fmaxf((vv.y - mu) * rstd * g4.y + b4.y + f4.y, 0.f);
        vv.z = fmaxf((vv.z - mu) * rstd * g4.z + b4.z + f4.z, 0.f);
        vv.w = fmaxf((vv.w - mu) * rstd * g4.w + b4.w + f4.w, 0.f);
        *reinterpret_cast<float4*>(p + j * 4) = vv;
        *reinterpret_cast<uint2*>(Ch + ro + j * 4) = cvt4(vv);
    }
}

// ---------------- fused QKV kernel (z=0:Q, z=1:K, z=2:V->transposed) ------------
__global__ __launch_bounds__(256, 2)
void qkv_k(const f16* __restrict__ ctrs_h, const f16* __restrict__ feat_h,
           const f16* __restrict__ wq, const f16* __restrict__ wk, const f16* __restrict__ wv,
           f16* __restrict__ q_h, f16* __restrict__ k_h, f16* __restrict__ vt_h)
{
    extern __shared__ char sm[];
    const u32 sb = smem_u32(sm);
    const int z = blockIdx.z;
    const int row0 = blockIdx.x * 128;
    const f16* Ah = (z == 0) ? ctrs_h : feat_h;
    const f16* Bh = (z == 0) ? wq : (z == 1) ? wk : wv;

    const int tid = threadIdx.x;
    const int wid = tid >> 5, lane = tid & 31;
    const int m0w = (wid >> 1) * 32, n0w = (wid & 1) * 64;

    float acc[2][8][4];
    #pragma unroll
    for (int mi = 0; mi < 2; mi++)
        #pragma unroll
        for (int nj = 0; nj < 8; nj++)
            #pragma unroll
            for (int e = 0; e < 4; e++) acc[mi][nj][e] = 0.f;

    const u32 a_rb = (u32)(m0w + (lane & 15)) * 128;
    const u32 b_rb = (u32)(n0w + ((lane >> 4) << 3) + (lane & 7)) * 128;
    const int a_hi = lane >> 4;
    const int b_hi = (lane >> 3) & 1;
    const int xr = lane & 7;
    const int r_ld = tid >> 1;
    const int c0_ld = (tid & 1) * 4;

    {
        const f16* ap = Ah + (i64)(row0 + r_ld) * D;
        const f16* bp = Bh + (i64)r_ld * D;
        #pragma unroll
        for (int h = 0; h < 2; h++)
            #pragma unroll
            for (int j = 0; j < 4; j++) {
                int c = c0_ld + j;
                u32 so = (u32)r_ld * 128 + (u32)((c ^ (r_ld & 7)) << 4);
                cp16_cg(sb + (u32)h * 16384u + so,          ap + h * 64 + c * 8);
                cp16_ca(sb + 32768u + (u32)h * 16384u + so, bp + h * 64 + c * 8);
            }
        cp_commit();
    }
    cp_wait<0>();
    __syncthreads();
    compute_tile(acc, sb + a_rb, sb + 32768u + b_rb, a_hi, b_hi, xr);
    __syncthreads();

    float* Cs = reinterpret_cast<float*>(sm);
    const int g = lane >> 2, q2 = (lane & 3) * 2;
    #pragma unroll
    for (int mi = 0; mi < 2; mi++)
        #pragma unroll
        for (int nj = 0; nj < 8; nj++) {
            int r = m0w + mi * 16 + g;
            int c = n0w + nj * 8 + q2;
            Cs[r * 132 + c]           = acc[mi][nj][0];
            Cs[r * 132 + c + 1]       = acc[mi][nj][1];
            Cs[(r + 8) * 132 + c]     = acc[mi][nj][2];
            Cs[(r + 8) * 132 + c + 1] = acc[mi][nj][3];
        }
    __syncthreads();

    if (z < 2) {
        f16* out = (z == 0) ? q_h : k_h;
        const int rr = tid >> 1, hh = tid & 1;
        const float* srow = Cs + rr * 132 + hh * 64;
        const i64 ro = (i64)(row0 + rr) * D + hh * 64;
        #pragma unroll
        for (int j = 0; j < 16; j++) {
            float4 vv = *reinterpret_cast<const float4*>(srow + j * 4);
            *reinterpret_cast<uint2*>(out + ro + j * 4) = cvt4(vv);
        }
    } else {
        const int d = tid >> 1, hh = tid & 1;
        const int jg0 = row0 + hh * 64;
        const int b = jg0 >> 10, jin = jg0 & 1023;
        f16* dst = vt_h + (i64)b * D * NSEQ + (i64)d * NSEQ + jin;
        #pragma unroll
        for (int j = 0; j < 64; j += 2) {
            float a0 = Cs[(hh * 64 + j) * 132 + d];
            float a1 = Cs[(hh * 64 + j + 1) * 132 + d];
            __half2 hv = __floats2half2_rn(a0, a1);
            *reinterpret_cast<u32*>(dst + j) = *(u32*)&hv;
        }
    }
}

// ---------------- QK scores kernel: A-resident, 4 B tiles streamed ---------------
// grid (8 row-tiles, 2 col-groups, 16 batches); smem A 32KB + B 2x32KB = 96KB.
__global__ __launch_bounds__(256, 2)
void qk_k(const f16* __restrict__ q_h, const f16* __restrict__ k_h,
          float* __restrict__ sc, float scale)
{
    extern __shared__ char sm[];
    const u32 sb = smem_u32(sm);
    const int z = blockIdx.z;
    const int row0 = blockIdx.x * 128;
    const int cg0 = blockIdx.y * 4;
    const f16* Ab = q_h + (i64)z * NSEQ * D;
    const f16* Bb = k_h + (i64)z * NSEQ * D;
    float* Cb = sc + (i64)z * NSEQ * NSEQ;

    const int tid = threadIdx.x;
    const int wid = tid >> 5, lane = tid & 31;
    const int m0w = (wid >> 1) * 32, n0w = (wid & 1) * 64;
    const u32 a_rb = (u32)(m0w + (lane & 15)) * 128;
    const u32 b_rb = (u32)(n0w + ((lane >> 4) << 3) + (lane & 7)) * 128;
    const int a_hi = lane >> 4;
    const int b_hi = (lane >> 3) & 1;
    const int xr = lane & 7;
    const int r_ld = tid >> 1;
    const int c0_ld = (tid & 1) * 4;

    // A resident (both halves)
    {
        const f16* ap = Ab + (i64)(row0 + r_ld) * D;
        #pragma unroll
        for (int h = 0; h < 2; h++)
            #pragma unroll
            for (int j = 0; j < 4; j++) {
                int c = c0_ld + j;
                u32 so = (u32)r_ld * 128 + (u32)((c ^ (r_ld & 7)) << 4);
                cp16_cg(sb + (u32)h * 16384u + so, ap + h * 64 + c * 8);
            }
        cp_commit();
    }
    auto load_B = [&](int ct, int s) {
        const f16* bp = Bb + (i64)(ct * 128 + r_ld) * D;
        const u32 base = sb + 32768u + (u32)s * 32768u;
        #pragma unroll
        for (int h = 0; h < 2; h++)
            #pragma unroll
            for (int j = 0; j < 4; j++) {
                int c = c0_ld + j;
                u32 so = (u32)r_ld * 128 + (u32)((c ^ (r_ld & 7)) << 4);
                cp16_ca(base + (u32)h * 16384u + so, bp + h * 64 + c * 8);
            }
        cp_commit();
    };
    load_B(cg0, 0);

    const int g = lane >> 2;
    const int q = lane & 3;
    const int cb = n0w + ((q >> 1) << 2);
    const bool evenlane = ((lane & 1) == 0);

    for (int i = 0; i < 4; i++) {
        const int s = i & 1;
        if (i < 3) { load_B(cg0 + i + 1, 1 - s); cp_wait<1>(); }
        else       { cp_wait<0>(); }
        __syncthreads();

        float acc[2][8][4];
        #pragma unroll
        for (int mi = 0; mi < 2; mi++)
            #pragma unroll
            for (int nj = 0; nj < 8; nj++)
                #pragma unroll
                for (int e = 0; e < 4; e++) acc[mi][nj][e] = 0.f;

        compute_tile(acc, sb + a_rb, sb + 32768u + (u32)s * 32768u + b_rb, a_hi, b_hi, xr);

        // pair-shfl -> st.v4, scaled
        const int col0 = (cg0 + i) * 128;
        #pragma unroll
        for (int mi = 0; mi < 2; mi++) {
            int r1 = row0 + m0w + mi * 16 + g;
            float* pr = evenlane ? (Cb + (i64)r1 * NSEQ) : (Cb + (i64)(r1 + 8) * NSEQ);
            #pragma unroll
            for (int nj = 0; nj < 8; nj++) {
                float v0 = acc[mi][nj][0] * scale, v1 = acc[mi][nj][1] * scale;
                float v2 = acc[mi][nj][2] * scale, v3 = acc[mi][nj][3] * scale;
                float p0 = __shfl_xor_sync(0xffffffffu, v0, 1);
                float p1 = __shfl_xor_sync(0xffffffffu, v1, 1);
                float p2 = __shfl_xor_sync(0xffffffffu, v2, 1);
                float p3 = __shfl_xor_sync(0xffffffffu, v3, 1);
                float4 o = evenlane ? make_float4(v0, v1, p0, p1)
                                    : make_float4(p2, p3, v2, v3);
                *reinterpret_cast<float4*>(pr + col0 + cb + nj * 8) = o;
            }
        }
        __syncthreads();
    }
}

// ---------------- PV kernel: split-K x2, red.v4 into X (pre-init with feats) -----
// grid (8 row-tiles, 1, 32 = 16 batches x 2 k-halves); smem 2 stages x 32KB.
__global__ __launch_bounds__(256, 2)
void pv_k(const f16* __restrict__ sc_h, const f16* __restrict__ vt_h,
          float* __restrict__ X)
{
    extern __shared__ char sm[];
    const u32 sb = smem_u32(sm);
    const int z = blockIdx.z;
    const int b = z >> 1, kh = z & 1;
    const int row0 = blockIdx.x * 128;
    const f16* Ab = sc_h + (i64)b * NSEQ * NSEQ + kh * 512;
    const f16* Bb = vt_h + (i64)b * D * NSEQ + kh * 512;
    float* Xb = X + (i64)b * NSEQ * D;

    const int tid = threadIdx.x;
    const int wid = tid >> 5, lane = tid & 31;
    const int m0w = (wid >> 1) * 32, n0w = (wid & 1) * 64;
    const u32 a_rb = (u32)(m0w + (lane & 15)) * 128;
    const u32 b_rb = (u32)(n0w + ((lane >> 4) << 3) + (lane & 7)) * 128;
    const int a_hi = lane >> 4;
    const int b_hi = (lane >> 3) & 1;
    const int xr = lane & 7;
    const int r_ld = tid >> 1;
    const int c0_ld = (tid & 1) * 4;

    float acc[2][8][4];
    #pragma unroll
    for (int mi = 0; mi < 2; mi++)
        #pragma unroll
        for (int nj = 0; nj < 8; nj++)
            #pragma unroll
            for (int e = 0; e < 4; e++) acc[mi][nj][e] = 0.f;

    auto load_half = [&](int h, int s) {
        const int kofs = h * 64;
        const u32 base = sb + (u32)s * 32768u;
        const f16* ap = Ab + (i64)(row0 + r_ld) * NSEQ + kofs;
        const f16* bp = Bb + (i64)r_ld * NSEQ + kofs;
        #pragma unroll
        for (int j = 0; j < 4; j++) {
            int c = c0_ld + j;
            u32 so = (u32)r_ld * 128 + (u32)((c ^ (r_ld & 7)) << 4);
            cp16_cg(base + so,          ap + c * 8);
            cp16_ca(base + 16384u + so, bp + c * 8);
        }
        cp_commit();
    };

    load_half(0, 0);
    for (int h = 0; h < 8; h++) {
        const int s = h & 1;
        if (h < 7) { load_half(h + 1, 1 - s); cp_wait<1>(); }
        else       { cp_wait<0>(); }
        __syncthreads();
        const u32 base = sb + (u32)s * 32768u;
        const u32 abase = base + a_rb;
        const u32 bbase = base + 16384u + b_rb;
        #pragma unroll
        for (int ks = 0; ks < 4; ks++) {
            const u32 aoff = (u32)(((ks * 2 + a_hi) ^ xr) << 4);
            const u32 boff = (u32)(((ks * 2 + b_hi) ^ xr) << 4);
            u32 bf[4][4], a0[4], a1[4];
            #pragma unroll
            for (int p = 0; p < 4; p++)
                ldsm4(bf[p], bbase + boff + p * 2048);
            ldsm4(a0, abase + aoff);
            ldsm4(a1, abase + aoff + 2048);
            #pragma unroll
            for (int nj = 0; nj < 8; nj++) {
                u32 bb0 = bf[nj >> 1][(nj & 1) * 2], bb1 = bf[nj >> 1][(nj & 1) * 2 + 1];
                mma_f16(acc[0][nj], a0, bb0, bb1);
                mma_f16(acc[1][nj], a1, bb0, bb1);
            }
        }
        __syncthreads();
    }

    // pair-shfl -> red.v4 into X
    const int g = lane >> 2;
    const int q = lane & 3;
    const int cb = n0w + ((q >> 1) << 2);
    const bool evenlane = ((lane & 1) == 0);
    #pragma unroll
    for (int mi = 0; mi < 2; mi++) {
        int r1 = row0 + m0w + mi * 16 + g;
        float* pr = evenlane ? (Xb + (i64)r1 * D) : (Xb + (i64)(r1 + 8) * D);
        #pragma unroll
        for (int nj = 0; nj < 8; nj++) {
            float v0 = acc[mi][nj][0], v1 = acc[mi][nj][1];
            float v2 = acc[mi][nj][2], v3 = acc[mi][nj][3];
            float p0 = __shfl_xor_sync(0xffffffffu, v0, 1);
            float p1 = __shfl_xor_sync(0xffffffffu, v1, 1);
            float p2 = __shfl_xor_sync(0xffffffffu, v2, 1);
            float p3 = __shfl_xor_sync(0xffffffffu, v3, 1);
            if (evenlane) red4(pr + cb + nj * 8, v0, v1, p0, p1);
            else          red4(pr + cb + nj * 8, p2, p3, v2, v3);
        }
    }
}

// ---------------- persistent-B scatter kernel (includes ctr group) --------------
#define NTILES_SC 3840
#define CHUNK_SC 13
#define GRID_SC ((NTILES_SC + CHUNK_SC - 1) / CHUNK_SC)   // 296

__global__ __launch_bounds__(256, 2)
void layer_scatter_p(const f16* __restrict__ Xh,
                     const f16* __restrict__ wch,
                     const f16* __restrict__ wph, const f16* __restrict__ wsh,
                     const f16* __restrict__ wlh, const f16* __restrict__ wrh,
                     float* __restrict__ T,
                     const int* __restrict__ pre_u, const int* __restrict__ pre_v,
                     const int* __restrict__ suc_u, const int* __restrict__ suc_v,
                     const int* __restrict__ left_u, const int* __restrict__ left_v,
                     const int* __restrict__ right_u, const int* __restrict__ right_v)
{
    extern __shared__ char sm[];
    const u32 sb = smem_u32(sm);
    const int t0 = blockIdx.x * CHUNK_SC;
    const int t1 = (t0 + CHUNK_SC < NTILES_SC) ? t0 + CHUNK_SC : NTILES_SC;
    if (t0 >= NTILES_SC) return;

    const int tid = threadIdx.x;
    const int wid = tid >> 5, lane = tid & 31;
    const int m0w = (wid >> 1) * 32, n0w = (wid & 1) * 64;
    const u32 a_rb = (u32)(m0w + (lane & 15)) * 128;
    const u32 b_rb = (u32)(n0w + ((lane >> 4) << 3) + (lane & 7)) * 128;
    const int a_hi = lane >> 4;
    const int b_hi = (lane >> 3) & 1;
    const int xr = lane & 7;
    const int r_ld = tid >> 1;
    const int c0_ld = (tid & 1) * 4;

    auto group_of = [&](int t, const f16*& Bw, const int*& gv, const int*& su, int& base) {
        int g = t >> 8, e = (t & 255) * 128;
        base = e;
        if (g == 0)       { Bw = wch; gv = 0; su = 0; }
        else if (g < 7)   { int z = g - 1; Bw = wph + (i64)z * DD; gv = pre_v + z * NE + e; su = pre_u + z * NE + e; }
        else if (g < 13)  { int z = g - 7; Bw = wsh + (i64)z * DD; gv = suc_v + z * NE + e; su = suc_u + z * NE + e; }
        else if (g == 13) { Bw = wlh; gv = left_v + e; su = left_u + e; }
        else              { Bw = wrh; gv = right_v + e; su = right_u + e; }
    };

    auto load_B = [&](const f16* Bw) {
        const f16* bp = Bw + (i64)r_ld * D;
        #pragma unroll
        for (int h = 0; h < 2; h++) {
            const u32 base = sb + 32768u + (u32)h * 16384u;
            #pragma unroll
            for (int j = 0; j < 4; j++) {
                int c = c0_ld + j;
                u32 so = (u32)r_ld * 128 + (u32)((c ^ (r_ld & 7)) << 4);
                cp16_ca(base + so, bp + h * 64 + c * 8);
            }
        }
        cp_commit();
    };
    auto load_A = [&](const int* gv, int base_row, int h, int s) {
        i64 arow = gv ? (i64)__ldg(gv + r_ld) : (i64)(base_row + r_ld);
        const f16* ap = Xh + arow * D + h * 64;
        const u32 base = sb + (u32)s * 16384u;
        #pragma unroll
        for (int j = 0; j < 4; j++) {
            int c = c0_ld + j;
            u32 so = (u32)r_ld * 128 + (u32)((c ^ (r_ld & 7)) << 4);
            cp16_cg(base + so, ap + c * 8);
        }
        cp_commit();
    };

    const int g = lane >> 2;
    const int q = lane & 3;
    const int cb = n0w + ((q >> 1) << 2);
    const bool evenlane = ((lane & 1) == 0);
    const f16* Bw; const int* gv; const int* su; int base_row;
    group_of(t0, Bw, gv, su, base_row);
    int curg = t0 >> 8;
    load_B(Bw);
    load_A(gv, base_row, 0, 0);
    load_A(gv, base_row, 1, 1);

    for (int t = t0; t < t1; t++) {
        const f16* Bw_n = 0; const int* gv_n = 0; const int* su_n = 0; int base_n = 0;
        const bool have_next = (t + 1 < t1);
        int g_n = curg;
        if (have_next) { group_of(t + 1, Bw_n, gv_n, su_n, base_n); g_n = (t + 1) >> 8; }
        const bool pref0 = have_next && (g_n == curg);

        float acc[2][8][4];
        #pragma unroll
        for (int mi = 0; mi < 2; mi++)
            #pragma unroll
            for (int nj = 0; nj < 8; nj++)
                #pragma unroll
                for (int e = 0; e < 4; e++) acc[mi][nj][e] = 0.f;

        // half 0
        cp_wait<1>(); __syncthreads();
        {
            const u32 abase = sb + a_rb;
            const u32 bbase = sb + 32768u + b_rb;
            #pragma unroll
            for (int ks = 0; ks < 4; ks++) {
                const u32 aoff = (u32)(((ks * 2 + a_hi) ^ xr) << 4);
                const u32 boff = (u32)(((ks * 2 + b_hi) ^ xr) << 4);
                u32 b[4][4], a0[4], a1[4];
                #pragma unroll
                for (int p = 0; p < 4; p++)
                    ldsm4(b[p], bbase + boff + p * 2048);
                ldsm4(a0, abase + aoff);
                ldsm4(a1, abase + aoff + 2048);
                #pragma unroll
                for (int nj = 0; nj < 8; nj++) {
                    u32 bb0 = b[nj >> 1][(nj & 1) * 2], bb1 = b[nj >> 1][(nj & 1) * 2 + 1];
                    mma_f16(acc[0][nj], a0, bb0, bb1);
                    mma_f16(acc[1][nj], a1, bb0, bb1);
                }
            }
        }
        __syncthreads();
        if (pref0) load_A(gv_n, base_n, 0, 0);

        // half 1
        if (pref0) cp_wait<1>(); else cp_wait<0>();
        __syncthreads();
        {
            const u32 abase = sb + 16384u + a_rb;
            const u32 bbase = sb + 49152u + b_rb;
            #pragma unroll
            for (int ks = 0; ks < 4; ks++) {
                const u32 aoff = (u32)(((ks * 2 + a_hi) ^ xr) << 4);
                const u32 boff = (u32)(((ks * 2 + b_hi) ^ xr) << 4);
                u32 b[4][4], a0[4], a1[4];
                #pragma unroll
                for (int p = 0; p < 4; p++)
                    ldsm4(b[p], bbase + boff + p * 2048);
                ldsm4(a0, abase + aoff);
                ldsm4(a1, abase + aoff + 2048);
                #pragma unroll
                for (int nj = 0; nj < 8; nj++) {
                    u32 bb0 = b[nj >> 1][(nj & 1) * 2], bb1 = b[nj >> 1][(nj & 1) * 2 + 1];
                    mma_f16(acc[0][nj], a0, bb0, bb1);
                    mma_f16(acc[1][nj], a1, bb0, bb1);
                }
            }
        }

        #pragma unroll
        for (int mi = 0; mi < 2; mi++) {
            int lr1 = m0w + mi * 16 + g;
            i64 dr1 = su ? (i64)__ldg(su + lr1)     : (i64)(base_row + lr1);
            i64 dr2 = su ? (i64)__ldg(su + lr1 + 8) : (i64)(base_row + lr1 + 8);
            float* pr = evenlane ? (T + dr1 * D) : (T + dr2 * D);
            #pragma unroll
            for (int nj = 0; nj < 8; nj++) {
                float v0 = acc[mi][nj][0], v1 = acc[mi][nj][1];
                float v2 = acc[mi][nj][2], v3 = acc[mi][nj][3];
                float p0 = __shfl_xor_sync(0xffffffffu, v0, 1);
                float p1 = __shfl_xor_sync(0xffffffffu, v1, 1);
                float p2 = __shfl_xor_sync(0xffffffffu, v2, 1);
                float p3 = __shfl_xor_sync(0xffffffffu, v3, 1);
                if (evenlane) red4(pr + cb + nj * 8, v0, v1, p0, p1);
                else          red4(pr + cb + nj * 8, p2, p3, v2, v3);
            }
        }
        __syncthreads();

        if (have_next) {
            if (g_n == curg) {
                load_A(gv_n, base_n, 1, 1);
            } else {
                cp_wait<0>(); __syncthreads();
                load_B(Bw_n);
                load_A(gv_n, base_n, 0, 0);
                load_A(gv_n, base_n, 1, 1);
                curg = g_n;
            }
            gv = gv_n; su = su_n; base_row = base_n;
        }
    }
}

// ---------------- small kernels ----------------------------------------------------
#define NSEG 11
struct CvtArgs {
    const float4* src[NSEG];
    uint2* dst[NSEG];
    int n4[NSEG];
};
__global__ __launch_bounds__(256)
void cvt_all(CvtArgs a)
{
    const int seg = blockIdx.y;
    const int i = blockIdx.x * 256 + threadIdx.x;
    if (i < a.n4[seg]) a.dst[seg][i] = cvt4(a.src[seg][i]);
}
__global__ __launch_bounds__(256)
void zero_T(float4* p)
{
    p[blockIdx.x * 256 + threadIdx.x] = make_float4(0.f, 0.f, 0.f, 0.f);
}
__global__ __launch_bounds__(256)
void copy4_k(float4* __restrict__ dst, const float4* __restrict__ src)
{
    const int i = blockIdx.x * 256 + threadIdx.x;
    dst[i] = src[i];
}
__global__ __launch_bounds__(256)
void cvtX_k(const float4* __restrict__ X, uint2* __restrict__ xh)
{
    const int i = blockIdx.x * 256 + threadIdx.x;
    xh[i] = cvt4(X[i]);
}

// row softmax over 1024, emit fp16
__global__ __launch_bounds__(256)
void softmax_k(const float* __restrict__ Sc, f16* __restrict__ oh)
{
    i64 row = blockIdx.x;
    const float4* p = reinterpret_cast<const float4*>(Sc + row * NSEQ);
    int t = threadIdx.x;
    float4 v = p[t];
    float mx = fmaxf(fmaxf(v.x, v.y), fmaxf(v.z, v.w));
    #pragma unroll
    for (int o = 16; o; o >>= 1) mx = fmaxf(mx, __shfl_xor_sync(0xffffffffu, mx, o));
    __shared__ float red8[8];
    int w = t >> 5;
    if ((t & 31) == 0) red8[w] = mx;
    __syncthreads();
    mx = red8[0];
    #pragma unroll
    for (int i = 1; i < 8; i++) mx = fmaxf(mx, red8[i]);
    v.x = expf(v.x - mx); v.y = expf(v.y - mx);
    v.z = expf(v.z - mx); v.w = expf(v.w - mx);
    float s = v.x + v.y + v.z + v.w;
    #pragma unroll
    for (int o = 16; o; o >>= 1) s += __shfl_xor_sync(0xffffffffu, s, o);
    __syncthreads();
    if ((t & 31) == 0) red8[w] = s;
    __syncthreads();
    s = red8[0] + red8[1] + red8[2] + red8[3] + red8[4] + red8[5] + red8[6] + red8[7];
    float inv = 1.0f / s;
    v.x *= inv; v.y *= inv; v.z *= inv; v.w *= inv;
    *reinterpret_cast<uint2*>(oh + row * NSEQ + t * 4) = cvt4(v);
}

// gn1: warp-per-row; zeroes T in place for the next layer
__global__ __launch_bounds__(256)
void gn1_kernel(float* __restrict__ T, f16* __restrict__ outh,
                const float* __restrict__ gw, const float* __restrict__ bw)
{
    const int row = blockIdx.x * 8 + (threadIdx.x >> 5);
    const int lane = threadIdx.x & 31;
    const i64 ro = (i64)row * D + lane * 4;
    float4 v = *reinterpret_cast<const float4*>(T + ro);
    float s1 = v.x + v.y + v.z + v.w;
    float s2 = v.x * v.x + v.y * v.y + v.z * v.z + v.w * v.w;
    #pragma unroll
    for (int o = 16; o; o >>= 1) {
        s1 += __shfl_xor_sync(0xffffffffu, s1, o);
        s2 += __shfl_xor_sync(0xffffffffu, s2, o);
    }
    const float mu = s1 * (1.f / 128.f);
    const float var = s2 * (1.f / 128.f) - mu * mu;
    const float rstd = rsqrtf(var + 1e-5f);
    float4 g4 = *reinterpret_cast<const float4*>(gw + lane * 4);
    float4 b4 = *reinterpret_cast<const float4*>(bw + lane * 4);
    float4 y;
    y.x = fmaxf((v.x - mu) * rstd * g4.x + b4.x, 0.f);
    y.y = fmaxf((v.y - mu) * rstd * g4.y + b4.y, 0.f);
    y.z = fmaxf((v.z - mu) * rstd * g4.z + b4.z, 0.f);
    y.w = fmaxf((v.w - mu) * rstd * g4.w + b4.w, 0.f);
    *reinterpret_cast<uint2*>(outh + ro) = cvt4(y);
    *reinterpret_cast<float4*>(T + ro) = make_float4(0.f, 0.f, 0.f, 0.f);
}

// ---------------- driver ---------------------------------------------------------
#define SMEM_GN 67584   // gemm_gn2 / qkv: 64KB tiles + 66KB staging overlap
#define SMEM_QK 98304   // qk: A 32KB + 2x32KB B stages
#define SMEM_PV 65536   // pv: 2 stages x 32KB
#define SMEM_SC 65536   // scatter: 2x16KB A + 32KB B

extern "C" void kernel_launch(void* const* d_in, const int* in_sizes, int n_in,
                              void* d_out, int out_size)
{
    (void)in_sizes; (void)n_in; (void)out_size;
    const float* ctrs   = (const float*)d_in[0];
    const float* feats  = (const float*)d_in[1];
    const float* Wq     = (const float*)d_in[2];
    const float* Wk     = (const float*)d_in[3];
    const float* Wv     = (const float*)d_in[4];
    const float* Wc     = (const float*)d_in[5];
    const float* Wp     = (const float*)d_in[6];
    const float* Ws     = (const float*)d_in[7];
    const float* Wl     = (const float*)d_in[8];
    const float* Wr     = (const float*)d_in[9];
    const float* Wc2    = (const float*)d_in[10];
    const float* g1     = (const float*)d_in[11];
    const float* b1     = (const float*)d_in[12];
    const float* g2     = (const float*)d_in[13];
    const float* b2     = (const float*)d_in[14];
    const int* pre_u    = (const int*)d_in[15];
    const int* pre_v    = (const int*)d_in[16];
    const int* suc_u    = (const int*)d_in[17];
    const int* suc_v    = (const int*)d_in[18];
    const int* left_u   = (const int*)d_in[19];
    const int* left_v   = (const int*)d_in[20];
    const int* right_u  = (const int*)d_in[21];
    const int* right_v  = (const int*)d_in[22];
    float* X = (float*)d_out;

    float *sc, *T;
    cudaGetSymbolAddress((void**)&sc, g_sc);
    cudaGetSymbolAddress((void**)&T,  g_T);
    f16 *ctrs_h, *feat_h, *q_h, *k_h, *vt_h, *x_h, *y_h, *sc_h;
    f16 *wq_h, *wk_h, *wv_h, *wc_h, *wp_h, *ws_h, *wl_h, *wr_h, *w2_h;
    cudaGetSymbolAddress((void**)&ctrs_h, s_ctrs_h);
    cudaGetSymbolAddress((void**)&feat_h, s_feat_h);
    cudaGetSymbolAddress((void**)&q_h, s_q_h);
    cudaGetSymbolAddress((void**)&k_h, s_k_h);
    cudaGetSymbolAddress((void**)&vt_h, s_vt_h);
    cudaGetSymbolAddress((void**)&x_h, s_x_h);
    cudaGetSymbolAddress((void**)&y_h, s_y_h);
    cudaGetSymbolAddress((void**)&sc_h, s_sc_h);
    cudaGetSymbolAddress((void**)&wq_h, s_wq_h);
    cudaGetSymbolAddress((void**)&wk_h, s_wk_h);
    cudaGetSymbolAddress((void**)&wv_h, s_wv_h);
    cudaGetSymbolAddress((void**)&wc_h, s_wc_h);
    cudaGetSymbolAddress((void**)&wp_h, s_wp_h);
    cudaGetSymbolAddress((void**)&ws_h, s_ws_h);
    cudaGetSymbolAddress((void**)&wl_h, s_wl_h);
    cudaGetSymbolAddress((void**)&wr_h, s_wr_h);
    cudaGetSymbolAddress((void**)&w2_h, s_w2_h);

    cudaFuncSetAttribute((const void*)gemm_gn2_k, cudaFuncAttributeMaxDynamicSharedMemorySize, SMEM_GN);
    cudaFuncSetAttribute((const void*)qkv_k, cudaFuncAttributeMaxDynamicSharedMemorySize, SMEM_GN);
    cudaFuncSetAttribute((const void*)qk_k, cudaFuncAttributeMaxDynamicSharedMemorySize, SMEM_QK);
    cudaFuncSetAttribute((const void*)pv_k, cudaFuncAttributeMaxDynamicSharedMemorySize, SMEM_PV);
    cudaFuncSetAttribute((const void*)layer_scatter_p, cudaFuncAttributeMaxDynamicSharedMemorySize, SMEM_SC);

    const float NF = 0.08838834764831845f;  // 1/sqrt(128)
    dim3 blk(256);

    // ---- conversions + T zero + X init ----
    CvtArgs ca;
    const float* srcs[NSEG] = {ctrs, feats, Wq, Wk, Wv, Wc, Wp, Ws, Wl, Wr, Wc2};
    f16* dsts[NSEG] = {ctrs_h, feat_h, wq_h, wk_h, wv_h, wc_h, wp_h, ws_h, wl_h, wr_h, w2_h};
    const int ns[NSEG] = {M_ROWS*D, M_ROWS*D, DD, DD, DD, NL*DD, NL*NS*DD, NL*NS*DD, NL*DD, NL*DD, NL*DD};
    int maxn4 = 0;
    for (int i = 0; i < NSEG; i++) {
        ca.src[i] = (const float4*)srcs[i];
        ca.dst[i] = (uint2*)dsts[i];
        ca.n4[i] = ns[i] / 4;
        if (ca.n4[i] > maxn4) maxn4 = ca.n4[i];
    }
    cvt_all<<<dim3((maxn4 + 255) / 256, NSEG), 256>>>(ca);
    zero_T<<<M_ROWS * D / 4 / 256, 256>>>((float4*)T);
    copy4_k<<<M_ROWS * D / 4 / 256, 256>>>((float4*)X, (const float4*)feats);

    // ---- attention ----
    qkv_k<<<dim3(128, 1, 3), blk, SMEM_GN>>>(ctrs_h, feat_h, wq_h, wk_h, wv_h, q_h, k_h, vt_h);
    qk_k<<<dim3(8, 2, 16), blk, SMEM_QK>>>(q_h, k_h, sc, NF);
    softmax_k<<<M_ROWS, 256>>>(sc, sc_h);
    pv_k<<<dim3(8, 1, 32), blk, SMEM_PV>>>(sc_h, vt_h, X);
    cvtX_k<<<M_ROWS * D / 4 / 256, 256>>>((const float4*)X, (uint2*)x_h);

    // ---- 4-layer fusion loop ----
    for (int i = 0; i < NL; i++) {
        layer_scatter_p<<<GRID_SC, blk, SMEM_SC>>>(
            x_h,
            wc_h + (i64)i*DD,
            wp_h + (i64)i*NS*DD,
            ws_h + (i64)i*NS*DD,
            wl_h + (i64)i*DD,
            wr_h + (i64)i*DD,
            T, pre_u, pre_v, suc_u, suc_v, left_u, left_v, right_u, right_v);
        gn1_kernel<<<M_ROWS / 8, 256>>>(T, y_h, g1 + i*D, b1 + i*D);
        gemm_gn2_k<<<dim3(128, 1, 1), blk, SMEM_GN>>>(
            y_h, w2_h + (i64)i*DD, X, x_h, X, g2 + i*D, b2 + i*D);
    }
}

// round 13
// speedup vs baseline: 2.2320x; 1.0197x over previous
#include <cuda_runtime.h>
#include <cuda_fp16.h>
#include <math.h>
#include <stdint.h>

#define D 128
#define DD 16384
#define BATCH 16
#define NSEQ 1024
#define M_ROWS 16384
#define NE 32768
#define NS 6
#define NL 4

typedef unsigned long long u64;
typedef unsigned int u32;
typedef long long i64;
typedef __half f16;

// ---------------- scratch (fp32) ---------------------------------------------
__device__ __align__(256) float g_sc[(size_t)BATCH * NSEQ * NSEQ];
__device__ __align__(256) float g_T [M_ROWS * D];

// ---------------- scratch (fp16) -----------------------------------------------
__device__ __align__(256) f16 s_ctrs_h[M_ROWS*D];
__device__ __align__(256) f16 s_feat_h[M_ROWS*D];
__device__ __align__(256) f16 s_q_h[M_ROWS*D];
__device__ __align__(256) f16 s_k_h[M_ROWS*D];
__device__ __align__(256) f16 s_vt_h[M_ROWS*D];
__device__ __align__(256) f16 s_x_h[M_ROWS*D];
__device__ __align__(256) f16 s_sc_h[(size_t)BATCH*NSEQ*NSEQ];
__device__ __align__(256) f16 s_wq_h[DD], s_wk_h[DD], s_wv_h[DD];
__device__ __align__(256) f16 s_wc_h[NL*DD];
__device__ __align__(256) f16 s_wp_h[NL*NS*DD];
__device__ __align__(256) f16 s_ws_h[NL*NS*DD];
__device__ __align__(256) f16 s_wl_h[NL*DD];
__device__ __align__(256) f16 s_wr_h[NL*DD];
__device__ __align__(256) f16 s_w2_h[NL*DD];

// ---------------- PTX helpers ------------------------------------------------
__device__ __forceinline__ u32 smem_u32(const void* p) {
    u32 a;
    asm("{ .reg .u64 t; cvta.to.shared.u64 t, %1; cvt.u32.u64 %0, t; }" : "=r"(a) : "l"(p));
    return a;
}
__device__ __forceinline__ void ldsm4(u32* r, u32 addr) {
    asm volatile("ldmatrix.sync.aligned.m8n8.x4.shared.b16 {%0,%1,%2,%3}, [%4];"
                 : "=r"(r[0]), "=r"(r[1]), "=r"(r[2]), "=r"(r[3]) : "r"(addr));
}
__device__ __forceinline__ void mma_f16(float* d, const u32* a, u32 b0, u32 b1) {
    asm volatile("mma.sync.aligned.m16n8k16.row.col.f32.f16.f16.f32 "
                 "{%0,%1,%2,%3}, {%4,%5,%6,%7}, {%8,%9}, {%0,%1,%2,%3};"
                 : "+f"(d[0]), "+f"(d[1]), "+f"(d[2]), "+f"(d[3])
                 : "r"(a[0]), "r"(a[1]), "r"(a[2]), "r"(a[3]), "r"(b0), "r"(b1));
}
__device__ __forceinline__ void red4(float* p, float a, float b, float c, float d) {
    asm volatile("red.global.add.v4.f32 [%0], {%1,%2,%3,%4};"
                 :: "l"(p), "f"(a), "f"(b), "f"(c), "f"(d) : "memory");
}
__device__ __forceinline__ void cp16_cg(u32 dst, const void* src) {
    asm volatile("cp.async.cg.shared.global [%0], [%1], 16;" :: "r"(dst), "l"(src));
}
__device__ __forceinline__ void cp16_ca(u32 dst, const void* src) {
    asm volatile("cp.async.ca.shared.global [%0], [%1], 16;" :: "r"(dst), "l"(src));
}
__device__ __forceinline__ void cp_commit() { asm volatile("cp.async.commit_group;" ::: "memory"); }
template<int N> __device__ __forceinline__ void cp_wait() {
    asm volatile("cp.async.wait_group %0;" :: "n"(N) : "memory");
}
__device__ __forceinline__ uint2 cvt4(float4 v) {
    __half2 h0 = __floats2half2_rn(v.x, v.y);
    __half2 h1 = __floats2half2_rn(v.z, v.w);
    return make_uint2(*(u32*)&h0, *(u32*)&h1);
}

// =====================================================================
// MMA fragment compute over one resident 128-K tile pair (two halves).
// =====================================================================
__device__ __forceinline__ void compute_tile(
    float acc[2][8][4], u32 abase0, u32 bbase0, int a_hi, int b_hi, int xr)
{
    #pragma unroll
    for (int h = 0; h < 2; h++) {
        const u32 abase = abase0 + (u32)h * 16384u;
        const u32 bbase = bbase0 + (u32)h * 16384u;
        #pragma unroll
        for (int ks = 0; ks < 4; ks++) {
            const u32 aoff = (u32)(((ks * 2 + a_hi) ^ xr) << 4);
            const u32 boff = (u32)(((ks * 2 + b_hi) ^ xr) << 4);
            u32 b[4][4], a0[4], a1[4];
            #pragma unroll
            for (int p = 0; p < 4; p++)
                ldsm4(b[p], bbase + boff + p * 2048);
            ldsm4(a0, abase + aoff);
            ldsm4(a1, abase + aoff + 2048);
            #pragma unroll
            for (int nj = 0; nj < 8; nj++) {
                u32 bb0 = b[nj >> 1][(nj & 1) * 2], bb1 = b[nj >> 1][(nj & 1) * 2 + 1];
                mma_f16(acc[0][nj], a0, bb0, bb1);
                mma_f16(acc[1][nj], a1, bb0, bb1);
            }
        }
    }
}

// ---------------- fused gn1 + ctr2 GEMM + gn2 kernel -----------------------------
// A = fp16(relu(GN1(T_row))), built in-kernel; zeroes T for next layer.
// C epilogue: GN2 + residual(X) + relu -> X (fp32) + x_h (fp16).
__global__ __launch_bounds__(256, 2)
void gemm_gn12_k(float* __restrict__ T,
                 const f16* __restrict__ Bh,
                 float* __restrict__ X, f16* __restrict__ Ch,
                 const float* __restrict__ g1w, const float* __restrict__ b1w,
                 const float* __restrict__ g2w, const float* __restrict__ b2w)
{
    extern __shared__ char sm[];
    const u32 sb = smem_u32(sm);
    const int row0 = blockIdx.x * 128;
    const int tid = threadIdx.x;
    const int wid = tid >> 5, lane = tid & 31;
    const int m0w = (wid >> 1) * 32, n0w = (wid & 1) * 64;
    const int r_ld = tid >> 1;
    const int hh_ld = tid & 1;

    // B (w2) both halves via cp.async (swizzled)
    {
        const f16* bp = Bh + (i64)r_ld * D;
        #pragma unroll
        for (int h = 0; h < 2; h++)
            #pragma unroll
            for (int j = 0; j < 4; j++) {
                int c = hh_ld * 4 + j;
                u32 so = (u32)r_ld * 128 + (u32)((c ^ (r_ld & 7)) << 4);
                cp16_ca(sb + 32768u + (u32)h * 16384u + so, bp + h * 64 + c * 8);
            }
        cp_commit();
    }

    // T rows -> GN1 + relu -> fp16 A smem; zero T in place
    {
        float* Tp = T + (i64)(row0 + r_ld) * D + hh_ld * 64;
        float4 tv[16];
        float s1 = 0.f, s2 = 0.f;
        #pragma unroll
        for (int j = 0; j < 16; j++) {
            tv[j] = *reinterpret_cast<const float4*>(Tp + j * 4);
            s1 += tv[j].x + tv[j].y + tv[j].z + tv[j].w;
            s2 += tv[j].x * tv[j].x + tv[j].y * tv[j].y + tv[j].z * tv[j].z + tv[j].w * tv[j].w;
        }
        s1 += __shfl_xor_sync(0xffffffffu, s1, 1);
        s2 += __shfl_xor_sync(0xffffffffu, s2, 1);
        const float mu = s1 * (1.f / 128.f);
        const float var = s2 * (1.f / 128.f) - mu * mu;
        const float rstd = rsqrtf(var + 1e-5f);
        const float* gp = g1w + hh_ld * 64;
        const float* bp = b1w + hh_ld * 64;
        #pragma unroll
        for (int j = 0; j < 16; j++) {
            float4 g4 = *reinterpret_cast<const float4*>(gp + j * 4);
            float4 b4 = *reinterpret_cast<const float4*>(bp + j * 4);
            float4 y;
            y.x = fmaxf((tv[j].x - mu) * rstd * g4.x + b4.x, 0.f);
            y.y = fmaxf((tv[j].y - mu) * rstd * g4.y + b4.y, 0.f);
            y.z = fmaxf((tv[j].z - mu) * rstd * g4.z + b4.z, 0.f);
            y.w = fmaxf((tv[j].w - mu) * rstd * g4.w + b4.w, 0.f);
            int c = j >> 1;
            u32 so = (u32)r_ld * 128 + (u32)((c ^ (r_ld & 7)) << 4) + (u32)(j & 1) * 8;
            *reinterpret_cast<uint2*>(sm + hh_ld * 16384 + so) = cvt4(y);
            *reinterpret_cast<float4*>(Tp + j * 4) = make_float4(0.f, 0.f, 0.f, 0.f);
        }
    }
    cp_wait<0>();
    __syncthreads();

    float acc[2][8][4];
    #pragma unroll
    for (int mi = 0; mi < 2; mi++)
        #pragma unroll
        for (int nj = 0; nj < 8; nj++)
            #pragma unroll
            for (int e = 0; e < 4; e++) acc[mi][nj][e] = 0.f;

    const u32 a_rb = (u32)(m0w + (lane & 15)) * 128;
    const u32 b_rb = (u32)(n0w + ((lane >> 4) << 3) + (lane & 7)) * 128;
    const int a_hi = lane >> 4;
    const int b_hi = (lane >> 3) & 1;
    const int xr = lane & 7;
    compute_tile(acc, sb + a_rb, sb + 32768u + b_rb, a_hi, b_hi, xr);
    __syncthreads();

    // stage to SMEM (pitch 132) for row-wise GN2
    float* Cs = reinterpret_cast<float*>(sm);
    const int g = lane >> 2, q2 = (lane & 3) * 2;
    #pragma unroll
    for (int mi = 0; mi < 2; mi++)
        #pragma unroll
        for (int nj = 0; nj < 8; nj++) {
            int r = m0w + mi * 16 + g;
            int c = n0w + nj * 8 + q2;
            Cs[r * 132 + c]           = acc[mi][nj][0];
            Cs[r * 132 + c + 1]       = acc[mi][nj][1];
            Cs[(r + 8) * 132 + c]     = acc[mi][nj][2];
            Cs[(r + 8) * 132 + c + 1] = acc[mi][nj][3];
        }
    __syncthreads();

    const int rr = tid >> 1, hh = tid & 1;
    const float* srow = Cs + rr * 132 + hh * 64;
    float s1 = 0.f, s2 = 0.f;
    #pragma unroll
    for (int j = 0; j < 16; j++) {
        float4 vv = *reinterpret_cast<const float4*>(srow + j * 4);
        s1 += vv.x + vv.y + vv.z + vv.w;
        s2 += vv.x * vv.x + vv.y * vv.y + vv.z * vv.z + vv.w * vv.w;
    }
    s1 += __shfl_xor_sync(0xffffffffu, s1, 1);
    s2 += __shfl_xor_sync(0xffffffffu, s2, 1);
    const float mu = s1 * (1.f / 128.f);
    const float var = s2 * (1.f / 128.f) - mu * mu;
    const float rstd = rsqrtf(var + 1e-5f);
    const i64 ro = (i64)(row0 + rr) * D + hh * 64;
    float* p = X + ro;
    const float* gp = g2w + hh * 64;
    const float* bp = b2w + hh * 64;
    #pragma unroll
    for (int j = 0; j < 16; j++) {
        float4 vv = *reinterpret_cast<const float4*>(srow + j * 4);
        float4 g4 = *reinterpret_cast<const float4*>(gp + j * 4);
        float4 b4 = *reinterpret_cast<const float4*>(bp + j * 4);
        float4 f4 = *reinterpret_cast<const float4*>(p + j * 4);
        vv.x = fmaxf((vv.x - mu) * rstd * g4.x + b4.x + f4.x, 0.f);
        vv.y = fmaxf((vv.y - mu) * rstd * g4.y + b4.y + f4.y, 0.f);
        vv.z = fmaxf((vv.z - mu) * rstd * g4.z + b4.z + f4.z, 0.f);
        vv.w = fmaxf((vv.w - mu) * rstd * g4.w + b4.w + f4.w, 0.f);
        *reinterpret_cast<float4*>(p + j * 4) = vv;
        *reinterpret_cast<uint2*>(Ch + ro + j * 4) = cvt4(vv);
    }
}

// ---------------- fused QKV kernel (z=0:Q, z=1:K, z=2:V->transposed) ------------
__global__ __launch_bounds__(256, 2)
void qkv_k(const f16* __restrict__ ctrs_h, const f16* __restrict__ feat_h,
           const f16* __restrict__ wq, const f16* __restrict__ wk, const f16* __restrict__ wv,
           f16* __restrict__ q_h, f16* __restrict__ k_h, f16* __restrict__ vt_h)
{
    extern __shared__ char sm[];
    const u32 sb = smem_u32(sm);
    const int z = blockIdx.z;
    const int row0 = blockIdx.x * 128;
    const f16* Ah = (z == 0) ? ctrs_h : feat_h;
    const f16* Bh = (z == 0) ? wq : (z == 1) ? wk : wv;

    const int tid = threadIdx.x;
    const int wid = tid >> 5, lane = tid & 31;
    const int m0w = (wid >> 1) * 32, n0w = (wid & 1) * 64;

    float acc[2][8][4];
    #pragma unroll
    for (int mi = 0; mi < 2; mi++)
        #pragma unroll
        for (int nj = 0; nj < 8; nj++)
            #pragma unroll
            for (int e = 0; e < 4; e++) acc[mi][nj][e] = 0.f;

    const u32 a_rb = (u32)(m0w + (lane & 15)) * 128;
    const u32 b_rb = (u32)(n0w + ((lane >> 4) << 3) + (lane & 7)) * 128;
    const int a_hi = lane >> 4;
    const int b_hi = (lane >> 3) & 1;
    const int xr = lane & 7;
    const int r_ld = tid >> 1;
    const int c0_ld = (tid & 1) * 4;

    {
        const f16* ap = Ah + (i64)(row0 + r_ld) * D;
        const f16* bp = Bh + (i64)r_ld * D;
        #pragma unroll
        for (int h = 0; h < 2; h++)
            #pragma unroll
            for (int j = 0; j < 4; j++) {
                int c = c0_ld + j;
                u32 so = (u32)r_ld * 128 + (u32)((c ^ (r_ld & 7)) << 4);
                cp16_cg(sb + (u32)h * 16384u + so,          ap + h * 64 + c * 8);
                cp16_ca(sb + 32768u + (u32)h * 16384u + so, bp + h * 64 + c * 8);
            }
        cp_commit();
    }
    cp_wait<0>();
    __syncthreads();
    compute_tile(acc, sb + a_rb, sb + 32768u + b_rb, a_hi, b_hi, xr);
    __syncthreads();

    float* Cs = reinterpret_cast<float*>(sm);
    const int g = lane >> 2, q2 = (lane & 3) * 2;
    #pragma unroll
    for (int mi = 0; mi < 2; mi++)
        #pragma unroll
        for (int nj = 0; nj < 8; nj++) {
            int r = m0w + mi * 16 + g;
            int c = n0w + nj * 8 + q2;
            Cs[r * 132 + c]           = acc[mi][nj][0];
            Cs[r * 132 + c + 1]       = acc[mi][nj][1];
            Cs[(r + 8) * 132 + c]     = acc[mi][nj][2];
            Cs[(r + 8) * 132 + c + 1] = acc[mi][nj][3];
        }
    __syncthreads();

    if (z < 2) {
        f16* out = (z == 0) ? q_h : k_h;
        const int rr = tid >> 1, hh = tid & 1;
        const float* srow = Cs + rr * 132 + hh * 64;
        const i64 ro = (i64)(row0 + rr) * D + hh * 64;
        #pragma unroll
        for (int j = 0; j < 16; j++) {
            float4 vv = *reinterpret_cast<const float4*>(srow + j * 4);
            *reinterpret_cast<uint2*>(out + ro + j * 4) = cvt4(vv);
        }
    } else {
        const int d = tid >> 1, hh = tid & 1;
        const int jg0 = row0 + hh * 64;
        const int b = jg0 >> 10, jin = jg0 & 1023;
        f16* dst = vt_h + (i64)b * D * NSEQ + (i64)d * NSEQ + jin;
        #pragma unroll
        for (int j = 0; j < 64; j += 2) {
            float a0 = Cs[(hh * 64 + j) * 132 + d];
            float a1 = Cs[(hh * 64 + j + 1) * 132 + d];
            __half2 hv = __floats2half2_rn(a0, a1);
            *reinterpret_cast<u32*>(dst + j) = *(u32*)&hv;
        }
    }
}

// ---------------- QK scores kernel: A-resident, 4 B tiles streamed ---------------
__global__ __launch_bounds__(256, 2)
void qk_k(const f16* __restrict__ q_h, const f16* __restrict__ k_h,
          float* __restrict__ sc, float scale)
{
    extern __shared__ char sm[];
    const u32 sb = smem_u32(sm);
    const int z = blockIdx.z;
    const int row0 = blockIdx.x * 128;
    const int cg0 = blockIdx.y * 4;
    const f16* Ab = q_h + (i64)z * NSEQ * D;
    const f16* Bb = k_h + (i64)z * NSEQ * D;
    float* Cb = sc + (i64)z * NSEQ * NSEQ;

    const int tid = threadIdx.x;
    const int wid = tid >> 5, lane = tid & 31;
    const int m0w = (wid >> 1) * 32, n0w = (wid & 1) * 64;
    const u32 a_rb = (u32)(m0w + (lane & 15)) * 128;
    const u32 b_rb = (u32)(n0w + ((lane >> 4) << 3) + (lane & 7)) * 128;
    const int a_hi = lane >> 4;
    const int b_hi = (lane >> 3) & 1;
    const int xr = lane & 7;
    const int r_ld = tid >> 1;
    const int c0_ld = (tid & 1) * 4;

    {
        const f16* ap = Ab + (i64)(row0 + r_ld) * D;
        #pragma unroll
        for (int h = 0; h < 2; h++)
            #pragma unroll
            for (int j = 0; j < 4; j++) {
                int c = c0_ld + j;
                u32 so = (u32)r_ld * 128 + (u32)((c ^ (r_ld & 7)) << 4);
                cp16_cg(sb + (u32)h * 16384u + so, ap + h * 64 + c * 8);
            }
        cp_commit();
    }
    auto load_B = [&](int ct, int s) {
        const f16* bp = Bb + (i64)(ct * 128 + r_ld) * D;
        const u32 base = sb + 32768u + (u32)s * 32768u;
        #pragma unroll
        for (int h = 0; h < 2; h++)
            #pragma unroll
            for (int j = 0; j < 4; j++) {
                int c = c0_ld + j;
                u32 so = (u32)r_ld * 128 + (u32)((c ^ (r_ld & 7)) << 4);
                cp16_ca(base + (u32)h * 16384u + so, bp + h * 64 + c * 8);
            }
        cp_commit();
    };
    load_B(cg0, 0);

    const int g = lane >> 2;
    const int q = lane & 3;
    const int cb = n0w + ((q >> 1) << 2);
    const bool evenlane = ((lane & 1) == 0);

    for (int i = 0; i < 4; i++) {
        const int s = i & 1;
        if (i < 3) { load_B(cg0 + i + 1, 1 - s); cp_wait<1>(); }
        else       { cp_wait<0>(); }
        __syncthreads();

        float acc[2][8][4];
        #pragma unroll
        for (int mi = 0; mi < 2; mi++)
            #pragma unroll
            for (int nj = 0; nj < 8; nj++)
                #pragma unroll
                for (int e = 0; e < 4; e++) acc[mi][nj][e] = 0.f;

        compute_tile(acc, sb + a_rb, sb + 32768u + (u32)s * 32768u + b_rb, a_hi, b_hi, xr);

        const int col0 = (cg0 + i) * 128;
        #pragma unroll
        for (int mi = 0; mi < 2; mi++) {
            int r1 = row0 + m0w + mi * 16 + g;
            float* pr = evenlane ? (Cb + (i64)r1 * NSEQ) : (Cb + (i64)(r1 + 8) * NSEQ);
            #pragma unroll
            for (int nj = 0; nj < 8; nj++) {
                float v0 = acc[mi][nj][0] * scale, v1 = acc[mi][nj][1] * scale;
                float v2 = acc[mi][nj][2] * scale, v3 = acc[mi][nj][3] * scale;
                float p0 = __shfl_xor_sync(0xffffffffu, v0, 1);
                float p1 = __shfl_xor_sync(0xffffffffu, v1, 1);
                float p2 = __shfl_xor_sync(0xffffffffu, v2, 1);
                float p3 = __shfl_xor_sync(0xffffffffu, v3, 1);
                float4 o = evenlane ? make_float4(v0, v1, p0, p1)
                                    : make_float4(p2, p3, v2, v3);
                *reinterpret_cast<float4*>(pr + col0 + cb + nj * 8) = o;
            }
        }
        __syncthreads();
    }
}

// ---------------- PV kernel: split-K x2, red.v4 into X (pre-init with feats) -----
__global__ __launch_bounds__(256, 2)
void pv_k(const f16* __restrict__ sc_h, const f16* __restrict__ vt_h,
          float* __restrict__ X)
{
    extern __shared__ char sm[];
    const u32 sb = smem_u32(sm);
    const int z = blockIdx.z;
    const int b = z >> 1, kh = z & 1;
    const int row0 = blockIdx.x * 128;
    const f16* Ab = sc_h + (i64)b * NSEQ * NSEQ + kh * 512;
    const f16* Bb = vt_h + (i64)b * D * NSEQ + kh * 512;
    float* Xb = X + (i64)b * NSEQ * D;

    const int tid = threadIdx.x;
    const int wid = tid >> 5, lane = tid & 31;
    const int m0w = (wid >> 1) * 32, n0w = (wid & 1) * 64;
    const u32 a_rb = (u32)(m0w + (lane & 15)) * 128;
    const u32 b_rb = (u32)(n0w + ((lane >> 4) << 3) + (lane & 7)) * 128;
    const int a_hi = lane >> 4;
    const int b_hi = (lane >> 3) & 1;
    const int xr = lane & 7;
    const int r_ld = tid >> 1;
    const int c0_ld = (tid & 1) * 4;

    float acc[2][8][4];
    #pragma unroll
    for (int mi = 0; mi < 2; mi++)
        #pragma unroll
        for (int nj = 0; nj < 8; nj++)
            #pragma unroll
            for (int e = 0; e < 4; e++) acc[mi][nj][e] = 0.f;

    auto load_half = [&](int h, int s) {
        const int kofs = h * 64;
        const u32 base = sb + (u32)s * 32768u;
        const f16* ap = Ab + (i64)(row0 + r_ld) * NSEQ + kofs;
        const f16* bp = Bb + (i64)r_ld * NSEQ + kofs;
        #pragma unroll
        for (int j = 0; j < 4; j++) {
            int c = c0_ld + j;
            u32 so = (u32)r_ld * 128 + (u32)((c ^ (r_ld & 7)) << 4);
            cp16_cg(base + so,          ap + c * 8);
            cp16_ca(base + 16384u + so, bp + c * 8);
        }
        cp_commit();
    };

    load_half(0, 0);
    for (int h = 0; h < 8; h++) {
        const int s = h & 1;
        if (h < 7) { load_half(h + 1, 1 - s); cp_wait<1>(); }
        else       { cp_wait<0>(); }
        __syncthreads();
        const u32 base = sb + (u32)s * 32768u;
        const u32 abase = base + a_rb;
        const u32 bbase = base + 16384u + b_rb;
        #pragma unroll
        for (int ks = 0; ks < 4; ks++) {
            const u32 aoff = (u32)(((ks * 2 + a_hi) ^ xr) << 4);
            const u32 boff = (u32)(((ks * 2 + b_hi) ^ xr) << 4);
            u32 bf[4][4], a0[4], a1[4];
            #pragma unroll
            for (int p = 0; p < 4; p++)
                ldsm4(bf[p], bbase + boff + p * 2048);
            ldsm4(a0, abase + aoff);
            ldsm4(a1, abase + aoff + 2048);
            #pragma unroll
            for (int nj = 0; nj < 8; nj++) {
                u32 bb0 = bf[nj >> 1][(nj & 1) * 2], bb1 = bf[nj >> 1][(nj & 1) * 2 + 1];
                mma_f16(acc[0][nj], a0, bb0, bb1);
                mma_f16(acc[1][nj], a1, bb0, bb1);
            }
        }
        __syncthreads();
    }

    const int g = lane >> 2;
    const int q = lane & 3;
    const int cb = n0w + ((q >> 1) << 2);
    const bool evenlane = ((lane & 1) == 0);
    #pragma unroll
    for (int mi = 0; mi < 2; mi++) {
        int r1 = row0 + m0w + mi * 16 + g;
        float* pr = evenlane ? (Xb + (i64)r1 * D) : (Xb + (i64)(r1 + 8) * D);
        #pragma unroll
        for (int nj = 0; nj < 8; nj++) {
            float v0 = acc[mi][nj][0], v1 = acc[mi][nj][1];
            float v2 = acc[mi][nj][2], v3 = acc[mi][nj][3];
            float p0 = __shfl_xor_sync(0xffffffffu, v0, 1);
            float p1 = __shfl_xor_sync(0xffffffffu, v1, 1);
            float p2 = __shfl_xor_sync(0xffffffffu, v2, 1);
            float p3 = __shfl_xor_sync(0xffffffffu, v3, 1);
            if (evenlane) red4(pr + cb + nj * 8, v0, v1, p0, p1);
            else          red4(pr + cb + nj * 8, p2, p3, v2, v3);
        }
    }
}

// ---------------- persistent-B scatter kernel (includes ctr group) --------------
#define NTILES_SC 3840
#define CHUNK_SC 13
#define GRID_SC ((NTILES_SC + CHUNK_SC - 1) / CHUNK_SC)   // 296

__global__ __launch_bounds__(256, 2)
void layer_scatter_p(const f16* __restrict__ Xh,
                     const f16* __restrict__ wch,
                     const f16* __restrict__ wph, const f16* __restrict__ wsh,
                     const f16* __restrict__ wlh, const f16* __restrict__ wrh,
                     float* __restrict__ T,
                     const int* __restrict__ pre_u, const int* __restrict__ pre_v,
                     const int* __restrict__ suc_u, const int* __restrict__ suc_v,
                     const int* __restrict__ left_u, const int* __restrict__ left_v,
                     const int* __restrict__ right_u, const int* __restrict__ right_v)
{
    extern __shared__ char sm[];
    const u32 sb = smem_u32(sm);
    const int t0 = blockIdx.x * CHUNK_SC;
    const int t1 = (t0 + CHUNK_SC < NTILES_SC) ? t0 + CHUNK_SC : NTILES_SC;
    if (t0 >= NTILES_SC) return;

    const int tid = threadIdx.x;
    const int wid = tid >> 5, lane = tid & 31;
    const int m0w = (wid >> 1) * 32, n0w = (wid & 1) * 64;
    const u32 a_rb = (u32)(m0w + (lane & 15)) * 128;
    const u32 b_rb = (u32)(n0w + ((lane >> 4) << 3) + (lane & 7)) * 128;
    const int a_hi = lane >> 4;
    const int b_hi = (lane >> 3) & 1;
    const int xr = lane & 7;
    const int r_ld = tid >> 1;
    const int c0_ld = (tid & 1) * 4;

    auto group_of = [&](int t, const f16*& Bw, const int*& gv, const int*& su, int& base) {
        int g = t >> 8, e = (t & 255) * 128;
        base = e;
        if (g == 0)       { Bw = wch; gv = 0; su = 0; }
        else if (g < 7)   { int z = g - 1; Bw = wph + (i64)z * DD; gv = pre_v + z * NE + e; su = pre_u + z * NE + e; }
        else if (g < 13)  { int z = g - 7; Bw = wsh + (i64)z * DD; gv = suc_v + z * NE + e; su = suc_u + z * NE + e; }
        else if (g == 13) { Bw = wlh; gv = left_v + e; su = left_u + e; }
        else              { Bw = wrh; gv = right_v + e; su = right_u + e; }
    };

    auto load_B = [&](const f16* Bw) {
        const f16* bp = Bw + (i64)r_ld * D;
        #pragma unroll
        for (int h = 0; h < 2; h++) {
            const u32 base = sb + 32768u + (u32)h * 16384u;
            #pragma unroll
            for (int j = 0; j < 4; j++) {
                int c = c0_ld + j;
                u32 so = (u32)r_ld * 128 + (u32)((c ^ (r_ld & 7)) << 4);
                cp16_ca(base + so, bp + h * 64 + c * 8);
            }
        }
        cp_commit();
    };
    auto load_A = [&](const int* gv, int base_row, int h, int s) {
        i64 arow = gv ? (i64)__ldg(gv + r_ld) : (i64)(base_row + r_ld);
        const f16* ap = Xh + arow * D + h * 64;
        const u32 base = sb + (u32)s * 16384u;
        #pragma unroll
        for (int j = 0; j < 4; j++) {
            int c = c0_ld + j;
            u32 so = (u32)r_ld * 128 + (u32)((c ^ (r_ld & 7)) << 4);
            cp16_cg(base + so, ap + c * 8);
        }
        cp_commit();
    };

    const int g = lane >> 2;
    const int q = lane & 3;
    const int cb = n0w + ((q >> 1) << 2);
    const bool evenlane = ((lane & 1) == 0);
    const f16* Bw; const int* gv; const int* su; int base_row;
    group_of(t0, Bw, gv, su, base_row);
    int curg = t0 >> 8;
    load_B(Bw);
    load_A(gv, base_row, 0, 0);
    load_A(gv, base_row, 1, 1);

    for (int t = t0; t < t1; t++) {
        const f16* Bw_n = 0; const int* gv_n = 0; const int* su_n = 0; int base_n = 0;
        const bool have_next = (t + 1 < t1);
        int g_n = curg;
        if (have_next) { group_of(t + 1, Bw_n, gv_n, su_n, base_n); g_n = (t + 1) >> 8; }
        const bool pref0 = have_next && (g_n == curg);

        float acc[2][8][4];
        #pragma unroll
        for (int mi = 0; mi < 2; mi++)
            #pragma unroll
            for (int nj = 0; nj < 8; nj++)
                #pragma unroll
                for (int e = 0; e < 4; e++) acc[mi][nj][e] = 0.f;

        // half 0
        cp_wait<1>(); __syncthreads();
        {
            const u32 abase = sb + a_rb;
            const u32 bbase = sb + 32768u + b_rb;
            #pragma unroll
            for (int ks = 0; ks < 4; ks++) {
                const u32 aoff = (u32)(((ks * 2 + a_hi) ^ xr) << 4);
                const u32 boff = (u32)(((ks * 2 + b_hi) ^ xr) << 4);
                u32 b[4][4], a0[4], a1[4];
                #pragma unroll
                for (int p = 0; p < 4; p++)
                    ldsm4(b[p], bbase + boff + p * 2048);
                ldsm4(a0, abase + aoff);
                ldsm4(a1, abase + aoff + 2048);
                #pragma unroll
                for (int nj = 0; nj < 8; nj++) {
                    u32 bb0 = b[nj >> 1][(nj & 1) * 2], bb1 = b[nj >> 1][(nj & 1) * 2 + 1];
                    mma_f16(acc[0][nj], a0, bb0, bb1);
                    mma_f16(acc[1][nj], a1, bb0, bb1);
                }
            }
        }
        __syncthreads();
        if (pref0) load_A(gv_n, base_n, 0, 0);

        // half 1
        if (pref0) cp_wait<1>(); else cp_wait<0>();
        __syncthreads();
        {
            const u32 abase = sb + 16384u + a_rb;
            const u32 bbase = sb + 49152u + b_rb;
            #pragma unroll
            for (int ks = 0; ks < 4; ks++) {
                const u32 aoff = (u32)(((ks * 2 + a_hi) ^ xr) << 4);
                const u32 boff = (u32)(((ks * 2 + b_hi) ^ xr) << 4);
                u32 b[4][4], a0[4], a1[4];
                #pragma unroll
                for (int p = 0; p < 4; p++)
                    ldsm4(b[p], bbase + boff + p * 2048);
                ldsm4(a0, abase + aoff);
                ldsm4(a1, abase + aoff + 2048);
                #pragma unroll
                for (int nj = 0; nj < 8; nj++) {
                    u32 bb0 = b[nj >> 1][(nj & 1) * 2], bb1 = b[nj >> 1][(nj & 1) * 2 + 1];
                    mma_f16(acc[0][nj], a0, bb0, bb1);
                    mma_f16(acc[1][nj], a1, bb0, bb1);
                }
            }
        }

        #pragma unroll
        for (int mi = 0; mi < 2; mi++) {
            int lr1 = m0w + mi * 16 + g;
            i64 dr1 = su ? (i64)__ldg(su + lr1)     : (i64)(base_row + lr1);
            i64 dr2 = su ? (i64)__ldg(su + lr1 + 8) : (i64)(base_row + lr1 + 8);
            float* pr = evenlane ? (T + dr1 * D) : (T + dr2 * D);
            #pragma unroll
            for (int nj = 0; nj < 8; nj++) {
                float v0 = acc[mi][nj][0], v1 = acc[mi][nj][1];
                float v2 = acc[mi][nj][2], v3 = acc[mi][nj][3];
                float p0 = __shfl_xor_sync(0xffffffffu, v0, 1);
                float p1 = __shfl_xor_sync(0xffffffffu, v1, 1);
                float p2 = __shfl_xor_sync(0xffffffffu, v2, 1);
                float p3 = __shfl_xor_sync(0xffffffffu, v3, 1);
                if (evenlane) red4(pr + cb + nj * 8, v0, v1, p0, p1);
                else          red4(pr + cb + nj * 8, p2, p3, v2, v3);
            }
        }
        __syncthreads();

        if (have_next) {
            if (g_n == curg) {
                load_A(gv_n, base_n, 1, 1);
            } else {
                cp_wait<0>(); __syncthreads();
                load_B(Bw_n);
                load_A(gv_n, base_n, 0, 0);
                load_A(gv_n, base_n, 1, 1);
                curg = g_n;
            }
            gv = gv_n; su = su_n; base_row = base_n;
        }
    }
}

// ---------------- merged prolog kernel (cvt x11 + zero T + X=feats) --------------
#define NSEG 11
struct PrologArgs {
    const float4* src[NSEG];
    uint2* dst[NSEG];
    int n4[NSEG];
    float4* T;
    float4* X;
    const float4* feats;
    int nT4;
};
__global__ __launch_bounds__(256)
void prolog_k(PrologArgs a)
{
    const int seg = blockIdx.y;
    const int i = blockIdx.x * 256 + threadIdx.x;
    if (seg < NSEG) {
        if (i < a.n4[seg]) a.dst[seg][i] = cvt4(a.src[seg][i]);
    } else if (seg == NSEG) {
        if (i < a.nT4) a.T[i] = make_float4(0.f, 0.f, 0.f, 0.f);
    } else {
        if (i < a.nT4) a.X[i] = a.feats[i];
    }
}

__global__ __launch_bounds__(256)
void cvtX_k(const float4* __restrict__ X, uint2* __restrict__ xh)
{
    const int i = blockIdx.x * 256 + threadIdx.x;
    xh[i] = cvt4(X[i]);
}

// row softmax over 1024, emit fp16
__global__ __launch_bounds__(256)
void softmax_k(const float* __restrict__ Sc, f16* __restrict__ oh)
{
    i64 row = blockIdx.x;
    const float4* p = reinterpret_cast<const float4*>(Sc + row * NSEQ);
    int t = threadIdx.x;
    float4 v = p[t];
    float mx = fmaxf(fmaxf(v.x, v.y), fmaxf(v.z, v.w));
    #pragma unroll
    for (int o = 16; o; o >>= 1) mx = fmaxf(mx, __shfl_xor_sync(0xffffffffu, mx, o));
    __shared__ float red8[8];
    int w = t >> 5;
    if ((t & 31) == 0) red8[w] = mx;
    __syncthreads();
    mx = red8[0];
    #pragma unroll
    for (int i = 1; i < 8; i++) mx = fmaxf(mx, red8[i]);
    v.x = expf(v.x - mx); v.y = expf(v.y - mx);
    v.z = expf(v.z - mx); v.w = expf(v.w - mx);
    float s = v.x + v.y + v.z + v.w;
    #pragma unroll
    for (int o = 16; o; o >>= 1) s += __shfl_xor_sync(0xffffffffu, s, o);
    __syncthreads();
    if ((t & 31) == 0) red8[w] = s;
    __syncthreads();
    s = red8[0] + red8[1] + red8[2] + red8[3] + red8[4] + red8[5] + red8[6] + red8[7];
    float inv = 1.0f / s;
    v.x *= inv; v.y *= inv; v.z *= inv; v.w *= inv;
    *reinterpret_cast<uint2*>(oh + row * NSEQ + t * 4) = cvt4(v);
}

// ---------------- driver ---------------------------------------------------------
#define SMEM_GN 67584   // gemm_gn12 / qkv: 64KB tiles, 66KB staging overlap
#define SMEM_QK 98304   // qk: A 32KB + 2x32KB B stages
#define SMEM_PV 65536   // pv: 2 stages x 32KB
#define SMEM_SC 65536   // scatter: 2x16KB A + 32KB B

extern "C" void kernel_launch(void* const* d_in, const int* in_sizes, int n_in,
                              void* d_out, int out_size)
{
    (void)in_sizes; (void)n_in; (void)out_size;
    const float* ctrs   = (const float*)d_in[0];
    const float* feats  = (const float*)d_in[1];
    const float* Wq     = (const float*)d_in[2];
    const float* Wk     = (const float*)d_in[3];
    const float* Wv     = (const float*)d_in[4];
    const float* Wc     = (const float*)d_in[5];
    const float* Wp     = (const float*)d_in[6];
    const float* Ws     = (const float*)d_in[7];
    const float* Wl     = (const float*)d_in[8];
    const float* Wr     = (const float*)d_in[9];
    const float* Wc2    = (const float*)d_in[10];
    const float* g1     = (const float*)d_in[11];
    const float* b1     = (const float*)d_in[12];
    const float* g2     = (const float*)d_in[13];
    const float* b2     = (const float*)d_in[14];
    const int* pre_u    = (const int*)d_in[15];
    const int* pre_v    = (const int*)d_in[16];
    const int* suc_u    = (const int*)d_in[17];
    const int* suc_v    = (const int*)d_in[18];
    const int* left_u   = (const int*)d_in[19];
    const int* left_v   = (const int*)d_in[20];
    const int* right_u  = (const int*)d_in[21];
    const int* right_v  = (const int*)d_in[22];
    float* X = (float*)d_out;

    float *sc, *T;
    cudaGetSymbolAddress((void**)&sc, g_sc);
    cudaGetSymbolAddress((void**)&T,  g_T);
    f16 *ctrs_h, *feat_h, *q_h, *k_h, *vt_h, *x_h, *sc_h;
    f16 *wq_h, *wk_h, *wv_h, *wc_h, *wp_h, *ws_h, *wl_h, *wr_h, *w2_h;
    cudaGetSymbolAddress((void**)&ctrs_h, s_ctrs_h);
    cudaGetSymbolAddress((void**)&feat_h, s_feat_h);
    cudaGetSymbolAddress((void**)&q_h, s_q_h);
    cudaGetSymbolAddress((void**)&k_h, s_k_h);
    cudaGetSymbolAddress((void**)&vt_h, s_vt_h);
    cudaGetSymbolAddress((void**)&x_h, s_x_h);
    cudaGetSymbolAddress((void**)&sc_h, s_sc_h);
    cudaGetSymbolAddress((void**)&wq_h, s_wq_h);
    cudaGetSymbolAddress((void**)&wk_h, s_wk_h);
    cudaGetSymbolAddress((void**)&wv_h, s_wv_h);
    cudaGetSymbolAddress((void**)&wc_h, s_wc_h);
    cudaGetSymbolAddress((void**)&wp_h, s_wp_h);
    cudaGetSymbolAddress((void**)&ws_h, s_ws_h);
    cudaGetSymbolAddress((void**)&wl_h, s_wl_h);
    cudaGetSymbolAddress((void**)&wr_h, s_wr_h);
    cudaGetSymbolAddress((void**)&w2_h, s_w2_h);

    cudaFuncSetAttribute((const void*)gemm_gn12_k, cudaFuncAttributeMaxDynamicSharedMemorySize, SMEM_GN);
    cudaFuncSetAttribute((const void*)qkv_k, cudaFuncAttributeMaxDynamicSharedMemorySize, SMEM_GN);
    cudaFuncSetAttribute((const void*)qk_k, cudaFuncAttributeMaxDynamicSharedMemorySize, SMEM_QK);
    cudaFuncSetAttribute((const void*)pv_k, cudaFuncAttributeMaxDynamicSharedMemorySize, SMEM_PV);
    cudaFuncSetAttribute((const void*)layer_scatter_p, cudaFuncAttributeMaxDynamicSharedMemorySize, SMEM_SC);

    const float NF = 0.08838834764831845f;  // 1/sqrt(128)
    dim3 blk(256);

    // ---- single prolog launch: 11 conversions + zero T + X = feats ----
    PrologArgs pa;
    const float* srcs[NSEG] = {ctrs, feats, Wq, Wk, Wv, Wc, Wp, Ws, Wl, Wr, Wc2};
    f16* dsts[NSEG] = {ctrs_h, feat_h, wq_h, wk_h, wv_h, wc_h, wp_h, ws_h, wl_h, wr_h, w2_h};
    const int ns[NSEG] = {M_ROWS*D, M_ROWS*D, DD, DD, DD, NL*DD, NL*NS*DD, NL*NS*DD, NL*DD, NL*DD, NL*DD};
    int maxn4 = M_ROWS * D / 4;
    for (int i = 0; i < NSEG; i++) {
        pa.src[i] = (const float4*)srcs[i];
        pa.dst[i] = (uint2*)dsts[i];
        pa.n4[i] = ns[i] / 4;
        if (pa.n4[i] > maxn4) maxn4 = pa.n4[i];
    }
    pa.T = (float4*)T;
    pa.X = (float4*)X;
    pa.feats = (const float4*)feats;
    pa.nT4 = M_ROWS * D / 4;
    prolog_k<<<dim3((maxn4 + 255) / 256, NSEG + 2), 256>>>(pa);

    // ---- attention ----
    qkv_k<<<dim3(128, 1, 3), blk, SMEM_GN>>>(ctrs_h, feat_h, wq_h, wk_h, wv_h, q_h, k_h, vt_h);
    qk_k<<<dim3(8, 2, 16), blk, SMEM_QK>>>(q_h, k_h, sc, NF);
    softmax_k<<<M_ROWS, 256>>>(sc, sc_h);
    pv_k<<<dim3(8, 1, 32), blk, SMEM_PV>>>(sc_h, vt_h, X);
    cvtX_k<<<M_ROWS * D / 4 / 256, 256>>>((const float4*)X, (uint2*)x_h);

    // ---- 4-layer fusion loop (2 launches per layer) ----
    for (int i = 0; i < NL; i++) {
        layer_scatter_p<<<GRID_SC, blk, SMEM_SC>>>(
            x_h,
            wc_h + (i64)i*DD,
            wp_h + (i64)i*NS*DD,
            ws_h + (i64)i*NS*DD,
            wl_h + (i64)i*DD,
            wr_h + (i64)i*DD,
            T, pre_u, pre_v, suc_u, suc_v, left_u, left_v, right_u, right_v);
        gemm_gn12_k<<<dim3(128, 1, 1), blk, SMEM_GN>>>(
            T, w2_h + (i64)i*DD, X, x_h,
            g1 + i*D, b1 + i*D, g2 + i*D, b2 + i*D);
    }
}

// round 14
// speedup vs baseline: 2.2707x; 1.0173x over previous
#include <cuda_runtime.h>
#include <cuda_fp16.h>
#include <math.h>
#include <stdint.h>

#define D 128
#define DD 16384
#define BATCH 16
#define NSEQ 1024
#define M_ROWS 16384
#define NE 32768
#define NS 6
#define NL 4

typedef unsigned long long u64;
typedef unsigned int u32;
typedef long long i64;
typedef __half f16;

// ---------------- scratch -------------------------------------------------------
__device__ __align__(256) float g_T [M_ROWS * D];
__device__ __align__(256) f16 s_ctrs_h[M_ROWS*D];
__device__ __align__(256) f16 s_feat_h[M_ROWS*D];
__device__ __align__(256) f16 s_q_h[M_ROWS*D];
__device__ __align__(256) f16 s_k_h[M_ROWS*D];
__device__ __align__(256) f16 s_vt_h[M_ROWS*D];
__device__ __align__(256) f16 s_x_h[M_ROWS*D];
__device__ __align__(256) f16 s_sc_h[(size_t)BATCH*NSEQ*NSEQ];
__device__ __align__(256) f16 s_wq_h[DD], s_wk_h[DD], s_wv_h[DD];
__device__ __align__(256) f16 s_wc_h[NL*DD];
__device__ __align__(256) f16 s_wp_h[NL*NS*DD];
__device__ __align__(256) f16 s_ws_h[NL*NS*DD];
__device__ __align__(256) f16 s_wl_h[NL*DD];
__device__ __align__(256) f16 s_wr_h[NL*DD];
__device__ __align__(256) f16 s_w2_h[NL*DD];

// ---------------- PTX helpers ------------------------------------------------
__device__ __forceinline__ u32 smem_u32(const void* p) {
    u32 a;
    asm("{ .reg .u64 t; cvta.to.shared.u64 t, %1; cvt.u32.u64 %0, t; }" : "=r"(a) : "l"(p));
    return a;
}
__device__ __forceinline__ void ldsm4(u32* r, u32 addr) {
    asm volatile("ldmatrix.sync.aligned.m8n8.x4.shared.b16 {%0,%1,%2,%3}, [%4];"
                 : "=r"(r[0]), "=r"(r[1]), "=r"(r[2]), "=r"(r[3]) : "r"(addr));
}
__device__ __forceinline__ void mma_f16(float* d, const u32* a, u32 b0, u32 b1) {
    asm volatile("mma.sync.aligned.m16n8k16.row.col.f32.f16.f16.f32 "
                 "{%0,%1,%2,%3}, {%4,%5,%6,%7}, {%8,%9}, {%0,%1,%2,%3};"
                 : "+f"(d[0]), "+f"(d[1]), "+f"(d[2]), "+f"(d[3])
                 : "r"(a[0]), "r"(a[1]), "r"(a[2]), "r"(a[3]), "r"(b0), "r"(b1));
}
__device__ __forceinline__ void red4(float* p, float a, float b, float c, float d) {
    asm volatile("red.global.add.v4.f32 [%0], {%1,%2,%3,%4};"
                 :: "l"(p), "f"(a), "f"(b), "f"(c), "f"(d) : "memory");
}
__device__ __forceinline__ void cp16_cg(u32 dst, const void* src) {
    asm volatile("cp.async.cg.shared.global [%0], [%1], 16;" :: "r"(dst), "l"(src));
}
__device__ __forceinline__ void cp16_ca(u32 dst, const void* src) {
    asm volatile("cp.async.ca.shared.global [%0], [%1], 16;" :: "r"(dst), "l"(src));
}
__device__ __forceinline__ void cp_commit() { asm volatile("cp.async.commit_group;" ::: "memory"); }
template<int N> __device__ __forceinline__ void cp_wait() {
    asm volatile("cp.async.wait_group %0;" :: "n"(N) : "memory");
}
__device__ __forceinline__ uint2 cvt4(float4 v) {
    __half2 h0 = __floats2half2_rn(v.x, v.y);
    __half2 h1 = __floats2half2_rn(v.z, v.w);
    return make_uint2(*(u32*)&h0, *(u32*)&h1);
}

// =====================================================================
// MMA fragment compute over one resident 128-K tile pair (two halves).
// =====================================================================
__device__ __forceinline__ void compute_tile(
    float acc[2][8][4], u32 abase0, u32 bbase0, int a_hi, int b_hi, int xr)
{
    #pragma unroll
    for (int h = 0; h < 2; h++) {
        const u32 abase = abase0 + (u32)h * 16384u;
        const u32 bbase = bbase0 + (u32)h * 16384u;
        #pragma unroll
        for (int ks = 0; ks < 4; ks++) {
            const u32 aoff = (u32)(((ks * 2 + a_hi) ^ xr) << 4);
            const u32 boff = (u32)(((ks * 2 + b_hi) ^ xr) << 4);
            u32 b[4][4], a0[4], a1[4];
            #pragma unroll
            for (int p = 0; p < 4; p++)
                ldsm4(b[p], bbase + boff + p * 2048);
            ldsm4(a0, abase + aoff);
            ldsm4(a1, abase + aoff + 2048);
            #pragma unroll
            for (int nj = 0; nj < 8; nj++) {
                u32 bb0 = b[nj >> 1][(nj & 1) * 2], bb1 = b[nj >> 1][(nj & 1) * 2 + 1];
                mma_f16(acc[0][nj], a0, bb0, bb1);
                mma_f16(acc[1][nj], a1, bb0, bb1);
            }
        }
    }
}

// ---------------- fused gn1 + ctr2 GEMM + gn2 kernel -----------------------------
__global__ __launch_bounds__(256, 2)
void gemm_gn12_k(float* __restrict__ T,
                 const f16* __restrict__ Bh,
                 float* __restrict__ X, f16* __restrict__ Ch,
                 const float* __restrict__ g1w, const float* __restrict__ b1w,
                 const float* __restrict__ g2w, const float* __restrict__ b2w)
{
    extern __shared__ char sm[];
    const u32 sb = smem_u32(sm);
    const int row0 = blockIdx.x * 128;
    const int tid = threadIdx.x;
    const int wid = tid >> 5, lane = tid & 31;
    const int m0w = (wid >> 1) * 32, n0w = (wid & 1) * 64;
    const int r_ld = tid >> 1;
    const int hh_ld = tid & 1;

    {
        const f16* bp = Bh + (i64)r_ld * D;
        #pragma unroll
        for (int h = 0; h < 2; h++)
            #pragma unroll
            for (int j = 0; j < 4; j++) {
                int c = hh_ld * 4 + j;
                u32 so = (u32)r_ld * 128 + (u32)((c ^ (r_ld & 7)) << 4);
                cp16_ca(sb + 32768u + (u32)h * 16384u + so, bp + h * 64 + c * 8);
            }
        cp_commit();
    }

    // T rows -> GN1 + relu -> fp16 A smem; zero T in place
    {
        float* Tp = T + (i64)(row0 + r_ld) * D + hh_ld * 64;
        float4 tv[16];
        float s1 = 0.f, s2 = 0.f;
        #pragma unroll
        for (int j = 0; j < 16; j++) {
            tv[j] = *reinterpret_cast<const float4*>(Tp + j * 4);
            s1 += tv[j].x + tv[j].y + tv[j].z + tv[j].w;
            s2 += tv[j].x * tv[j].x + tv[j].y * tv[j].y + tv[j].z * tv[j].z + tv[j].w * tv[j].w;
        }
        s1 += __shfl_xor_sync(0xffffffffu, s1, 1);
        s2 += __shfl_xor_sync(0xffffffffu, s2, 1);
        const float mu = s1 * (1.f / 128.f);
        const float var = s2 * (1.f / 128.f) - mu * mu;
        const float rstd = rsqrtf(var + 1e-5f);
        const float* gp = g1w + hh_ld * 64;
        const float* bp = b1w + hh_ld * 64;
        #pragma unroll
        for (int j = 0; j < 16; j++) {
            float4 g4 = *reinterpret_cast<const float4*>(gp + j * 4);
            float4 b4 = *reinterpret_cast<const float4*>(bp + j * 4);
            float4 y;
            y.x = fmaxf((tv[j].x - mu) * rstd * g4.x + b4.x, 0.f);
            y.y = fmaxf((tv[j].y - mu) * rstd * g4.y + b4.y, 0.f);
            y.z = fmaxf((tv[j].z - mu) * rstd * g4.z + b4.z, 0.f);
            y.w = fmaxf((tv[j].w - mu) * rstd * g4.w + b4.w, 0.f);
            int c = j >> 1;
            u32 so = (u32)r_ld * 128 + (u32)((c ^ (r_ld & 7)) << 4) + (u32)(j & 1) * 8;
            *reinterpret_cast<uint2*>(sm + hh_ld * 16384 + so) = cvt4(y);
            *reinterpret_cast<float4*>(Tp + j * 4) = make_float4(0.f, 0.f, 0.f, 0.f);
        }
    }
    cp_wait<0>();
    __syncthreads();

    float acc[2][8][4];
    #pragma unroll
    for (int mi = 0; mi < 2; mi++)
        #pragma unroll
        for (int nj = 0; nj < 8; nj++)
            #pragma unroll
            for (int e = 0; e < 4; e++) acc[mi][nj][e] = 0.f;

    const u32 a_rb = (u32)(m0w + (lane & 15)) * 128;
    const u32 b_rb = (u32)(n0w + ((lane >> 4) << 3) + (lane & 7)) * 128;
    const int a_hi = lane >> 4;
    const int b_hi = (lane >> 3) & 1;
    const int xr = lane & 7;
    compute_tile(acc, sb + a_rb, sb + 32768u + b_rb, a_hi, b_hi, xr);
    __syncthreads();

    float* Cs = reinterpret_cast<float*>(sm);
    const int g = lane >> 2, q2 = (lane & 3) * 2;
    #pragma unroll
    for (int mi = 0; mi < 2; mi++)
        #pragma unroll
        for (int nj = 0; nj < 8; nj++) {
            int r = m0w + mi * 16 + g;
            int c = n0w + nj * 8 + q2;
            Cs[r * 132 + c]           = acc[mi][nj][0];
            Cs[r * 132 + c + 1]       = acc[mi][nj][1];
            Cs[(r + 8) * 132 + c]     = acc[mi][nj][2];
            Cs[(r + 8) * 132 + c + 1] = acc[mi][nj][3];
        }
    __syncthreads();

    const int rr = tid >> 1, hh = tid & 1;
    const float* srow = Cs + rr * 132 + hh * 64;
    float s1 = 0.f, s2 = 0.f;
    #pragma unroll
    for (int j = 0; j < 16; j++) {
        float4 vv = *reinterpret_cast<const float4*>(srow + j * 4);
        s1 += vv.x + vv.y + vv.z + vv.w;
        s2 += vv.x * vv.x + vv.y * vv.y + vv.z * vv.z + vv.w * vv.w;
    }
    s1 += __shfl_xor_sync(0xffffffffu, s1, 1);
    s2 += __shfl_xor_sync(0xffffffffu, s2, 1);
    const float mu = s1 * (1.f / 128.f);
    const float var = s2 * (1.f / 128.f) - mu * mu;
    const float rstd = rsqrtf(var + 1e-5f);
    const i64 ro = (i64)(row0 + rr) * D + hh * 64;
    float* p = X + ro;
    const float* gp = g2w + hh * 64;
    const float* bp = b2w + hh * 64;
    #pragma unroll
    for (int j = 0; j < 16; j++) {
        float4 vv = *reinterpret_cast<const float4*>(srow + j * 4);
        float4 g4 = *reinterpret_cast<const float4*>(gp + j * 4);
        float4 b4 = *reinterpret_cast<const float4*>(bp + j * 4);
        float4 f4 = *reinterpret_cast<const float4*>(p + j * 4);
        vv.x = fmaxf((vv.x - mu) * rstd * g4.x + b4.x + f4.x, 0.f);
        vv.y = fmaxf((vv.y - mu) * rstd * g4.y + b4.y + f4.y, 0.f);
        vv.z = fmaxf((vv.z - mu) * rstd * g4.z + b4.z + f4.z, 0.f);
        vv.w = fmaxf((vv.w - mu) * rstd * g4.w + b4.w + f4.w, 0.f);
        *reinterpret_cast<float4*>(p + j * 4) = vv;
        *reinterpret_cast<uint2*>(Ch + ro + j * 4) = cvt4(vv);
    }
}

// ---------------- fused QKV kernel (z=0:Q, z=1:K, z=2:V->transposed) ------------
__global__ __launch_bounds__(256, 2)
void qkv_k(const f16* __restrict__ ctrs_h, const f16* __restrict__ feat_h,
           const f16* __restrict__ wq, const f16* __restrict__ wk, const f16* __restrict__ wv,
           f16* __restrict__ q_h, f16* __restrict__ k_h, f16* __restrict__ vt_h)
{
    extern __shared__ char sm[];
    const u32 sb = smem_u32(sm);
    const int z = blockIdx.z;
    const int row0 = blockIdx.x * 128;
    const f16* Ah = (z == 0) ? ctrs_h : feat_h;
    const f16* Bh = (z == 0) ? wq : (z == 1) ? wk : wv;

    const int tid = threadIdx.x;
    const int wid = tid >> 5, lane = tid & 31;
    const int m0w = (wid >> 1) * 32, n0w = (wid & 1) * 64;

    float acc[2][8][4];
    #pragma unroll
    for (int mi = 0; mi < 2; mi++)
        #pragma unroll
        for (int nj = 0; nj < 8; nj++)
            #pragma unroll
            for (int e = 0; e < 4; e++) acc[mi][nj][e] = 0.f;

    const u32 a_rb = (u32)(m0w + (lane & 15)) * 128;
    const u32 b_rb = (u32)(n0w + ((lane >> 4) << 3) + (lane & 7)) * 128;
    const int a_hi = lane >> 4;
    const int b_hi = (lane >> 3) & 1;
    const int xr = lane & 7;
    const int r_ld = tid >> 1;
    const int c0_ld = (tid & 1) * 4;

    {
        const f16* ap = Ah + (i64)(row0 + r_ld) * D;
        const f16* bp = Bh + (i64)r_ld * D;
        #pragma unroll
        for (int h = 0; h < 2; h++)
            #pragma unroll
            for (int j = 0; j < 4; j++) {
                int c = c0_ld + j;
                u32 so = (u32)r_ld * 128 + (u32)((c ^ (r_ld & 7)) << 4);
                cp16_cg(sb + (u32)h * 16384u + so,          ap + h * 64 + c * 8);
                cp16_ca(sb + 32768u + (u32)h * 16384u + so, bp + h * 64 + c * 8);
            }
        cp_commit();
    }
    cp_wait<0>();
    __syncthreads();
    compute_tile(acc, sb + a_rb, sb + 32768u + b_rb, a_hi, b_hi, xr);
    __syncthreads();

    float* Cs = reinterpret_cast<float*>(sm);
    const int g = lane >> 2, q2 = (lane & 3) * 2;
    #pragma unroll
    for (int mi = 0; mi < 2; mi++)
        #pragma unroll
        for (int nj = 0; nj < 8; nj++) {
            int r = m0w + mi * 16 + g;
            int c = n0w + nj * 8 + q2;
            Cs[r * 132 + c]           = acc[mi][nj][0];
            Cs[r * 132 + c + 1]       = acc[mi][nj][1];
            Cs[(r + 8) * 132 + c]     = acc[mi][nj][2];
            Cs[(r + 8) * 132 + c + 1] = acc[mi][nj][3];
        }
    __syncthreads();

    if (z < 2) {
        f16* out = (z == 0) ? q_h : k_h;
        const int rr = tid >> 1, hh = tid & 1;
        const float* srow = Cs + rr * 132 + hh * 64;
        const i64 ro = (i64)(row0 + rr) * D + hh * 64;
        #pragma unroll
        for (int j = 0; j < 16; j++) {
            float4 vv = *reinterpret_cast<const float4*>(srow + j * 4);
            *reinterpret_cast<uint2*>(out + ro + j * 4) = cvt4(vv);
        }
    } else {
        const int d = tid >> 1, hh = tid & 1;
        const int jg0 = row0 + hh * 64;
        const int b = jg0 >> 10, jin = jg0 & 1023;
        f16* dst = vt_h + (i64)b * D * NSEQ + (i64)d * NSEQ + jin;
        #pragma unroll
        for (int j = 0; j < 64; j += 2) {
            float a0 = Cs[(hh * 64 + j) * 132 + d];
            float a1 = Cs[(hh * 64 + j + 1) * 132 + d];
            __half2 hv = __floats2half2_rn(a0, a1);
            *reinterpret_cast<u32*>(dst + j) = *(u32*)&hv;
        }
    }
}

// ---------------- QK scores kernel: A-resident, 4 B tiles streamed, fp16 out -----
__global__ __launch_bounds__(256, 2)
void qk_k(const f16* __restrict__ q_h, const f16* __restrict__ k_h,
          f16* __restrict__ sch, float scale)
{
    extern __shared__ char sm[];
    const u32 sb = smem_u32(sm);
    const int z = blockIdx.z;
    const int row0 = blockIdx.x * 128;
    const int cg0 = blockIdx.y * 4;
    const f16* Ab = q_h + (i64)z * NSEQ * D;
    const f16* Bb = k_h + (i64)z * NSEQ * D;
    f16* Cb = sch + (i64)z * NSEQ * NSEQ;

    const int tid = threadIdx.x;
    const int wid = tid >> 5, lane = tid & 31;
    const int m0w = (wid >> 1) * 32, n0w = (wid & 1) * 64;
    const u32 a_rb = (u32)(m0w + (lane & 15)) * 128;
    const u32 b_rb = (u32)(n0w + ((lane >> 4) << 3) + (lane & 7)) * 128;
    const int a_hi = lane >> 4;
    const int b_hi = (lane >> 3) & 1;
    const int xr = lane & 7;
    const int r_ld = tid >> 1;
    const int c0_ld = (tid & 1) * 4;

    {
        const f16* ap = Ab + (i64)(row0 + r_ld) * D;
        #pragma unroll
        for (int h = 0; h < 2; h++)
            #pragma unroll
            for (int j = 0; j < 4; j++) {
                int c = c0_ld + j;
                u32 so = (u32)r_ld * 128 + (u32)((c ^ (r_ld & 7)) << 4);
                cp16_cg(sb + (u32)h * 16384u + so, ap + h * 64 + c * 8);
            }
        cp_commit();
    }
    auto load_B = [&](int ct, int s) {
        const f16* bp = Bb + (i64)(ct * 128 + r_ld) * D;
        const u32 base = sb + 32768u + (u32)s * 32768u;
        #pragma unroll
        for (int h = 0; h < 2; h++)
            #pragma unroll
            for (int j = 0; j < 4; j++) {
                int c = c0_ld + j;
                u32 so = (u32)r_ld * 128 + (u32)((c ^ (r_ld & 7)) << 4);
                cp16_ca(base + (u32)h * 16384u + so, bp + h * 64 + c * 8);
            }
        cp_commit();
    };
    load_B(cg0, 0);

    const int g = lane >> 2;
    const int q = lane & 3;
    const int cb = n0w + ((q >> 1) << 2);
    const bool evenlane = ((lane & 1) == 0);

    for (int i = 0; i < 4; i++) {
        const int s = i & 1;
        if (i < 3) { load_B(cg0 + i + 1, 1 - s); cp_wait<1>(); }
        else       { cp_wait<0>(); }
        __syncthreads();

        float acc[2][8][4];
        #pragma unroll
        for (int mi = 0; mi < 2; mi++)
            #pragma unroll
            for (int nj = 0; nj < 8; nj++)
                #pragma unroll
                for (int e = 0; e < 4; e++) acc[mi][nj][e] = 0.f;

        compute_tile(acc, sb + a_rb, sb + 32768u + (u32)s * 32768u + b_rb, a_hi, b_hi, xr);

        const int col0 = (cg0 + i) * 128;
        #pragma unroll
        for (int mi = 0; mi < 2; mi++) {
            int r1 = row0 + m0w + mi * 16 + g;
            f16* pr = evenlane ? (Cb + (i64)r1 * NSEQ) : (Cb + (i64)(r1 + 8) * NSEQ);
            #pragma unroll
            for (int nj = 0; nj < 8; nj++) {
                float v0 = acc[mi][nj][0] * scale, v1 = acc[mi][nj][1] * scale;
                float v2 = acc[mi][nj][2] * scale, v3 = acc[mi][nj][3] * scale;
                float p0 = __shfl_xor_sync(0xffffffffu, v0, 1);
                float p1 = __shfl_xor_sync(0xffffffffu, v1, 1);
                float p2 = __shfl_xor_sync(0xffffffffu, v2, 1);
                float p3 = __shfl_xor_sync(0xffffffffu, v3, 1);
                float4 o = evenlane ? make_float4(v0, v1, p0, p1)
                                    : make_float4(p2, p3, v2, v3);
                *reinterpret_cast<uint2*>(pr + col0 + cb + nj * 8) = cvt4(o);
            }
        }
        __syncthreads();
    }
}

// ---------------- PV kernel: split-K x2, red.v4 into X (pre-init with feats) -----
__global__ __launch_bounds__(256, 2)
void pv_k(const f16* __restrict__ sc_h, const f16* __restrict__ vt_h,
          float* __restrict__ X)
{
    extern __shared__ char sm[];
    const u32 sb = smem_u32(sm);
    const int z = blockIdx.z;
    const int b = z >> 1, kh = z & 1;
    const int row0 = blockIdx.x * 128;
    const f16* Ab = sc_h + (i64)b * NSEQ * NSEQ + kh * 512;
    const f16* Bb = vt_h + (i64)b * D * NSEQ + kh * 512;
    float* Xb = X + (i64)b * NSEQ * D;

    const int tid = threadIdx.x;
    const int wid = tid >> 5, lane = tid & 31;
    const int m0w = (wid >> 1) * 32, n0w = (wid & 1) * 64;
    const u32 a_rb = (u32)(m0w + (lane & 15)) * 128;
    const u32 b_rb = (u32)(n0w + ((lane >> 4) << 3) + (lane & 7)) * 128;
    const int a_hi = lane >> 4;
    const int b_hi = (lane >> 3) & 1;
    const int xr = lane & 7;
    const int r_ld = tid >> 1;
    const int c0_ld = (tid & 1) * 4;

    float acc[2][8][4];
    #pragma unroll
    for (int mi = 0; mi < 2; mi++)
        #pragma unroll
        for (int nj = 0; nj < 8; nj++)
            #pragma unroll
            for (int e = 0; e < 4; e++) acc[mi][nj][e] = 0.f;

    auto load_half = [&](int h, int s) {
        const int kofs = h * 64;
        const u32 base = sb + (u32)s * 32768u;
        const f16* ap = Ab + (i64)(row0 + r_ld) * NSEQ + kofs;
        const f16* bp = Bb + (i64)r_ld * NSEQ + kofs;
        #pragma unroll
        for (int j = 0; j < 4; j++) {
            int c = c0_ld + j;
            u32 so = (u32)r_ld * 128 + (u32)((c ^ (r_ld & 7)) << 4);
            cp16_cg(base + so,          ap + c * 8);
            cp16_ca(base + 16384u + so, bp + c * 8);
        }
        cp_commit();
    };

    load_half(0, 0);
    for (int h = 0; h < 8; h++) {
        const int s = h & 1;
        if (h < 7) { load_half(h + 1, 1 - s); cp_wait<1>(); }
        else       { cp_wait<0>(); }
        __syncthreads();
        const u32 base = sb + (u32)s * 32768u;
        const u32 abase = base + a_rb;
        const u32 bbase = base + 16384u + b_rb;
        #pragma unroll
        for (int ks = 0; ks < 4; ks++) {
            const u32 aoff = (u32)(((ks * 2 + a_hi) ^ xr) << 4);
            const u32 boff = (u32)(((ks * 2 + b_hi) ^ xr) << 4);
            u32 bf[4][4], a0[4], a1[4];
            #pragma unroll
            for (int p = 0; p < 4; p++)
                ldsm4(bf[p], bbase + boff + p * 2048);
            ldsm4(a0, abase + aoff);
            ldsm4(a1, abase + aoff + 2048);
            #pragma unroll
            for (int nj = 0; nj < 8; nj++) {
                u32 bb0 = bf[nj >> 1][(nj & 1) * 2], bb1 = bf[nj >> 1][(nj & 1) * 2 + 1];
                mma_f16(acc[0][nj], a0, bb0, bb1);
                mma_f16(acc[1][nj], a1, bb0, bb1);
            }
        }
        __syncthreads();
    }

    const int g = lane >> 2;
    const int q = lane & 3;
    const int cb = n0w + ((q >> 1) << 2);
    const bool evenlane = ((lane & 1) == 0);
    #pragma unroll
    for (int mi = 0; mi < 2; mi++) {
        int r1 = row0 + m0w + mi * 16 + g;
        float* pr = evenlane ? (Xb + (i64)r1 * D) : (Xb + (i64)(r1 + 8) * D);
        #pragma unroll
        for (int nj = 0; nj < 8; nj++) {
            float v0 = acc[mi][nj][0], v1 = acc[mi][nj][1];
            float v2 = acc[mi][nj][2], v3 = acc[mi][nj][3];
            float p0 = __shfl_xor_sync(0xffffffffu, v0, 1);
            float p1 = __shfl_xor_sync(0xffffffffu, v1, 1);
            float p2 = __shfl_xor_sync(0xffffffffu, v2, 1);
            float p3 = __shfl_xor_sync(0xffffffffu, v3, 1);
            if (evenlane) red4(pr + cb + nj * 8, v0, v1, p0, p1);
            else          red4(pr + cb + nj * 8, p2, p3, v2, v3);
        }
    }
}

// ---------------- persistent-B scatter kernel (includes ctr group) --------------
#define NTILES_SC 3840
#define CHUNK_SC 13
#define GRID_SC ((NTILES_SC + CHUNK_SC - 1) / CHUNK_SC)   // 296

__global__ __launch_bounds__(256, 2)
void layer_scatter_p(const f16* __restrict__ Xh,
                     const f16* __restrict__ wch,
                     const f16* __restrict__ wph, const f16* __restrict__ wsh,
                     const f16* __restrict__ wlh, const f16* __restrict__ wrh,
                     float* __restrict__ T,
                     const int* __restrict__ pre_u, const int* __restrict__ pre_v,
                     const int* __restrict__ suc_u, const int* __restrict__ suc_v,
                     const int* __restrict__ left_u, const int* __restrict__ left_v,
                     const int* __restrict__ right_u, const int* __restrict__ right_v)
{
    extern __shared__ char sm[];
    const u32 sb = smem_u32(sm);
    const int t0 = blockIdx.x * CHUNK_SC;
    const int t1 = (t0 + CHUNK_SC < NTILES_SC) ? t0 + CHUNK_SC : NTILES_SC;
    if (t0 >= NTILES_SC) return;

    const int tid = threadIdx.x;
    const int wid = tid >> 5, lane = tid & 31;
    const int m0w = (wid >> 1) * 32, n0w = (wid & 1) * 64;
    const u32 a_rb = (u32)(m0w + (lane & 15)) * 128;
    const u32 b_rb = (u32)(n0w + ((lane >> 4) << 3) + (lane & 7)) * 128;
    const int a_hi = lane >> 4;
    const int b_hi = (lane >> 3) & 1;
    const int xr = lane & 7;
    const int r_ld = tid >> 1;
    const int c0_ld = (tid & 1) * 4;

    auto group_of = [&](int t, const f16*& Bw, const int*& gv, const int*& su, int& base) {
        int g = t >> 8, e = (t & 255) * 128;
        base = e;
        if (g == 0)       { Bw = wch; gv = 0; su = 0; }
        else if (g < 7)   { int z = g - 1; Bw = wph + (i64)z * DD; gv = pre_v + z * NE + e; su = pre_u + z * NE + e; }
        else if (g < 13)  { int z = g - 7; Bw = wsh + (i64)z * DD; gv = suc_v + z * NE + e; su = suc_u + z * NE + e; }
        else if (g == 13) { Bw = wlh; gv = left_v + e; su = left_u + e; }
        else              { Bw = wrh; gv = right_v + e; su = right_u + e; }
    };

    auto load_B = [&](const f16* Bw) {
        const f16* bp = Bw + (i64)r_ld * D;
        #pragma unroll
        for (int h = 0; h < 2; h++) {
            const u32 base = sb + 32768u + (u32)h * 16384u;
            #pragma unroll
            for (int j = 0; j < 4; j++) {
                int c = c0_ld + j;
                u32 so = (u32)r_ld * 128 + (u32)((c ^ (r_ld & 7)) << 4);
                cp16_ca(base + so, bp + h * 64 + c * 8);
            }
        }
        cp_commit();
    };
    auto load_A = [&](const int* gv, int base_row, int h, int s) {
        i64 arow = gv ? (i64)__ldg(gv + r_ld) : (i64)(base_row + r_ld);
        const f16* ap = Xh + arow * D + h * 64;
        const u32 base = sb + (u32)s * 16384u;
        #pragma unroll
        for (int j = 0; j < 4; j++) {
            int c = c0_ld + j;
            u32 so = (u32)r_ld * 128 + (u32)((c ^ (r_ld & 7)) << 4);
            cp16_cg(base + so, ap + c * 8);
        }
        cp_commit();
    };

    const int g = lane >> 2;
    const int q = lane & 3;
    const int cb = n0w + ((q >> 1) << 2);
    const bool evenlane = ((lane & 1) == 0);
    const f16* Bw; const int* gv; const int* su; int base_row;
    group_of(t0, Bw, gv, su, base_row);
    int curg = t0 >> 8;
    load_B(Bw);
    load_A(gv, base_row, 0, 0);
    load_A(gv, base_row, 1, 1);

    for (int t = t0; t < t1; t++) {
        const f16* Bw_n = 0; const int* gv_n = 0; const int* su_n = 0; int base_n = 0;
        const bool have_next = (t + 1 < t1);
        int g_n = curg;
        if (have_next) { group_of(t + 1, Bw_n, gv_n, su_n, base_n); g_n = (t + 1) >> 8; }
        const bool pref0 = have_next && (g_n == curg);

        float acc[2][8][4];
        #pragma unroll
        for (int mi = 0; mi < 2; mi++)
            #pragma unroll
            for (int nj = 0; nj < 8; nj++)
                #pragma unroll
                for (int e = 0; e < 4; e++) acc[mi][nj][e] = 0.f;

        // half 0
        cp_wait<1>(); __syncthreads();
        {
            const u32 abase = sb + a_rb;
            const u32 bbase = sb + 32768u + b_rb;
            #pragma unroll
            for (int ks = 0; ks < 4; ks++) {
                const u32 aoff = (u32)(((ks * 2 + a_hi) ^ xr) << 4);
                const u32 boff = (u32)(((ks * 2 + b_hi) ^ xr) << 4);
                u32 b[4][4], a0[4], a1[4];
                #pragma unroll
                for (int p = 0; p < 4; p++)
                    ldsm4(b[p], bbase + boff + p * 2048);
                ldsm4(a0, abase + aoff);
                ldsm4(a1, abase + aoff + 2048);
                #pragma unroll
                for (int nj = 0; nj < 8; nj++) {
                    u32 bb0 = b[nj >> 1][(nj & 1) * 2], bb1 = b[nj >> 1][(nj & 1) * 2 + 1];
                    mma_f16(acc[0][nj], a0, bb0, bb1);
                    mma_f16(acc[1][nj], a1, bb0, bb1);
                }
            }
        }
        __syncthreads();
        if (pref0) load_A(gv_n, base_n, 0, 0);

        // half 1
        if (pref0) cp_wait<1>(); else cp_wait<0>();
        __syncthreads();
        {
            const u32 abase = sb + 16384u + a_rb;
            const u32 bbase = sb + 49152u + b_rb;
            #pragma unroll
            for (int ks = 0; ks < 4; ks++) {
                const u32 aoff = (u32)(((ks * 2 + a_hi) ^ xr) << 4);
                const u32 boff = (u32)(((ks * 2 + b_hi) ^ xr) << 4);
                u32 b[4][4], a0[4], a1[4];
                #pragma unroll
                for (int p = 0; p < 4; p++)
                    ldsm4(b[p], bbase + boff + p * 2048);
                ldsm4(a0, abase + aoff);
                ldsm4(a1, abase + aoff + 2048);
                #pragma unroll
                for (int nj = 0; nj < 8; nj++) {
                    u32 bb0 = b[nj >> 1][(nj & 1) * 2], bb1 = b[nj >> 1][(nj & 1) * 2 + 1];
                    mma_f16(acc[0][nj], a0, bb0, bb1);
                    mma_f16(acc[1][nj], a1, bb0, bb1);
                }
            }
        }

        #pragma unroll
        for (int mi = 0; mi < 2; mi++) {
            int lr1 = m0w + mi * 16 + g;
            i64 dr1 = su ? (i64)__ldg(su + lr1)     : (i64)(base_row + lr1);
            i64 dr2 = su ? (i64)__ldg(su + lr1 + 8) : (i64)(base_row + lr1 + 8);
            float* pr = evenlane ? (T + dr1 * D) : (T + dr2 * D);
            #pragma unroll
            for (int nj = 0; nj < 8; nj++) {
                float v0 = acc[mi][nj][0], v1 = acc[mi][nj][1];
                float v2 = acc[mi][nj][2], v3 = acc[mi][nj][3];
                float p0 = __shfl_xor_sync(0xffffffffu, v0, 1);
                float p1 = __shfl_xor_sync(0xffffffffu, v1, 1);
                float p2 = __shfl_xor_sync(0xffffffffu, v2, 1);
                float p3 = __shfl_xor_sync(0xffffffffu, v3, 1);
                if (evenlane) red4(pr + cb + nj * 8, v0, v1, p0, p1);
                else          red4(pr + cb + nj * 8, p2, p3, v2, v3);
            }
        }
        __syncthreads();

        if (have_next) {
            if (g_n == curg) {
                load_A(gv_n, base_n, 1, 1);
            } else {
                cp_wait<0>(); __syncthreads();
                load_B(Bw_n);
                load_A(gv_n, base_n, 0, 0);
                load_A(gv_n, base_n, 1, 1);
                curg = g_n;
            }
            gv = gv_n; su = su_n; base_row = base_n;
        }
    }
}

// ---------------- merged prolog kernel (cvt x11 + zero T + X=feats) --------------
#define NSEG 11
struct PrologArgs {
    const float4* src[NSEG];
    uint2* dst[NSEG];
    int n4[NSEG];
    float4* T;
    float4* X;
    const float4* feats;
    int nT4;
};
__global__ __launch_bounds__(256)
void prolog_k(PrologArgs a)
{
    const int seg = blockIdx.y;
    const int i = blockIdx.x * 256 + threadIdx.x;
    if (seg < NSEG) {
        if (i < a.n4[seg]) a.dst[seg][i] = cvt4(a.src[seg][i]);
    } else if (seg == NSEG) {
        if (i < a.nT4) a.T[i] = make_float4(0.f, 0.f, 0.f, 0.f);
    } else {
        if (i < a.nT4) a.X[i] = a.feats[i];
    }
}

__global__ __launch_bounds__(256)
void cvtX_k(const float4* __restrict__ X, uint2* __restrict__ xh)
{
    const int i = blockIdx.x * 256 + threadIdx.x;
    xh[i] = cvt4(X[i]);
}

// ---------------- softmax: warp-per-row, in-place over fp16 scores ---------------
__global__ __launch_bounds__(256)
void softmax_h(f16* __restrict__ sch)
{
    const i64 row = (i64)blockIdx.x * 8 + (threadIdx.x >> 5);
    const int lane = threadIdx.x & 31;
    f16* p = sch + row * NSEQ + lane * 32;

    float f[32];
    #pragma unroll
    for (int j = 0; j < 4; j++) {
        uint4 r = *reinterpret_cast<const uint4*>(p + j * 8);
        const u32 w[4] = {r.x, r.y, r.z, r.w};
        #pragma unroll
        for (int e = 0; e < 4; e++) {
            __half2 h = *(const __half2*)&w[e];
            float2 ff = __half22float2(h);
            f[j * 8 + e * 2]     = ff.x;
            f[j * 8 + e * 2 + 1] = ff.y;
        }
    }
    float mx = f[0];
    #pragma unroll
    for (int j = 1; j < 32; j++) mx = fmaxf(mx, f[j]);
    #pragma unroll
    for (int o = 16; o; o >>= 1) mx = fmaxf(mx, __shfl_xor_sync(0xffffffffu, mx, o));
    float s = 0.f;
    #pragma unroll
    for (int j = 0; j < 32; j++) { f[j] = __expf(f[j] - mx); s += f[j]; }
    #pragma unroll
    for (int o = 16; o; o >>= 1) s += __shfl_xor_sync(0xffffffffu, s, o);
    const float inv = 1.0f / s;
    #pragma unroll
    for (int j = 0; j < 4; j++) {
        uint4 r;
        u32* w = (u32*)&r;
        #pragma unroll
        for (int e = 0; e < 4; e++) {
            __half2 h = __floats2half2_rn(f[j * 8 + e * 2] * inv, f[j * 8 + e * 2 + 1] * inv);
            w[e] = *(u32*)&h;
        }
        *reinterpret_cast<uint4*>(p + j * 8) = r;
    }
}

// ---------------- driver ---------------------------------------------------------
#define SMEM_GN 67584
#define SMEM_QK 98304
#define SMEM_PV 65536
#define SMEM_SC 65536

extern "C" void kernel_launch(void* const* d_in, const int* in_sizes, int n_in,
                              void* d_out, int out_size)
{
    (void)in_sizes; (void)n_in; (void)out_size;
    const float* ctrs   = (const float*)d_in[0];
    const float* feats  = (const float*)d_in[1];
    const float* Wq     = (const float*)d_in[2];
    const float* Wk     = (const float*)d_in[3];
    const float* Wv     = (const float*)d_in[4];
    const float* Wc     = (const float*)d_in[5];
    const float* Wp     = (const float*)d_in[6];
    const float* Ws     = (const float*)d_in[7];
    const float* Wl     = (const float*)d_in[8];
    const float* Wr     = (const float*)d_in[9];
    const float* Wc2    = (const float*)d_in[10];
    const float* g1     = (const float*)d_in[11];
    const float* b1     = (const float*)d_in[12];
    const float* g2     = (const float*)d_in[13];
    const float* b2     = (const float*)d_in[14];
    const int* pre_u    = (const int*)d_in[15];
    const int* pre_v    = (const int*)d_in[16];
    const int* suc_u    = (const int*)d_in[17];
    const int* suc_v    = (const int*)d_in[18];
    const int* left_u   = (const int*)d_in[19];
    const int* left_v   = (const int*)d_in[20];
    const int* right_u  = (const int*)d_in[21];
    const int* right_v  = (const int*)d_in[22];
    float* X = (float*)d_out;

    float *T;
    cudaGetSymbolAddress((void**)&T,  g_T);
    f16 *ctrs_h, *feat_h, *q_h, *k_h, *vt_h, *x_h, *sc_h;
    f16 *wq_h, *wk_h, *wv_h, *wc_h, *wp_h, *ws_h, *wl_h, *wr_h, *w2_h;
    cudaGetSymbolAddress((void**)&ctrs_h, s_ctrs_h);
    cudaGetSymbolAddress((void**)&feat_h, s_feat_h);
    cudaGetSymbolAddress((void**)&q_h, s_q_h);
    cudaGetSymbolAddress((void**)&k_h, s_k_h);
    cudaGetSymbolAddress((void**)&vt_h, s_vt_h);
    cudaGetSymbolAddress((void**)&x_h, s_x_h);
    cudaGetSymbolAddress((void**)&sc_h, s_sc_h);
    cudaGetSymbolAddress((void**)&wq_h, s_wq_h);
    cudaGetSymbolAddress((void**)&wk_h, s_wk_h);
    cudaGetSymbolAddress((void**)&wv_h, s_wv_h);
    cudaGetSymbolAddress((void**)&wc_h, s_wc_h);
    cudaGetSymbolAddress((void**)&wp_h, s_wp_h);
    cudaGetSymbolAddress((void**)&ws_h, s_ws_h);
    cudaGetSymbolAddress((void**)&wl_h, s_wl_h);
    cudaGetSymbolAddress((void**)&wr_h, s_wr_h);
    cudaGetSymbolAddress((void**)&w2_h, s_w2_h);

    cudaFuncSetAttribute((const void*)gemm_gn12_k, cudaFuncAttributeMaxDynamicSharedMemorySize, SMEM_GN);
    cudaFuncSetAttribute((const void*)qkv_k, cudaFuncAttributeMaxDynamicSharedMemorySize, SMEM_GN);
    cudaFuncSetAttribute((const void*)qk_k, cudaFuncAttributeMaxDynamicSharedMemorySize, SMEM_QK);
    cudaFuncSetAttribute((const void*)pv_k, cudaFuncAttributeMaxDynamicSharedMemorySize, SMEM_PV);
    cudaFuncSetAttribute((const void*)layer_scatter_p, cudaFuncAttributeMaxDynamicSharedMemorySize, SMEM_SC);

    const float NF = 0.08838834764831845f;  // 1/sqrt(128)
    dim3 blk(256);

    // ---- single prolog launch: 11 conversions + zero T + X = feats ----
    PrologArgs pa;
    const float* srcs[NSEG] = {ctrs, feats, Wq, Wk, Wv, Wc, Wp, Ws, Wl, Wr, Wc2};
    f16* dsts[NSEG] = {ctrs_h, feat_h, wq_h, wk_h, wv_h, wc_h, wp_h, ws_h, wl_h, wr_h, w2_h};
    const int ns[NSEG] = {M_ROWS*D, M_ROWS*D, DD, DD, DD, NL*DD, NL*NS*DD, NL*NS*DD, NL*DD, NL*DD, NL*DD};
    int maxn4 = M_ROWS * D / 4;
    for (int i = 0; i < NSEG; i++) {
        pa.src[i] = (const float4*)srcs[i];
        pa.dst[i] = (uint2*)dsts[i];
        pa.n4[i] = ns[i] / 4;
        if (pa.n4[i] > maxn4) maxn4 = pa.n4[i];
    }
    pa.T = (float4*)T;
    pa.X = (float4*)X;
    pa.feats = (const float4*)feats;
    pa.nT4 = M_ROWS * D / 4;
    prolog_k<<<dim3((maxn4 + 255) / 256, NSEG + 2), 256>>>(pa);

    // ---- attention ----
    qkv_k<<<dim3(128, 1, 3), blk, SMEM_GN>>>(ctrs_h, feat_h, wq_h, wk_h, wv_h, q_h, k_h, vt_h);
    qk_k<<<dim3(8, 2, 16), blk, SMEM_QK>>>(q_h, k_h, sc_h, NF);
    softmax_h<<<M_ROWS / 8, 256>>>(sc_h);
    pv_k<<<dim3(8, 1, 32), blk, SMEM_PV>>>(sc_h, vt_h, X);
    cvtX_k<<<M_ROWS * D / 4 / 256, 256>>>((const float4*)X, (uint2*)x_h);

    // ---- 4-layer fusion loop (2 launches per layer) ----
    for (int i = 0; i < NL; i++) {
        layer_scatter_p<<<GRID_SC, blk, SMEM_SC>>>(
            x_h,
            wc_h + (i64)i*DD,
            wp_h + (i64)i*NS*DD,
            ws_h + (i64)i*NS*DD,
            wl_h + (i64)i*DD,
            wr_h + (i64)i*DD,
            T, pre_u, pre_v, suc_u, suc_v, left_u, left_v, right_u, right_v);
        gemm_gn12_k<<<dim3(128, 1, 1), blk, SMEM_GN>>>(
            T, w2_h + (i64)i*DD, X, x_h,
            g1 + i*D, b1 + i*D, g2 + i*D, b2 + i*D);
    }
}